// round 1
// baseline (speedup 1.0000x reference)
#include <cuda_runtime.h>
#include <math.h>
#include <math_constants.h>

#define B_   2
#define T_   1024
#define D_   512
#define H_   8
#define DK_  64
#define DFF_ 2048
#define L_   6
#define V_   50257
#define PAD_ 50256
#define BT_  (B_*T_)
#define QKVW_ (3*D_)   // 1536

// ---------------- scratch (device globals; no allocations allowed) ----------
__device__ float g_x[BT_*D_];            // activations [2048,512]
__device__ float g_qkv[BT_*QKVW_];       // fused qkv  [2048,1536]
__device__ float g_scores[B_*H_*T_*T_];  // attn scores/probs [16,1024,1024] (67MB)
__device__ float g_ctx[BT_*D_];          // attn context (heads concatenated)
__device__ float g_tmp[BT_*D_];          // attn_out / ffn_out
__device__ float g_ffn[BT_*DFF_];        // ffn hidden [2048,2048]
__device__ float g_wqkv[L_*D_*QKVW_];    // repacked qkv weights [L,512,1536]

// ---------------- weight repack: [L,H,D,DK] -> [L,D,(3*512)] ----------------
__global__ void repack_qkv_kernel(const float* __restrict__ WQ,
                                  const float* __restrict__ WK,
                                  const float* __restrict__ WV) {
    const int total = L_*H_*D_*DK_;
    for (int i = blockIdx.x*blockDim.x + threadIdx.x; i < total; i += gridDim.x*blockDim.x) {
        int kk = i % DK_;
        int d  = (i / DK_) % D_;
        int h  = (i / (DK_*D_)) % H_;
        int l  =  i / (DK_*D_*H_);
        int dst = l*D_*QKVW_ + d*QKVW_ + h*DK_ + kk;
        g_wqkv[dst         ] = WQ[i];
        g_wqkv[dst +   D_  ] = WK[i];
        g_wqkv[dst + 2*D_  ] = WV[i];
    }
}

// ---------------- embedding ------------------------------------------------
__global__ void embed_kernel(const int* __restrict__ ids,
                             const float* __restrict__ tok,
                             const float* __restrict__ pos) {
    int row = blockIdx.x;          // b*T + t
    int t   = row % T_;
    int id  = ids[row];
    const float sc = 22.62741699796952f;   // sqrt(512)
    for (int d = threadIdx.x; d < D_; d += blockDim.x) {
        float e = (id == PAD_) ? 0.f : tok[(size_t)id*D_ + d];
        g_x[(size_t)row*D_ + d] = e*sc + pos[(size_t)t*D_ + d];
    }
}

// ---------------- generic tiled SGEMM (C = A*B [+bias][+gelu]) --------------
// EPI: 0 = none, 1 = +bias, 2 = +bias then exact GELU
template<int BM,int BN,int BK,int TM,int TN,int EPI>
__global__ void __launch_bounds__((BM/TM)*(BN/TN))
sgemm_kernel(int M, int N, int K,
             const float* __restrict__ A, int lda,
             const float* __restrict__ B, int ldb,
             float* __restrict__ C, int ldc,
             const float* __restrict__ bias) {
    constexpr int THREADS = (BM/TM)*(BN/TN);
    __shared__ float As[BK][BM + 1];
    __shared__ float Bs[BK][BN];
    const int bm = blockIdx.y * BM;
    const int bn = blockIdx.x * BN;
    const int tid  = threadIdx.x;
    const int tcol = tid % (BN/TN);
    const int trow = tid / (BN/TN);

    float acc[TM][TN];
    #pragma unroll
    for (int m = 0; m < TM; m++)
        #pragma unroll
        for (int n = 0; n < TN; n++) acc[m][n] = 0.f;

    for (int k0 = 0; k0 < K; k0 += BK) {
        #pragma unroll
        for (int i = tid; i < BM*BK; i += THREADS) {
            int r = i / BK, c = i % BK;
            As[c][r] = A[(size_t)(bm + r)*lda + (k0 + c)];
        }
        #pragma unroll
        for (int i = tid; i < BK*BN; i += THREADS) {
            int r = i / BN, c = i % BN;
            int gc = bn + c;
            Bs[r][c] = (gc < N) ? B[(size_t)(k0 + r)*ldb + gc] : 0.f;
        }
        __syncthreads();
        #pragma unroll
        for (int kk = 0; kk < BK; kk++) {
            float a[TM], bv[TN];
            #pragma unroll
            for (int m = 0; m < TM; m++) a[m]  = As[kk][trow*TM + m];
            #pragma unroll
            for (int n = 0; n < TN; n++) bv[n] = Bs[kk][tcol*TN + n];
            #pragma unroll
            for (int m = 0; m < TM; m++)
                #pragma unroll
                for (int n = 0; n < TN; n++)
                    acc[m][n] = fmaf(a[m], bv[n], acc[m][n]);
        }
        __syncthreads();
    }

    #pragma unroll
    for (int m = 0; m < TM; m++) {
        int gr = bm + trow*TM + m;
        #pragma unroll
        for (int n = 0; n < TN; n++) {
            int gc = bn + tcol*TN + n;
            if (gc < N) {
                float v = acc[m][n];
                if (EPI >= 1) v += bias[gc];
                if (EPI == 2) v = 0.5f*v*(1.f + erff(v*0.70710678118654752f));
                C[(size_t)gr*ldc + gc] = v;
            }
        }
    }
}

// ---------------- attention scores: S = (Q K^T) * 1/8, causal ---------------
// grid (Tc=16, Tr=16, BH=16); skips tiles strictly above the diagonal entirely
__global__ void __launch_bounds__(256) scores_kernel() {
    const int bx = blockIdx.x, by = blockIdx.y, bh = blockIdx.z;
    if (bx > by) return;                      // fully masked tile: never read
    const int b = bh / H_, h = bh % H_;
    const float* qb = g_qkv + (size_t)b*T_*QKVW_ + h*DK_;
    const float* kb = qb + D_;
    float* sb = g_scores + (size_t)bh*T_*T_;

    __shared__ float qs[DK_][DK_ + 1];        // qs[k][row]
    __shared__ float ks[DK_][DK_ + 1];        // ks[k][col]
    const int tid = threadIdx.x;
    for (int i = tid; i < 64*64; i += 256) {
        int r = i >> 6, c = i & 63;
        qs[c][r] = qb[(size_t)(by*64 + r)*QKVW_ + c];
        ks[c][r] = kb[(size_t)(bx*64 + r)*QKVW_ + c];
    }
    __syncthreads();

    const int ty = tid >> 4, tx = tid & 15;
    float acc[4][4] = {};
    #pragma unroll
    for (int kk = 0; kk < 64; kk++) {
        float a[4], bv[4];
        #pragma unroll
        for (int m = 0; m < 4; m++) a[m]  = qs[kk][ty*4 + m];
        #pragma unroll
        for (int n = 0; n < 4; n++) bv[n] = ks[kk][tx*4 + n];
        #pragma unroll
        for (int m = 0; m < 4; m++)
            #pragma unroll
            for (int n = 0; n < 4; n++)
                acc[m][n] = fmaf(a[m], bv[n], acc[m][n]);
    }
    #pragma unroll
    for (int m = 0; m < 4; m++) {
        int gt = by*64 + ty*4 + m;
        #pragma unroll
        for (int n = 0; n < 4; n++) {
            int gs = bx*64 + tx*4 + n;
            sb[(size_t)gt*T_ + gs] = (gs <= gt) ? acc[m][n]*0.125f : -CUDART_INF_F;
        }
    }
}

// ---------------- row softmax over s' in [0, t], zero-pad to tile boundary --
__global__ void __launch_bounds__(256) softmax_kernel() {
    const int row = blockIdx.x;               // bh*T + t
    const int t = row % T_;
    float* s = g_scores + (size_t)row*T_;
    const int n = t + 1;
    const int tid = threadIdx.x;
    __shared__ float red[256];

    float mx = -CUDART_INF_F;
    for (int i = tid; i < n; i += 256) mx = fmaxf(mx, s[i]);
    red[tid] = mx; __syncthreads();
    for (int off = 128; off > 0; off >>= 1) {
        if (tid < off) red[tid] = fmaxf(red[tid], red[tid + off]);
        __syncthreads();
    }
    mx = red[0]; __syncthreads();

    float sum = 0.f;
    for (int i = tid; i < n; i += 256) sum += expf(s[i] - mx);
    red[tid] = sum; __syncthreads();
    for (int off = 128; off > 0; off >>= 1) {
        if (tid < off) red[tid] += red[tid + off];
        __syncthreads();
    }
    const float inv = 1.f / red[0];

    for (int i = tid; i < n; i += 256) s[i] = expf(s[i] - mx)*inv;
    const int pad_end = (t/64 + 1)*64;        // ctx kernel reads up to tile edge
    for (int i = n + tid; i < pad_end; i += 256) s[i] = 0.f;
}

// ---------------- ctx = P @ V, truncated at the diagonal tile ---------------
// grid (Tr=16, BH=16)
__global__ void __launch_bounds__(256) ctx_kernel() {
    const int by = blockIdx.x;                // row tile
    const int bh = blockIdx.y;
    const int b = bh / H_, h = bh % H_;
    const float* pb = g_scores + (size_t)bh*T_*T_;
    const float* vb = g_qkv + (size_t)b*T_*QKVW_ + 2*D_ + h*DK_;

    __shared__ float as[64][65];              // as[row][k]
    __shared__ float vs[64][65];              // vs[k][col]
    const int tid = threadIdx.x;
    const int ty = tid >> 4, tx = tid & 15;
    float acc[4][4] = {};

    for (int kt = 0; kt <= by; kt++) {        // causal: only k-tiles <= row tile
        for (int i = tid; i < 4096; i += 256) {
            int r = i >> 6, c = i & 63;
            as[r][c] = pb[(size_t)(by*64 + r)*T_ + kt*64 + c];
            vs[r][c] = vb[(size_t)(kt*64 + r)*QKVW_ + c];
        }
        __syncthreads();
        #pragma unroll
        for (int kk = 0; kk < 64; kk++) {
            float a[4], bv[4];
            #pragma unroll
            for (int m = 0; m < 4; m++) a[m]  = as[ty*4 + m][kk];
            #pragma unroll
            for (int n = 0; n < 4; n++) bv[n] = vs[kk][tx*4 + n];
            #pragma unroll
            for (int m = 0; m < 4; m++)
                #pragma unroll
                for (int n = 0; n < 4; n++)
                    acc[m][n] = fmaf(a[m], bv[n], acc[m][n]);
        }
        __syncthreads();
    }
    #pragma unroll
    for (int m = 0; m < 4; m++) {
        int gr = b*T_ + by*64 + ty*4 + m;
        #pragma unroll
        for (int n = 0; n < 4; n++)
            g_ctx[(size_t)gr*D_ + h*DK_ + tx*4 + n] = acc[m][n];
    }
}

// ---------------- fused residual add + LayerNorm (in-place on g_x) ----------
__global__ void __launch_bounds__(256) add_ln_kernel(const float* __restrict__ g,
                                                     const float* __restrict__ bta) {
    const int row = blockIdx.x;
    float* x = g_x + (size_t)row*D_;
    const float* dl = g_tmp + (size_t)row*D_;
    const int tid = threadIdx.x;
    __shared__ float red[256];

    float v0 = x[tid]       + dl[tid];
    float v1 = x[tid + 256] + dl[tid + 256];

    red[tid] = v0 + v1; __syncthreads();
    for (int off = 128; off > 0; off >>= 1) {
        if (tid < off) red[tid] += red[tid + off];
        __syncthreads();
    }
    const float mu = red[0] * (1.f/512.f); __syncthreads();

    float d0 = v0 - mu, d1 = v1 - mu;
    red[tid] = d0*d0 + d1*d1; __syncthreads();
    for (int off = 128; off > 0; off >>= 1) {
        if (tid < off) red[tid] += red[tid + off];
        __syncthreads();
    }
    const float inv = rsqrtf(red[0]*(1.f/512.f) + 1e-5f);

    x[tid]       = d0*inv*g[tid]       + bta[tid];
    x[tid + 256] = d1*inv*g[tid + 256] + bta[tid + 256];
}

// ---------------- launch ----------------------------------------------------
extern "C" void kernel_launch(void* const* d_in, const int* in_sizes, int n_in,
                              void* d_out, int out_size) {
    const int*   ids  = (const int*)  d_in[0];
    const float* tok  = (const float*)d_in[1];
    const float* pos  = (const float*)d_in[2];
    const float* WQ   = (const float*)d_in[3];
    const float* WK   = (const float*)d_in[4];
    const float* WV   = (const float*)d_in[5];
    const float* WO   = (const float*)d_in[6];
    const float* ln1g = (const float*)d_in[7];
    const float* ln1b = (const float*)d_in[8];
    const float* fc1w = (const float*)d_in[9];
    const float* fc1b = (const float*)d_in[10];
    const float* fc2w = (const float*)d_in[11];
    const float* fc2b = (const float*)d_in[12];
    const float* ln2g = (const float*)d_in[13];
    const float* ln2b = (const float*)d_in[14];
    const float* lmh  = (const float*)d_in[15];
    float* out = (float*)d_out;

    float *px, *pqkv, *pwqkv, *pctx, *ptmp, *pffn;
    cudaGetSymbolAddress((void**)&px,    g_x);
    cudaGetSymbolAddress((void**)&pqkv,  g_qkv);
    cudaGetSymbolAddress((void**)&pwqkv, g_wqkv);
    cudaGetSymbolAddress((void**)&pctx,  g_ctx);
    cudaGetSymbolAddress((void**)&ptmp,  g_tmp);
    cudaGetSymbolAddress((void**)&pffn,  g_ffn);

    repack_qkv_kernel<<<256, 256>>>(WQ, WK, WV);
    embed_kernel<<<BT_, 256>>>(ids, tok, pos);

    for (int l = 0; l < L_; l++) {
        // QKV projection: [2048,512] x [512,1536]
        sgemm_kernel<128,128,16,8,8,0><<<dim3(QKVW_/128, BT_/128), 256>>>(
            BT_, QKVW_, D_, px, D_, pwqkv + (size_t)l*D_*QKVW_, QKVW_, pqkv, QKVW_, nullptr);

        scores_kernel<<<dim3(T_/64, T_/64, B_*H_), 256>>>();
        softmax_kernel<<<B_*H_*T_, 256>>>();
        ctx_kernel<<<dim3(T_/64, B_*H_), 256>>>();

        // Output projection: [2048,512] x [512,512]
        sgemm_kernel<128,128,16,8,8,0><<<dim3(D_/128, BT_/128), 256>>>(
            BT_, D_, D_, pctx, D_, WO + (size_t)l*D_*D_, D_, ptmp, D_, nullptr);

        add_ln_kernel<<<BT_, 256>>>(ln1g + l*D_, ln1b + l*D_);

        // FC1 + bias + exact GELU: [2048,512] x [512,2048]
        sgemm_kernel<128,128,16,8,8,2><<<dim3(DFF_/128, BT_/128), 256>>>(
            BT_, DFF_, D_, px, D_, fc1w + (size_t)l*D_*DFF_, DFF_, pffn, DFF_, fc1b + l*DFF_);

        // FC2 + bias: [2048,2048] x [2048,512]
        sgemm_kernel<128,128,16,8,8,1><<<dim3(D_/128, BT_/128), 256>>>(
            BT_, D_, DFF_, pffn, DFF_, fc2w + (size_t)l*DFF_*D_, D_, ptmp, D_, fc2b + l*D_);

        add_ln_kernel<<<BT_, 256>>>(ln2g + l*D_, ln2b + l*D_);
    }

    // LM head: [2048,512] x [512,50257]
    sgemm_kernel<128,128,16,8,8,0><<<dim3((V_ + 127)/128, BT_/128), 256>>>(
        BT_, V_, D_, px, D_, lmh, V_, out, V_, nullptr);
}

// round 3
// speedup vs baseline: 1.5655x; 1.5655x over previous
#include <cuda_runtime.h>
#include <math.h>
#include <math_constants.h>
#include <stdint.h>

#define B_   2
#define T_   1024
#define D_   512
#define H_   8
#define DK_  64
#define DFF_ 2048
#define L_   6
#define V_   50257
#define PAD_ 50256
#define BT_  (B_*T_)
#define QKVW_ (3*D_)   // 1536

// ---------------- scratch (device globals; no allocations allowed) ----------
__device__ float g_x[BT_*D_];
__device__ float g_qkv[BT_*QKVW_];
__device__ float g_scores[B_*H_*T_*T_];
__device__ float g_ctx[BT_*D_];
__device__ float g_tmp[BT_*D_];
__device__ float g_ffn[BT_*DFF_];
__device__ float g_wqkv[L_*D_*QKVW_];

// ---------------- tf32 helpers ----------------------------------------------
__device__ __forceinline__ void tf32_split(float x, float& hi, float& lo) {
    uint32_t h;
    asm("cvt.rna.tf32.f32 %0, %1;" : "=r"(h) : "f"(x));
    float hf = __uint_as_float(h);
    uint32_t l;
    asm("cvt.rna.tf32.f32 %0, %1;" : "=r"(l) : "f"(x - hf));
    hi = hf;
    lo = __uint_as_float(l);
}

#define MMA8(cc, a, b) \
    asm volatile("mma.sync.aligned.m16n8k8.row.col.f32.tf32.tf32.f32 " \
        "{%0,%1,%2,%3}, {%4,%5,%6,%7}, {%8,%9}, {%0,%1,%2,%3};" \
        : "+f"((cc)[0]), "+f"((cc)[1]), "+f"((cc)[2]), "+f"((cc)[3]) \
        : "r"((a)[0]), "r"((a)[1]), "r"((a)[2]), "r"((a)[3]), \
          "r"((b)[0]), "r"((b)[1]))

// ============== 3xTF32 mma.sync GEMM: C[M,N] = A[M,K] * B[K,N] ===============
// CTA tile 128x128, 8 warps (2x4), each 64x32 via m16n8k8. BK=32.
// EPI: 0 none, 1 +bias, 2 +bias + exact GELU.  ALIGNB: B rows 16B-alignable.
#define AS_STR 36
#define BS_STR 136
#define GEMM_SMEM ((2*128*AS_STR + 2*32*BS_STR)*4)   // 71680 bytes

template<int EPI, bool ALIGNB>
__global__ void __launch_bounds__(256, 2)
gemm_mma(int M, int N, int K,
         const float* __restrict__ A, int lda,
         const float* __restrict__ Bm, int ldb,
         float* __restrict__ C, int ldc,
         const float* __restrict__ bias)
{
    extern __shared__ float sm[];
    float* As_hi = sm;                       // [128][36]
    float* As_lo = sm + 128*AS_STR;
    float* Bs_hi = sm + 2*128*AS_STR;        // [32][136]
    float* Bs_lo = Bs_hi + 32*BS_STR;

    const int tid  = threadIdx.x;
    const int wid  = tid >> 5, lane = tid & 31;
    const int g    = lane >> 2, t = lane & 3;
    const int bm   = blockIdx.y * 128, bn = blockIdx.x * 128;
    const int m0   = (wid >> 2) * 64, n0 = (wid & 3) * 32;

    float c[4][4][4];
    #pragma unroll
    for (int mi = 0; mi < 4; mi++)
        #pragma unroll
        for (int ni = 0; ni < 4; ni++)
            #pragma unroll
            for (int j = 0; j < 4; j++) c[mi][ni][j] = 0.f;

    for (int k0 = 0; k0 < K; k0 += 32) {
        // ---- A tile [128 x 32] ----
        #pragma unroll
        for (int i = 0; i < 4; i++) {
            int f = tid + i*256;
            int r = f >> 3, c4 = (f & 7) << 2;
            float4 v = *reinterpret_cast<const float4*>(A + (size_t)(bm + r)*lda + k0 + c4);
            float h0,l0,h1,l1,h2,l2,h3,l3;
            tf32_split(v.x, h0, l0); tf32_split(v.y, h1, l1);
            tf32_split(v.z, h2, l2); tf32_split(v.w, h3, l3);
            float* ph = As_hi + r*AS_STR + c4;
            float* pl = As_lo + r*AS_STR + c4;
            ph[0]=h0; ph[1]=h1; ph[2]=h2; ph[3]=h3;
            pl[0]=l0; pl[1]=l1; pl[2]=l2; pl[3]=l3;
        }
        // ---- B tile [32 x 128] ----
        #pragma unroll
        for (int i = 0; i < 4; i++) {
            int f = tid + i*256;
            int kr = f >> 5, n4 = (f & 31) << 2;
            const float* bp = Bm + (size_t)(k0 + kr)*ldb + bn + n4;
            float v0, v1, v2, v3;
            if (ALIGNB) {
                float4 v = *reinterpret_cast<const float4*>(bp);
                v0 = v.x; v1 = v.y; v2 = v.z; v3 = v.w;
            } else {
                int gc = bn + n4;
                v0 = (gc + 0 < N) ? bp[0] : 0.f;
                v1 = (gc + 1 < N) ? bp[1] : 0.f;
                v2 = (gc + 2 < N) ? bp[2] : 0.f;
                v3 = (gc + 3 < N) ? bp[3] : 0.f;
            }
            float h0,l0,h1,l1,h2,l2,h3,l3;
            tf32_split(v0, h0, l0); tf32_split(v1, h1, l1);
            tf32_split(v2, h2, l2); tf32_split(v3, h3, l3);
            float* ph = Bs_hi + kr*BS_STR + n4;
            float* pl = Bs_lo + kr*BS_STR + n4;
            ph[0]=h0; ph[1]=h1; ph[2]=h2; ph[3]=h3;
            pl[0]=l0; pl[1]=l1; pl[2]=l2; pl[3]=l3;
        }
        __syncthreads();

        #pragma unroll
        for (int ks = 0; ks < 4; ks++) {
            const int kk = ks*8;
            uint32_t bh[4][2], bl[4][2];
            #pragma unroll
            for (int ni = 0; ni < 4; ni++) {
                int col = n0 + ni*8 + g;
                bh[ni][0] = __float_as_uint(Bs_hi[(kk + t    )*BS_STR + col]);
                bh[ni][1] = __float_as_uint(Bs_hi[(kk + t + 4)*BS_STR + col]);
                bl[ni][0] = __float_as_uint(Bs_lo[(kk + t    )*BS_STR + col]);
                bl[ni][1] = __float_as_uint(Bs_lo[(kk + t + 4)*BS_STR + col]);
            }
            #pragma unroll
            for (int mi = 0; mi < 4; mi++) {
                int row = m0 + mi*16 + g;
                uint32_t ah[4], al[4];
                ah[0] = __float_as_uint(As_hi[(row    )*AS_STR + kk + t    ]);
                ah[1] = __float_as_uint(As_hi[(row + 8)*AS_STR + kk + t    ]);
                ah[2] = __float_as_uint(As_hi[(row    )*AS_STR + kk + t + 4]);
                ah[3] = __float_as_uint(As_hi[(row + 8)*AS_STR + kk + t + 4]);
                al[0] = __float_as_uint(As_lo[(row    )*AS_STR + kk + t    ]);
                al[1] = __float_as_uint(As_lo[(row + 8)*AS_STR + kk + t    ]);
                al[2] = __float_as_uint(As_lo[(row    )*AS_STR + kk + t + 4]);
                al[3] = __float_as_uint(As_lo[(row + 8)*AS_STR + kk + t + 4]);
                #pragma unroll
                for (int ni = 0; ni < 4; ni++) {
                    MMA8(c[mi][ni], ah, bh[ni]);   // hi*hi
                    MMA8(c[mi][ni], ah, bl[ni]);   // hi*lo
                    MMA8(c[mi][ni], al, bh[ni]);   // lo*hi
                }
            }
        }
        __syncthreads();
    }

    // ---- epilogue: direct register -> global ----
    #pragma unroll
    for (int mi = 0; mi < 4; mi++) {
        const int r0 = bm + m0 + mi*16 + g;
        #pragma unroll
        for (int ni = 0; ni < 4; ni++) {
            const int c0 = bn + n0 + ni*8 + t*2;
            #pragma unroll
            for (int j = 0; j < 4; j++) {
                const int gr = r0 + (j >> 1)*8;
                const int gc = c0 + (j & 1);
                if (gc < N) {
                    float v = c[mi][ni][j];
                    if (EPI >= 1) v += bias[gc];
                    if (EPI == 2) v = 0.5f*v*(1.f + erff(v*0.70710678118654752f));
                    C[(size_t)gr*ldc + gc] = v;
                }
            }
        }
    }
}

// ---------------- weight repack: [L,H,D,DK] -> [L,D,(3*512)] ----------------
__global__ void repack_qkv_kernel(const float* __restrict__ WQ,
                                  const float* __restrict__ WK,
                                  const float* __restrict__ WV) {
    const int total = L_*H_*D_*DK_;
    for (int i = blockIdx.x*blockDim.x + threadIdx.x; i < total; i += gridDim.x*blockDim.x) {
        int kk = i % DK_;
        int d  = (i / DK_) % D_;
        int h  = (i / (DK_*D_)) % H_;
        int l  =  i / (DK_*D_*H_);
        int dst = l*D_*QKVW_ + d*QKVW_ + h*DK_ + kk;
        g_wqkv[dst        ] = WQ[i];
        g_wqkv[dst +   D_ ] = WK[i];
        g_wqkv[dst + 2*D_ ] = WV[i];
    }
}

// ---------------- embedding --------------------------------------------------
__global__ void embed_kernel(const int* __restrict__ ids,
                             const float* __restrict__ tok,
                             const float* __restrict__ pos) {
    int row = blockIdx.x;
    int t   = row % T_;
    int id  = ids[row];
    const float sc = 22.62741699796952f;   // sqrt(512)
    for (int d = threadIdx.x; d < D_; d += blockDim.x) {
        float e = (id == PAD_) ? 0.f : tok[(size_t)id*D_ + d];
        g_x[(size_t)row*D_ + d] = e*sc + pos[(size_t)t*D_ + d];
    }
}

// ---------------- attention scores: S = (Q K^T) * 1/8, causal ----------------
__global__ void __launch_bounds__(256) scores_kernel() {
    const int bx = blockIdx.x, by = blockIdx.y, bh = blockIdx.z;
    if (bx > by) return;
    const int b = bh / H_, h = bh % H_;
    const float* qb = g_qkv + (size_t)b*T_*QKVW_ + h*DK_;
    const float* kb = qb + D_;
    float* sb = g_scores + (size_t)bh*T_*T_;

    __shared__ float qs[DK_][DK_ + 1];
    __shared__ float ks[DK_][DK_ + 1];
    const int tid = threadIdx.x;
    for (int i = tid; i < 64*64; i += 256) {
        int r = i >> 6, c = i & 63;
        qs[c][r] = qb[(size_t)(by*64 + r)*QKVW_ + c];
        ks[c][r] = kb[(size_t)(bx*64 + r)*QKVW_ + c];
    }
    __syncthreads();

    const int ty = tid >> 4, tx = tid & 15;
    float acc[4][4] = {};
    #pragma unroll
    for (int kk = 0; kk < 64; kk++) {
        float a[4], bv[4];
        #pragma unroll
        for (int m = 0; m < 4; m++) a[m]  = qs[kk][ty*4 + m];
        #pragma unroll
        for (int n = 0; n < 4; n++) bv[n] = ks[kk][tx*4 + n];
        #pragma unroll
        for (int m = 0; m < 4; m++)
            #pragma unroll
            for (int n = 0; n < 4; n++)
                acc[m][n] = fmaf(a[m], bv[n], acc[m][n]);
    }
    #pragma unroll
    for (int m = 0; m < 4; m++) {
        int gt = by*64 + ty*4 + m;
        #pragma unroll
        for (int n = 0; n < 4; n++) {
            int gs = bx*64 + tx*4 + n;
            sb[(size_t)gt*T_ + gs] = (gs <= gt) ? acc[m][n]*0.125f : -CUDART_INF_F;
        }
    }
}

// ---------------- row softmax over s' in [0, t] -------------------------------
__global__ void __launch_bounds__(256) softmax_kernel() {
    const int row = blockIdx.x;
    const int t = row % T_;
    float* s = g_scores + (size_t)row*T_;
    const int n = t + 1;
    const int tid = threadIdx.x;
    __shared__ float red[256];

    float mx = -CUDART_INF_F;
    for (int i = tid; i < n; i += 256) mx = fmaxf(mx, s[i]);
    red[tid] = mx; __syncthreads();
    for (int off = 128; off > 0; off >>= 1) {
        if (tid < off) red[tid] = fmaxf(red[tid], red[tid + off]);
        __syncthreads();
    }
    mx = red[0]; __syncthreads();

    float sum = 0.f;
    for (int i = tid; i < n; i += 256) sum += expf(s[i] - mx);
    red[tid] = sum; __syncthreads();
    for (int off = 128; off > 0; off >>= 1) {
        if (tid < off) red[tid] += red[tid + off];
        __syncthreads();
    }
    const float inv = 1.f / red[0];

    for (int i = tid; i < n; i += 256) s[i] = expf(s[i] - mx)*inv;
    const int pad_end = (t/64 + 1)*64;
    for (int i = n + tid; i < pad_end; i += 256) s[i] = 0.f;
}

// ---------------- ctx = P @ V, truncated at the diagonal tile ----------------
__global__ void __launch_bounds__(256) ctx_kernel() {
    const int by = blockIdx.x;
    const int bh = blockIdx.y;
    const int b = bh / H_, h = bh % H_;
    const float* pb = g_scores + (size_t)bh*T_*T_;
    const float* vb = g_qkv + (size_t)b*T_*QKVW_ + 2*D_ + h*DK_;

    __shared__ float as[64][65];
    __shared__ float vs[64][65];
    const int tid = threadIdx.x;
    const int ty = tid >> 4, tx = tid & 15;
    float acc[4][4] = {};

    for (int kt = 0; kt <= by; kt++) {
        for (int i = tid; i < 4096; i += 256) {
            int r = i >> 6, c = i & 63;
            as[r][c] = pb[(size_t)(by*64 + r)*T_ + kt*64 + c];
            vs[r][c] = vb[(size_t)(kt*64 + r)*QKVW_ + c];
        }
        __syncthreads();
        #pragma unroll
        for (int kk = 0; kk < 64; kk++) {
            float a[4], bv[4];
            #pragma unroll
            for (int m = 0; m < 4; m++) a[m]  = as[ty*4 + m][kk];
            #pragma unroll
            for (int n = 0; n < 4; n++) bv[n] = vs[kk][tx*4 + n];
            #pragma unroll
            for (int m = 0; m < 4; m++)
                #pragma unroll
                for (int n = 0; n < 4; n++)
                    acc[m][n] = fmaf(a[m], bv[n], acc[m][n]);
        }
        __syncthreads();
    }
    #pragma unroll
    for (int m = 0; m < 4; m++) {
        int gr = b*T_ + by*64 + ty*4 + m;
        #pragma unroll
        for (int n = 0; n < 4; n++)
            g_ctx[(size_t)gr*D_ + h*DK_ + tx*4 + n] = acc[m][n];
    }
}

// ---------------- fused residual add + LayerNorm (in-place on g_x) -----------
__global__ void __launch_bounds__(256) add_ln_kernel(const float* __restrict__ g,
                                                     const float* __restrict__ bta) {
    const int row = blockIdx.x;
    float* x = g_x + (size_t)row*D_;
    const float* dl = g_tmp + (size_t)row*D_;
    const int tid = threadIdx.x;
    __shared__ float red[256];

    float v0 = x[tid]       + dl[tid];
    float v1 = x[tid + 256] + dl[tid + 256];

    red[tid] = v0 + v1; __syncthreads();
    for (int off = 128; off > 0; off >>= 1) {
        if (tid < off) red[tid] += red[tid + off];
        __syncthreads();
    }
    const float mu = red[0] * (1.f/512.f); __syncthreads();

    float d0 = v0 - mu, d1 = v1 - mu;
    red[tid] = d0*d0 + d1*d1; __syncthreads();
    for (int off = 128; off > 0; off >>= 1) {
        if (tid < off) red[tid] += red[tid + off];
        __syncthreads();
    }
    const float inv = rsqrtf(red[0]*(1.f/512.f) + 1e-5f);

    x[tid]       = d0*inv*g[tid]       + bta[tid];
    x[tid + 256] = d1*inv*g[tid + 256] + bta[tid + 256];
}

// ---------------- launch ------------------------------------------------------
extern "C" void kernel_launch(void* const* d_in, const int* in_sizes, int n_in,
                              void* d_out, int out_size) {
    const int*   ids  = (const int*)  d_in[0];
    const float* tok  = (const float*)d_in[1];
    const float* pos  = (const float*)d_in[2];
    const float* WQ   = (const float*)d_in[3];
    const float* WK   = (const float*)d_in[4];
    const float* WV   = (const float*)d_in[5];
    const float* WO   = (const float*)d_in[6];
    const float* ln1g = (const float*)d_in[7];
    const float* ln1b = (const float*)d_in[8];
    const float* fc1w = (const float*)d_in[9];
    const float* fc1b = (const float*)d_in[10];
    const float* fc2w = (const float*)d_in[11];
    const float* fc2b = (const float*)d_in[12];
    const float* ln2g = (const float*)d_in[13];
    const float* ln2b = (const float*)d_in[14];
    const float* lmh  = (const float*)d_in[15];
    float* out = (float*)d_out;

    float *px, *pqkv, *pwqkv, *pctx, *ptmp, *pffn;
    cudaGetSymbolAddress((void**)&px,    g_x);
    cudaGetSymbolAddress((void**)&pqkv,  g_qkv);
    cudaGetSymbolAddress((void**)&pwqkv, g_wqkv);
    cudaGetSymbolAddress((void**)&pctx,  g_ctx);
    cudaGetSymbolAddress((void**)&ptmp,  g_tmp);
    cudaGetSymbolAddress((void**)&pffn,  g_ffn);

    cudaFuncSetAttribute(gemm_mma<0,true>,  cudaFuncAttributeMaxDynamicSharedMemorySize, GEMM_SMEM);
    cudaFuncSetAttribute(gemm_mma<1,true>,  cudaFuncAttributeMaxDynamicSharedMemorySize, GEMM_SMEM);
    cudaFuncSetAttribute(gemm_mma<2,true>,  cudaFuncAttributeMaxDynamicSharedMemorySize, GEMM_SMEM);
    cudaFuncSetAttribute(gemm_mma<0,false>, cudaFuncAttributeMaxDynamicSharedMemorySize, GEMM_SMEM);

    repack_qkv_kernel<<<256, 256>>>(WQ, WK, WV);
    embed_kernel<<<BT_, 256>>>(ids, tok, pos);

    for (int l = 0; l < L_; l++) {
        gemm_mma<0,true><<<dim3(QKVW_/128, BT_/128), 256, GEMM_SMEM>>>(
            BT_, QKVW_, D_, px, D_, pwqkv + (size_t)l*D_*QKVW_, QKVW_, pqkv, QKVW_, nullptr);

        scores_kernel<<<dim3(T_/64, T_/64, B_*H_), 256>>>();
        softmax_kernel<<<B_*H_*T_, 256>>>();
        ctx_kernel<<<dim3(T_/64, B_*H_), 256>>>();

        gemm_mma<0,true><<<dim3(D_/128, BT_/128), 256, GEMM_SMEM>>>(
            BT_, D_, D_, pctx, D_, WO + (size_t)l*D_*D_, D_, ptmp, D_, nullptr);

        add_ln_kernel<<<BT_, 256>>>(ln1g + l*D_, ln1b + l*D_);

        gemm_mma<2,true><<<dim3(DFF_/128, BT_/128), 256, GEMM_SMEM>>>(
            BT_, DFF_, D_, px, D_, fc1w + (size_t)l*D_*DFF_, DFF_, pffn, DFF_, fc1b + l*DFF_);

        gemm_mma<1,true><<<dim3(D_/128, BT_/128), 256, GEMM_SMEM>>>(
            BT_, D_, DFF_, pffn, DFF_, fc2w + (size_t)l*DFF_*D_, D_, ptmp, D_, fc2b + l*D_);

        add_ln_kernel<<<BT_, 256>>>(ln2g + l*D_, ln2b + l*D_);
    }

    gemm_mma<0,false><<<dim3((V_ + 127)/128, BT_/128), 256, GEMM_SMEM>>>(
        BT_, V_, D_, px, D_, lmh, V_, out, V_, nullptr);
}

// round 4
// speedup vs baseline: 1.7052x; 1.0893x over previous
#include <cuda_runtime.h>
#include <math.h>
#include <math_constants.h>
#include <stdint.h>

#define B_   2
#define T_   1024
#define D_   512
#define H_   8
#define DK_  64
#define DFF_ 2048
#define L_   6
#define V_   50257
#define PAD_ 50256
#define BT_  (B_*T_)
#define QKVW_ (3*D_)   // 1536

// ---------------- scratch (device globals; no allocations allowed) ----------
__device__ float g_x[BT_*D_];
__device__ float g_qkv[BT_*QKVW_];
__device__ float g_ctx[BT_*D_];
__device__ float g_tmp[BT_*D_];
__device__ float g_ffn[BT_*DFF_];
__device__ float g_wqkv[L_*D_*QKVW_];

// ---------------- tf32 helpers ----------------------------------------------
__device__ __forceinline__ void tf32_split(float x, float& hi, float& lo) {
    uint32_t h;
    asm("cvt.rna.tf32.f32 %0, %1;" : "=r"(h) : "f"(x));
    float hf = __uint_as_float(h);
    uint32_t l;
    asm("cvt.rna.tf32.f32 %0, %1;" : "=r"(l) : "f"(x - hf));
    hi = hf;
    lo = __uint_as_float(l);
}
__device__ __forceinline__ float tf32_rnd(float x) {
    uint32_t h;
    asm("cvt.rna.tf32.f32 %0, %1;" : "=r"(h) : "f"(x));
    return __uint_as_float(h);
}

#define MMA8(cc, a, b) \
    asm volatile("mma.sync.aligned.m16n8k8.row.col.f32.tf32.tf32.f32 " \
        "{%0,%1,%2,%3}, {%4,%5,%6,%7}, {%8,%9}, {%0,%1,%2,%3};" \
        : "+f"((cc)[0]), "+f"((cc)[1]), "+f"((cc)[2]), "+f"((cc)[3]) \
        : "r"((a)[0]), "r"((a)[1]), "r"((a)[2]), "r"((a)[3]), \
          "r"((b)[0]), "r"((b)[1]))

// ============== multi-pass TF32 mma.sync GEMM: C = A*B ======================
// CTA tile 128x128, 8 warps (2x4), each 64x32 via m16n8k8. BK=32.
// EPI: 0 none, 1 +bias, 2 +bias + exact GELU.
// ALIGNB: B rows 16B-alignable.  BSPLIT: split B too (3x) vs B tf32 only (2x).
#define AS_STR 36
#define BS_STR 136
#define GEMM_SMEM ((2*128*AS_STR + 2*32*BS_STR)*4)   // 71680 bytes

template<int EPI, bool ALIGNB, bool BSPLIT>
__global__ void __launch_bounds__(256, 2)
gemm_mma(int M, int N, int K,
         const float* __restrict__ A, int lda,
         const float* __restrict__ Bm, int ldb,
         float* __restrict__ C, int ldc,
         const float* __restrict__ bias)
{
    extern __shared__ float sm[];
    float* As_hi = sm;                       // [128][36]
    float* As_lo = sm + 128*AS_STR;
    float* Bs_hi = sm + 2*128*AS_STR;        // [32][136]
    float* Bs_lo = Bs_hi + 32*BS_STR;

    const int tid  = threadIdx.x;
    const int wid  = tid >> 5, lane = tid & 31;
    const int g    = lane >> 2, t = lane & 3;
    const int bm   = blockIdx.y * 128, bn = blockIdx.x * 128;
    const int m0   = (wid >> 2) * 64, n0 = (wid & 3) * 32;

    float c[4][4][4];
    #pragma unroll
    for (int mi = 0; mi < 4; mi++)
        #pragma unroll
        for (int ni = 0; ni < 4; ni++)
            #pragma unroll
            for (int j = 0; j < 4; j++) c[mi][ni][j] = 0.f;

    for (int k0 = 0; k0 < K; k0 += 32) {
        // ---- A tile [128 x 32] ----
        #pragma unroll
        for (int i = 0; i < 4; i++) {
            int f = tid + i*256;
            int r = f >> 3, c4 = (f & 7) << 2;
            float4 v = *reinterpret_cast<const float4*>(A + (size_t)(bm + r)*lda + k0 + c4);
            float h0,l0,h1,l1,h2,l2,h3,l3;
            tf32_split(v.x, h0, l0); tf32_split(v.y, h1, l1);
            tf32_split(v.z, h2, l2); tf32_split(v.w, h3, l3);
            float* ph = As_hi + r*AS_STR + c4;
            float* pl = As_lo + r*AS_STR + c4;
            ph[0]=h0; ph[1]=h1; ph[2]=h2; ph[3]=h3;
            pl[0]=l0; pl[1]=l1; pl[2]=l2; pl[3]=l3;
        }
        // ---- B tile [32 x 128] ----
        #pragma unroll
        for (int i = 0; i < 4; i++) {
            int f = tid + i*256;
            int kr = f >> 5, n4 = (f & 31) << 2;
            const float* bp = Bm + (size_t)(k0 + kr)*ldb + bn + n4;
            float v0, v1, v2, v3;
            if (ALIGNB) {
                float4 v = *reinterpret_cast<const float4*>(bp);
                v0 = v.x; v1 = v.y; v2 = v.z; v3 = v.w;
            } else {
                int gc = bn + n4;
                v0 = (gc + 0 < N) ? bp[0] : 0.f;
                v1 = (gc + 1 < N) ? bp[1] : 0.f;
                v2 = (gc + 2 < N) ? bp[2] : 0.f;
                v3 = (gc + 3 < N) ? bp[3] : 0.f;
            }
            float* ph = Bs_hi + kr*BS_STR + n4;
            if (BSPLIT) {
                float h0,l0,h1,l1,h2,l2,h3,l3;
                tf32_split(v0, h0, l0); tf32_split(v1, h1, l1);
                tf32_split(v2, h2, l2); tf32_split(v3, h3, l3);
                float* pl = Bs_lo + kr*BS_STR + n4;
                ph[0]=h0; ph[1]=h1; ph[2]=h2; ph[3]=h3;
                pl[0]=l0; pl[1]=l1; pl[2]=l2; pl[3]=l3;
            } else {
                ph[0]=tf32_rnd(v0); ph[1]=tf32_rnd(v1);
                ph[2]=tf32_rnd(v2); ph[3]=tf32_rnd(v3);
            }
        }
        __syncthreads();

        #pragma unroll
        for (int ks = 0; ks < 4; ks++) {
            const int kk = ks*8;
            uint32_t bh[4][2], bl[4][2];
            #pragma unroll
            for (int ni = 0; ni < 4; ni++) {
                int col = n0 + ni*8 + g;
                bh[ni][0] = __float_as_uint(Bs_hi[(kk + t    )*BS_STR + col]);
                bh[ni][1] = __float_as_uint(Bs_hi[(kk + t + 4)*BS_STR + col]);
                if (BSPLIT) {
                    bl[ni][0] = __float_as_uint(Bs_lo[(kk + t    )*BS_STR + col]);
                    bl[ni][1] = __float_as_uint(Bs_lo[(kk + t + 4)*BS_STR + col]);
                }
            }
            #pragma unroll
            for (int mi = 0; mi < 4; mi++) {
                int row = m0 + mi*16 + g;
                uint32_t ah[4], al[4];
                ah[0] = __float_as_uint(As_hi[(row    )*AS_STR + kk + t    ]);
                ah[1] = __float_as_uint(As_hi[(row + 8)*AS_STR + kk + t    ]);
                ah[2] = __float_as_uint(As_hi[(row    )*AS_STR + kk + t + 4]);
                ah[3] = __float_as_uint(As_hi[(row + 8)*AS_STR + kk + t + 4]);
                al[0] = __float_as_uint(As_lo[(row    )*AS_STR + kk + t    ]);
                al[1] = __float_as_uint(As_lo[(row + 8)*AS_STR + kk + t    ]);
                al[2] = __float_as_uint(As_lo[(row    )*AS_STR + kk + t + 4]);
                al[3] = __float_as_uint(As_lo[(row + 8)*AS_STR + kk + t + 4]);
                #pragma unroll
                for (int ni = 0; ni < 4; ni++) {
                    MMA8(c[mi][ni], ah, bh[ni]);              // hi*hi
                    if (BSPLIT) MMA8(c[mi][ni], ah, bl[ni]);  // hi*lo
                    MMA8(c[mi][ni], al, bh[ni]);              // lo*hi
                }
            }
        }
        __syncthreads();
    }

    // ---- epilogue: direct register -> global ----
    #pragma unroll
    for (int mi = 0; mi < 4; mi++) {
        const int r0 = bm + m0 + mi*16 + g;
        #pragma unroll
        for (int ni = 0; ni < 4; ni++) {
            const int c0 = bn + n0 + ni*8 + t*2;
            #pragma unroll
            for (int j = 0; j < 4; j++) {
                const int gr = r0 + (j >> 1)*8;
                const int gc = c0 + (j & 1);
                if (gc < N) {
                    float v = c[mi][ni][j];
                    if (EPI >= 1) v += bias[gc];
                    if (EPI == 2) v = 0.5f*v*(1.f + erff(v*0.70710678118654752f));
                    C[(size_t)gr*ldc + gc] = v;
                }
            }
        }
    }
}

// ---------------- weight repack: [L,H,D,DK] -> [L,D,(3*512)] ----------------
__global__ void repack_qkv_kernel(const float* __restrict__ WQ,
                                  const float* __restrict__ WK,
                                  const float* __restrict__ WV) {
    const int total = L_*H_*D_*DK_;
    for (int i = blockIdx.x*blockDim.x + threadIdx.x; i < total; i += gridDim.x*blockDim.x) {
        int kk = i % DK_;
        int d  = (i / DK_) % D_;
        int h  = (i / (DK_*D_)) % H_;
        int l  =  i / (DK_*D_*H_);
        int dst = l*D_*QKVW_ + d*QKVW_ + h*DK_ + kk;
        g_wqkv[dst        ] = WQ[i];
        g_wqkv[dst +   D_ ] = WK[i];
        g_wqkv[dst + 2*D_ ] = WV[i];
    }
}

// ---------------- embedding --------------------------------------------------
__global__ void embed_kernel(const int* __restrict__ ids,
                             const float* __restrict__ tok,
                             const float* __restrict__ pos) {
    int row = blockIdx.x;
    int t   = row % T_;
    int id  = ids[row];
    const float sc = 22.62741699796952f;   // sqrt(512)
    for (int d = threadIdx.x; d < D_; d += blockDim.x) {
        float e = (id == PAD_) ? 0.f : tok[(size_t)id*D_ + d];
        g_x[(size_t)row*D_ + d] = e*sc + pos[(size_t)t*D_ + d];
    }
}

// ================== fused flash attention (causal) ===========================
// One CTA per (64-row Q tile, bh). Online softmax, O in registers (4x4/thread),
// S/P staged through smem. Writes g_ctx (heads concatenated).
#define FA_SMEM (4*64*65*4)

__global__ void __launch_bounds__(256) fattn_kernel() {
    extern __shared__ float fs[];
    float* qs = fs;              // qs[kk][row]
    float* ks = qs + 64*65;      // ks[kk][col]
    float* vs = ks + 64*65;      // vs[kk][col]
    float* ps = vs + 64*65;      // ps[row][kk]

    const int by = blockIdx.x, bh = blockIdx.y;
    const int b = bh / H_, h = bh % H_;
    const float* qb = g_qkv + (size_t)b*T_*QKVW_ + h*DK_;
    const float* kb = qb + D_;
    const float* vb = qb + 2*D_;

    const int tid = threadIdx.x;
    const int ty = tid >> 4, tx = tid & 15;

    // load Q tile (transposed: qs[dim][row])
    for (int i = tid; i < 4096; i += 256) {
        int r = i >> 6, cc = i & 63;
        qs[cc*65 + r] = qb[(size_t)(by*64 + r)*QKVW_ + cc];
    }

    float m_i[4], l_i[4], o[4][4];
    #pragma unroll
    for (int m = 0; m < 4; m++) {
        m_i[m] = -CUDART_INF_F; l_i[m] = 0.f;
        #pragma unroll
        for (int n = 0; n < 4; n++) o[m][n] = 0.f;
    }

    for (int kt = 0; kt <= by; kt++) {
        __syncthreads();                       // prev PV done; qs visible (1st iter)
        for (int i = tid; i < 4096; i += 256) {
            int r = i >> 6, cc = i & 63;
            float kv = kb[(size_t)(kt*64 + r)*QKVW_ + cc];
            float vv = vb[(size_t)(kt*64 + r)*QKVW_ + cc];
            ks[cc*65 + r] = kv;
            vs[r*65 + cc] = vv;
        }
        __syncthreads();

        // S = Q K^T (4x4 per thread)
        float s[4][4] = {};
        #pragma unroll
        for (int kk = 0; kk < 64; kk++) {
            float a[4], bv[4];
            #pragma unroll
            for (int m = 0; m < 4; m++) a[m]  = qs[kk*65 + ty*4 + m];
            #pragma unroll
            for (int n = 0; n < 4; n++) bv[n] = ks[kk*65 + tx*4 + n];
            #pragma unroll
            for (int m = 0; m < 4; m++)
                #pragma unroll
                for (int n = 0; n < 4; n++)
                    s[m][n] = fmaf(a[m], bv[n], s[m][n]);
        }
        const bool diag = (kt == by);
        #pragma unroll
        for (int m = 0; m < 4; m++)
            #pragma unroll
            for (int n = 0; n < 4; n++) {
                s[m][n] *= 0.125f;
                if (diag && (tx*4 + n > ty*4 + m)) s[m][n] = -CUDART_INF_F;
            }

        // online softmax per row (16 threads per row share via shfl over tx bits)
        #pragma unroll
        for (int m = 0; m < 4; m++) {
            float rmax = fmaxf(fmaxf(s[m][0], s[m][1]), fmaxf(s[m][2], s[m][3]));
            #pragma unroll
            for (int off = 1; off < 16; off <<= 1)
                rmax = fmaxf(rmax, __shfl_xor_sync(0xffffffffu, rmax, off));
            const float mn = fmaxf(m_i[m], rmax);
            const float corr = expf(m_i[m] - mn);
            float rsum = 0.f;
            #pragma unroll
            for (int n = 0; n < 4; n++) {
                float p = expf(s[m][n] - mn);
                s[m][n] = p;
                rsum += p;
            }
            #pragma unroll
            for (int off = 1; off < 16; off <<= 1)
                rsum += __shfl_xor_sync(0xffffffffu, rsum, off);
            l_i[m] = l_i[m]*corr + rsum;
            #pragma unroll
            for (int n = 0; n < 4; n++) o[m][n] *= corr;
            m_i[m] = mn;
            #pragma unroll
            for (int n = 0; n < 4; n++)
                ps[(ty*4 + m)*65 + tx*4 + n] = s[m][n];
        }
        __syncthreads();

        // O += P @ V
        #pragma unroll
        for (int kk = 0; kk < 64; kk++) {
            float a[4], bv[4];
            #pragma unroll
            for (int m = 0; m < 4; m++) a[m]  = ps[(ty*4 + m)*65 + kk];
            #pragma unroll
            for (int n = 0; n < 4; n++) bv[n] = vs[kk*65 + tx*4 + n];
            #pragma unroll
            for (int m = 0; m < 4; m++)
                #pragma unroll
                for (int n = 0; n < 4; n++)
                    o[m][n] = fmaf(a[m], bv[n], o[m][n]);
        }
    }

    #pragma unroll
    for (int m = 0; m < 4; m++) {
        const float inv = 1.f / l_i[m];
        const int gr = b*T_ + by*64 + ty*4 + m;
        #pragma unroll
        for (int n = 0; n < 4; n++)
            g_ctx[(size_t)gr*D_ + h*DK_ + tx*4 + n] = o[m][n]*inv;
    }
}

// ---------------- fused residual add + LayerNorm (in-place on g_x) -----------
__global__ void __launch_bounds__(256) add_ln_kernel(const float* __restrict__ g,
                                                     const float* __restrict__ bta) {
    const int row = blockIdx.x;
    float* x = g_x + (size_t)row*D_;
    const float* dl = g_tmp + (size_t)row*D_;
    const int tid = threadIdx.x;
    __shared__ float red[256];

    float v0 = x[tid]       + dl[tid];
    float v1 = x[tid + 256] + dl[tid + 256];

    red[tid] = v0 + v1; __syncthreads();
    for (int off = 128; off > 0; off >>= 1) {
        if (tid < off) red[tid] += red[tid + off];
        __syncthreads();
    }
    const float mu = red[0] * (1.f/512.f); __syncthreads();

    float d0 = v0 - mu, d1 = v1 - mu;
    red[tid] = d0*d0 + d1*d1; __syncthreads();
    for (int off = 128; off > 0; off >>= 1) {
        if (tid < off) red[tid] += red[tid + off];
        __syncthreads();
    }
    const float inv = rsqrtf(red[0]*(1.f/512.f) + 1e-5f);

    x[tid]       = d0*inv*g[tid]       + bta[tid];
    x[tid + 256] = d1*inv*g[tid + 256] + bta[tid + 256];
}

// ---------------- launch ------------------------------------------------------
extern "C" void kernel_launch(void* const* d_in, const int* in_sizes, int n_in,
                              void* d_out, int out_size) {
    const int*   ids  = (const int*)  d_in[0];
    const float* tok  = (const float*)d_in[1];
    const float* pos  = (const float*)d_in[2];
    const float* WQ   = (const float*)d_in[3];
    const float* WK   = (const float*)d_in[4];
    const float* WV   = (const float*)d_in[5];
    const float* WO   = (const float*)d_in[6];
    const float* ln1g = (const float*)d_in[7];
    const float* ln1b = (const float*)d_in[8];
    const float* fc1w = (const float*)d_in[9];
    const float* fc1b = (const float*)d_in[10];
    const float* fc2w = (const float*)d_in[11];
    const float* fc2b = (const float*)d_in[12];
    const float* ln2g = (const float*)d_in[13];
    const float* ln2b = (const float*)d_in[14];
    const float* lmh  = (const float*)d_in[15];
    float* out = (float*)d_out;

    float *px, *pqkv, *pwqkv, *pctx, *ptmp, *pffn;
    cudaGetSymbolAddress((void**)&px,    g_x);
    cudaGetSymbolAddress((void**)&pqkv,  g_qkv);
    cudaGetSymbolAddress((void**)&pwqkv, g_wqkv);
    cudaGetSymbolAddress((void**)&pctx,  g_ctx);
    cudaGetSymbolAddress((void**)&ptmp,  g_tmp);
    cudaGetSymbolAddress((void**)&pffn,  g_ffn);

    cudaFuncSetAttribute((const void*)gemm_mma<0,true,true>,   cudaFuncAttributeMaxDynamicSharedMemorySize, GEMM_SMEM);
    cudaFuncSetAttribute((const void*)gemm_mma<1,true,true>,   cudaFuncAttributeMaxDynamicSharedMemorySize, GEMM_SMEM);
    cudaFuncSetAttribute((const void*)gemm_mma<2,true,true>,   cudaFuncAttributeMaxDynamicSharedMemorySize, GEMM_SMEM);
    cudaFuncSetAttribute((const void*)gemm_mma<0,false,false>, cudaFuncAttributeMaxDynamicSharedMemorySize, GEMM_SMEM);
    cudaFuncSetAttribute((const void*)fattn_kernel,            cudaFuncAttributeMaxDynamicSharedMemorySize, FA_SMEM);

    repack_qkv_kernel<<<256, 256>>>(WQ, WK, WV);
    embed_kernel<<<BT_, 256>>>(ids, tok, pos);

    for (int l = 0; l < L_; l++) {
        gemm_mma<0,true,true><<<dim3(QKVW_/128, BT_/128), 256, GEMM_SMEM>>>(
            BT_, QKVW_, D_, px, D_, pwqkv + (size_t)l*D_*QKVW_, QKVW_, pqkv, QKVW_, nullptr);

        fattn_kernel<<<dim3(T_/64, B_*H_), 256, FA_SMEM>>>();

        gemm_mma<0,true,true><<<dim3(D_/128, BT_/128), 256, GEMM_SMEM>>>(
            BT_, D_, D_, pctx, D_, WO + (size_t)l*D_*D_, D_, ptmp, D_, nullptr);

        add_ln_kernel<<<BT_, 256>>>(ln1g + l*D_, ln1b + l*D_);

        gemm_mma<2,true,true><<<dim3(DFF_/128, BT_/128), 256, GEMM_SMEM>>>(
            BT_, DFF_, D_, px, D_, fc1w + (size_t)l*D_*DFF_, DFF_, pffn, DFF_, fc1b + l*DFF_);

        gemm_mma<1,true,true><<<dim3(D_/128, BT_/128), 256, GEMM_SMEM>>>(
            BT_, D_, DFF_, pffn, DFF_, fc2w + (size_t)l*DFF_*D_, D_, ptmp, D_, fc2b + l*D_);

        add_ln_kernel<<<BT_, 256>>>(ln2g + l*D_, ln2b + l*D_);
    }

    // lm_head: 2xTF32 (A split, B single-pass) — error lands once on the output
    gemm_mma<0,false,false><<<dim3((V_ + 127)/128, BT_/128), 256, GEMM_SMEM>>>(
        BT_, V_, D_, px, D_, lmh, V_, out, V_, nullptr);
}

// round 5
// speedup vs baseline: 1.9466x; 1.1415x over previous
#include <cuda_runtime.h>
#include <cuda_bf16.h>
#include <math.h>
#include <math_constants.h>
#include <stdint.h>

#define B_   2
#define T_   1024
#define D_   512
#define H_   8
#define DK_  64
#define DFF_ 2048
#define L_   6
#define V_   50257
#define PAD_ 50256
#define BT_  (B_*T_)
#define QKVW_ (3*D_)   // 1536

// ---------------- scratch (device globals; no allocations allowed) ----------
__device__ float g_x[BT_*D_];
__device__ float g_qkv[BT_*QKVW_];
__device__ float g_ctx[BT_*D_];
__device__ float g_tmp[BT_*D_];
__device__ float g_ffn[BT_*DFF_];
__device__ float g_wqkv[L_*D_*QKVW_];

// ---------------- bf16x3 helpers ---------------------------------------------
// pack two adjacent-k fp32 into bf16x2 hi + bf16x2 lo (lo = round(x - hi))
__device__ __forceinline__ void bpack(float x0, float x1, uint32_t& hi, uint32_t& lo) {
    __nv_bfloat16 h0 = __float2bfloat16(x0);
    __nv_bfloat16 h1 = __float2bfloat16(x1);
    __nv_bfloat16 l0 = __float2bfloat16(x0 - __bfloat162float(h0));
    __nv_bfloat16 l1 = __float2bfloat16(x1 - __bfloat162float(h1));
    hi = ((uint32_t)__bfloat16_as_ushort(h1) << 16) | (uint32_t)__bfloat16_as_ushort(h0);
    lo = ((uint32_t)__bfloat16_as_ushort(l1) << 16) | (uint32_t)__bfloat16_as_ushort(l0);
}

#define MMA16(cc, a, b) \
    asm volatile("mma.sync.aligned.m16n8k16.row.col.f32.bf16.bf16.f32 " \
        "{%0,%1,%2,%3}, {%4,%5,%6,%7}, {%8,%9}, {%0,%1,%2,%3};" \
        : "+f"((cc)[0]), "+f"((cc)[1]), "+f"((cc)[2]), "+f"((cc)[3]) \
        : "r"((a)[0]), "r"((a)[1]), "r"((a)[2]), "r"((a)[3]), \
          "r"((b)[0]), "r"((b)[1]))

// ============== bf16x3 mma.sync GEMM: C = A*B =================================
// CTA tile 128x128, 8 warps (2x4), each 64x32 via m16n8k16, BK=32 (2 k-steps).
// EPI: 0 none, 1 +bias, 2 +bias + exact GELU.  GUARD: column guard (ragged N).
#define AU 20   // As u32 stride (16 used + 4 pad)
#define BU 17   // Bs u32 stride (16 used + 1 pad), n-major
#define GEMM_SMEM ((2*128*AU + 2*128*BU)*4)   // 37888 bytes

template<int EPI, bool GUARD>
__global__ void __launch_bounds__(256, 2)
gemm_bf16(int M, int N, int K,
          const float* __restrict__ A, int lda,
          const float* __restrict__ Bm, int ldb,
          float* __restrict__ C, int ldc,
          const float* __restrict__ bias)
{
    extern __shared__ uint32_t su[];
    uint32_t* As_hi = su;                    // [128][AU] row-major (k pairs)
    uint32_t* As_lo = su + 128*AU;
    uint32_t* Bs_hi = su + 2*128*AU;         // [128][BU] n-major (k pairs)
    uint32_t* Bs_lo = Bs_hi + 128*BU;

    const int tid  = threadIdx.x;
    const int wid  = tid >> 5, lane = tid & 31;
    const int g    = lane >> 2, t = lane & 3;
    const int bm   = blockIdx.y * 128, bn = blockIdx.x * 128;
    const int m0   = (wid >> 2) * 64, n0 = (wid & 3) * 32;

    float c[4][4][4];
    #pragma unroll
    for (int mi = 0; mi < 4; mi++)
        #pragma unroll
        for (int ni = 0; ni < 4; ni++)
            #pragma unroll
            for (int j = 0; j < 4; j++) c[mi][ni][j] = 0.f;

    for (int k0 = 0; k0 < K; k0 += 32) {
        // ---- A tile [128 rows x 32 k] : 1024 float4 ----
        #pragma unroll
        for (int i = 0; i < 4; i++) {
            int f = tid + i*256;
            int r = f >> 3, c4 = (f & 7) << 2;
            float4 v = *reinterpret_cast<const float4*>(A + (size_t)(bm + r)*lda + k0 + c4);
            uint32_t h0, l0, h1, l1;
            bpack(v.x, v.y, h0, l0);
            bpack(v.z, v.w, h1, l1);
            int idx = r*AU + (c4 >> 1);
            As_hi[idx] = h0; As_hi[idx + 1] = h1;
            As_lo[idx] = l0; As_lo[idx + 1] = l1;
        }
        // ---- B tile [32 k x 128 n], transposed to n-major k-pairs ----
        #pragma unroll
        for (int i = 0; i < 8; i++) {
            int item = tid + i*256;          // 2048 items: (kp, n)
            int n  = item & 127;
            int kp = item >> 7;              // 0..15
            int gc = bn + n;
            const float* bp = Bm + (size_t)(k0 + 2*kp)*ldb + gc;
            float x0 = 0.f, x1 = 0.f;
            if (!GUARD || gc < N) { x0 = bp[0]; x1 = bp[ldb]; }
            uint32_t h, l;
            bpack(x0, x1, h, l);
            Bs_hi[n*BU + kp] = h;
            Bs_lo[n*BU + kp] = l;
        }
        __syncthreads();

        #pragma unroll
        for (int ks = 0; ks < 2; ks++) {
            const int kb = ks*8;
            uint32_t bh[4][2], bl[4][2];
            #pragma unroll
            for (int ni = 0; ni < 4; ni++) {
                int col = (n0 + ni*8 + g)*BU + kb;
                bh[ni][0] = Bs_hi[col + t];
                bh[ni][1] = Bs_hi[col + t + 4];
                bl[ni][0] = Bs_lo[col + t];
                bl[ni][1] = Bs_lo[col + t + 4];
            }
            #pragma unroll
            for (int mi = 0; mi < 4; mi++) {
                int row = m0 + mi*16 + g;
                uint32_t ah[4], al[4];
                ah[0] = As_hi[(row    )*AU + kb + t];
                ah[1] = As_hi[(row + 8)*AU + kb + t];
                ah[2] = As_hi[(row    )*AU + kb + t + 4];
                ah[3] = As_hi[(row + 8)*AU + kb + t + 4];
                al[0] = As_lo[(row    )*AU + kb + t];
                al[1] = As_lo[(row + 8)*AU + kb + t];
                al[2] = As_lo[(row    )*AU + kb + t + 4];
                al[3] = As_lo[(row + 8)*AU + kb + t + 4];
                #pragma unroll
                for (int ni = 0; ni < 4; ni++) {
                    MMA16(c[mi][ni], ah, bh[ni]);   // hi*hi
                    MMA16(c[mi][ni], ah, bl[ni]);   // hi*lo
                    MMA16(c[mi][ni], al, bh[ni]);   // lo*hi
                }
            }
        }
        __syncthreads();
    }

    // ---- epilogue: direct register -> global ----
    #pragma unroll
    for (int mi = 0; mi < 4; mi++) {
        const int r0 = bm + m0 + mi*16 + g;
        #pragma unroll
        for (int ni = 0; ni < 4; ni++) {
            const int c0 = bn + n0 + ni*8 + t*2;
            #pragma unroll
            for (int j = 0; j < 4; j++) {
                const int gr = r0 + (j >> 1)*8;
                const int gc = c0 + (j & 1);
                if (!GUARD || gc < N) {
                    float v = c[mi][ni][j];
                    if (EPI >= 1) v += bias[gc];
                    if (EPI == 2) v = 0.5f*v*(1.f + erff(v*0.70710678118654752f));
                    C[(size_t)gr*ldc + gc] = v;
                }
            }
        }
    }
}

// ---------------- weight repack: [L,H,D,DK] -> [L,D,(3*512)] -----------------
__global__ void repack_qkv_kernel(const float* __restrict__ WQ,
                                  const float* __restrict__ WK,
                                  const float* __restrict__ WV) {
    const int total = L_*H_*D_*DK_;
    for (int i = blockIdx.x*blockDim.x + threadIdx.x; i < total; i += gridDim.x*blockDim.x) {
        int kk = i % DK_;
        int d  = (i / DK_) % D_;
        int h  = (i / (DK_*D_)) % H_;
        int l  =  i / (DK_*D_*H_);
        int dst = l*D_*QKVW_ + d*QKVW_ + h*DK_ + kk;
        g_wqkv[dst        ] = WQ[i];
        g_wqkv[dst +   D_ ] = WK[i];
        g_wqkv[dst + 2*D_ ] = WV[i];
    }
}

// ---------------- embedding ----------------------------------------------------
__global__ void embed_kernel(const int* __restrict__ ids,
                             const float* __restrict__ tok,
                             const float* __restrict__ pos) {
    int row = blockIdx.x;
    int t   = row % T_;
    int id  = ids[row];
    const float sc = 22.62741699796952f;   // sqrt(512)
    for (int d = threadIdx.x; d < D_; d += blockDim.x) {
        float e = (id == PAD_) ? 0.f : tok[(size_t)id*D_ + d];
        g_x[(size_t)row*D_ + d] = e*sc + pos[(size_t)t*D_ + d];
    }
}

// ================== fused flash attention (causal, load-balanced) =============
// grid (8, BH): CTA x processes Q-tiles x and 15-x -> uniform 17 k-iterations.
#define FA_SMEM (4*64*65*4)

__device__ __forceinline__ void fa_tile(float* qs, float* ks, float* vs, float* ps,
                                        const float* qb, const float* kb, const float* vb,
                                        int by, int b, int h, int tid, int ty, int tx) {
    // load Q tile (transposed: qs[dim][row])
    for (int i = tid; i < 4096; i += 256) {
        int r = i >> 6, cc = i & 63;
        qs[cc*65 + r] = qb[(size_t)(by*64 + r)*QKVW_ + cc];
    }

    float m_i[4], l_i[4], o[4][4];
    #pragma unroll
    for (int m = 0; m < 4; m++) {
        m_i[m] = -CUDART_INF_F; l_i[m] = 0.f;
        #pragma unroll
        for (int n = 0; n < 4; n++) o[m][n] = 0.f;
    }

    for (int kt = 0; kt <= by; kt++) {
        __syncthreads();
        for (int i = tid; i < 4096; i += 256) {
            int r = i >> 6, cc = i & 63;
            ks[cc*65 + r] = kb[(size_t)(kt*64 + r)*QKVW_ + cc];
            vs[r*65 + cc] = vb[(size_t)(kt*64 + r)*QKVW_ + cc];
        }
        __syncthreads();

        float s[4][4] = {};
        #pragma unroll
        for (int kk = 0; kk < 64; kk++) {
            float a[4], bv[4];
            #pragma unroll
            for (int m = 0; m < 4; m++) a[m]  = qs[kk*65 + ty*4 + m];
            #pragma unroll
            for (int n = 0; n < 4; n++) bv[n] = ks[kk*65 + tx*4 + n];
            #pragma unroll
            for (int m = 0; m < 4; m++)
                #pragma unroll
                for (int n = 0; n < 4; n++)
                    s[m][n] = fmaf(a[m], bv[n], s[m][n]);
        }
        const bool diag = (kt == by);
        #pragma unroll
        for (int m = 0; m < 4; m++)
            #pragma unroll
            for (int n = 0; n < 4; n++) {
                s[m][n] *= 0.125f;
                if (diag && (tx*4 + n > ty*4 + m)) s[m][n] = -CUDART_INF_F;
            }

        #pragma unroll
        for (int m = 0; m < 4; m++) {
            float rmax = fmaxf(fmaxf(s[m][0], s[m][1]), fmaxf(s[m][2], s[m][3]));
            #pragma unroll
            for (int off = 1; off < 16; off <<= 1)
                rmax = fmaxf(rmax, __shfl_xor_sync(0xffffffffu, rmax, off));
            const float mn = fmaxf(m_i[m], rmax);
            const float corr = __expf(m_i[m] - mn);
            float rsum = 0.f;
            #pragma unroll
            for (int n = 0; n < 4; n++) {
                float p = __expf(s[m][n] - mn);
                s[m][n] = p;
                rsum += p;
            }
            #pragma unroll
            for (int off = 1; off < 16; off <<= 1)
                rsum += __shfl_xor_sync(0xffffffffu, rsum, off);
            l_i[m] = l_i[m]*corr + rsum;
            #pragma unroll
            for (int n = 0; n < 4; n++) o[m][n] *= corr;
            m_i[m] = mn;
            #pragma unroll
            for (int n = 0; n < 4; n++)
                ps[(ty*4 + m)*65 + tx*4 + n] = s[m][n];
        }
        __syncthreads();

        #pragma unroll
        for (int kk = 0; kk < 64; kk++) {
            float a[4], bv[4];
            #pragma unroll
            for (int m = 0; m < 4; m++) a[m]  = ps[(ty*4 + m)*65 + kk];
            #pragma unroll
            for (int n = 0; n < 4; n++) bv[n] = vs[kk*65 + tx*4 + n];
            #pragma unroll
            for (int m = 0; m < 4; m++)
                #pragma unroll
                for (int n = 0; n < 4; n++)
                    o[m][n] = fmaf(a[m], bv[n], o[m][n]);
        }
    }

    #pragma unroll
    for (int m = 0; m < 4; m++) {
        const float inv = 1.f / l_i[m];
        const int gr = b*T_ + by*64 + ty*4 + m;
        #pragma unroll
        for (int n = 0; n < 4; n++)
            g_ctx[(size_t)gr*D_ + h*DK_ + tx*4 + n] = o[m][n]*inv;
    }
}

__global__ void __launch_bounds__(256) fattn_kernel() {
    extern __shared__ float fs[];
    float* qs = fs;
    float* ks = qs + 64*65;
    float* vs = ks + 64*65;
    float* ps = vs + 64*65;

    const int bx = blockIdx.x;               // 0..7 -> tiles bx and 15-bx
    const int bh = blockIdx.y;
    const int b = bh / H_, h = bh % H_;
    const float* qb = g_qkv + (size_t)b*T_*QKVW_ + h*DK_;
    const float* kb = qb + D_;
    const float* vb = qb + 2*D_;

    const int tid = threadIdx.x;
    const int ty = tid >> 4, tx = tid & 15;

    fa_tile(qs, ks, vs, ps, qb, kb, vb, bx,      b, h, tid, ty, tx);
    __syncthreads();
    fa_tile(qs, ks, vs, ps, qb, kb, vb, 15 - bx, b, h, tid, ty, tx);
}

// ---------------- fused residual add + LayerNorm (in-place on g_x) ------------
__global__ void __launch_bounds__(256) add_ln_kernel(const float* __restrict__ g,
                                                     const float* __restrict__ bta) {
    const int row = blockIdx.x;
    float* x = g_x + (size_t)row*D_;
    const float* dl = g_tmp + (size_t)row*D_;
    const int tid = threadIdx.x;
    __shared__ float red[256];

    float v0 = x[tid]       + dl[tid];
    float v1 = x[tid + 256] + dl[tid + 256];

    red[tid] = v0 + v1; __syncthreads();
    for (int off = 128; off > 0; off >>= 1) {
        if (tid < off) red[tid] += red[tid + off];
        __syncthreads();
    }
    const float mu = red[0] * (1.f/512.f); __syncthreads();

    float d0 = v0 - mu, d1 = v1 - mu;
    red[tid] = d0*d0 + d1*d1; __syncthreads();
    for (int off = 128; off > 0; off >>= 1) {
        if (tid < off) red[tid] += red[tid + off];
        __syncthreads();
    }
    const float inv = rsqrtf(red[0]*(1.f/512.f) + 1e-5f);

    x[tid]       = d0*inv*g[tid]       + bta[tid];
    x[tid + 256] = d1*inv*g[tid + 256] + bta[tid + 256];
}

// ---------------- launch --------------------------------------------------------
extern "C" void kernel_launch(void* const* d_in, const int* in_sizes, int n_in,
                              void* d_out, int out_size) {
    const int*   ids  = (const int*)  d_in[0];
    const float* tok  = (const float*)d_in[1];
    const float* pos  = (const float*)d_in[2];
    const float* WQ   = (const float*)d_in[3];
    const float* WK   = (const float*)d_in[4];
    const float* WV   = (const float*)d_in[5];
    const float* WO   = (const float*)d_in[6];
    const float* ln1g = (const float*)d_in[7];
    const float* ln1b = (const float*)d_in[8];
    const float* fc1w = (const float*)d_in[9];
    const float* fc1b = (const float*)d_in[10];
    const float* fc2w = (const float*)d_in[11];
    const float* fc2b = (const float*)d_in[12];
    const float* ln2g = (const float*)d_in[13];
    const float* ln2b = (const float*)d_in[14];
    const float* lmh  = (const float*)d_in[15];
    float* out = (float*)d_out;

    float *px, *pqkv, *pwqkv, *pctx, *ptmp, *pffn;
    cudaGetSymbolAddress((void**)&px,    g_x);
    cudaGetSymbolAddress((void**)&pqkv,  g_qkv);
    cudaGetSymbolAddress((void**)&pwqkv, g_wqkv);
    cudaGetSymbolAddress((void**)&pctx,  g_ctx);
    cudaGetSymbolAddress((void**)&ptmp,  g_tmp);
    cudaGetSymbolAddress((void**)&pffn,  g_ffn);

    cudaFuncSetAttribute((const void*)fattn_kernel,
                         cudaFuncAttributeMaxDynamicSharedMemorySize, FA_SMEM);

    repack_qkv_kernel<<<256, 256>>>(WQ, WK, WV);
    embed_kernel<<<BT_, 256>>>(ids, tok, pos);

    for (int l = 0; l < L_; l++) {
        gemm_bf16<0,false><<<dim3(QKVW_/128, BT_/128), 256, GEMM_SMEM>>>(
            BT_, QKVW_, D_, px, D_, pwqkv + (size_t)l*D_*QKVW_, QKVW_, pqkv, QKVW_, nullptr);

        fattn_kernel<<<dim3(8, B_*H_), 256, FA_SMEM>>>();

        gemm_bf16<0,false><<<dim3(D_/128, BT_/128), 256, GEMM_SMEM>>>(
            BT_, D_, D_, pctx, D_, WO + (size_t)l*D_*D_, D_, ptmp, D_, nullptr);

        add_ln_kernel<<<BT_, 256>>>(ln1g + l*D_, ln1b + l*D_);

        gemm_bf16<2,false><<<dim3(DFF_/128, BT_/128), 256, GEMM_SMEM>>>(
            BT_, DFF_, D_, px, D_, fc1w + (size_t)l*D_*DFF_, DFF_, pffn, DFF_, fc1b + l*DFF_);

        gemm_bf16<1,false><<<dim3(D_/128, BT_/128), 256, GEMM_SMEM>>>(
            BT_, D_, DFF_, pffn, DFF_, fc2w + (size_t)l*DFF_*D_, D_, ptmp, D_, fc2b + l*D_);

        add_ln_kernel<<<BT_, 256>>>(ln2g + l*D_, ln2b + l*D_);
    }

    // lm_head: bf16x3, ragged N -> guarded loads/stores
    gemm_bf16<0,true><<<dim3((V_ + 127)/128, BT_/128), 256, GEMM_SMEM>>>(
        BT_, V_, D_, px, D_, lmh, V_, out, V_, nullptr);
}

// round 6
// speedup vs baseline: 2.2479x; 1.1548x over previous
#include <cuda_runtime.h>
#include <cuda_bf16.h>
#include <math.h>
#include <math_constants.h>
#include <stdint.h>

#define B_   2
#define T_   1024
#define D_   512
#define H_   8
#define DK_  64
#define DFF_ 2048
#define L_   6
#define V_   50257
#define VP_  50304   // V padded to 128
#define PAD_ 50256
#define BT_  (B_*T_)
#define QKVW_ (3*D_)   // 1536

// ---------------- scratch (device globals; no allocations allowed) ----------
__device__ float g_x[BT_*D_];
__device__ float g_qkv[BT_*QKVW_];
__device__ float g_ctx[BT_*D_];
__device__ float g_tmp[BT_*D_];
__device__ float g_ffn[BT_*DFF_];
__device__ float g_wqkv[L_*D_*QKVW_];

// packed bf16 hi/lo operand buffers (u32 = bf16x2 of adjacent k)
__device__ uint32_t g_aH[BT_*1024];                 // activations, K<=2048
__device__ uint32_t g_aL[BT_*1024];
__device__ uint32_t g_wqkvH[L_*QKVW_*256], g_wqkvL[L_*QKVW_*256];
__device__ uint32_t g_woH[L_*D_*256],      g_woL[L_*D_*256];
__device__ uint32_t g_fc1H[L_*DFF_*256],   g_fc1L[L_*DFF_*256];
__device__ uint32_t g_fc2H[L_*D_*1024],    g_fc2L[L_*D_*1024];
__device__ uint32_t g_lmhH[VP_*256],       g_lmhL[VP_*256];

// ---------------- bf16x3 pack helper -----------------------------------------
__device__ __forceinline__ void bpack(float x0, float x1, uint32_t& hi, uint32_t& lo) {
    __nv_bfloat16 h0 = __float2bfloat16(x0);
    __nv_bfloat16 h1 = __float2bfloat16(x1);
    __nv_bfloat16 l0 = __float2bfloat16(x0 - __bfloat162float(h0));
    __nv_bfloat16 l1 = __float2bfloat16(x1 - __bfloat162float(h1));
    hi = ((uint32_t)__bfloat16_as_ushort(h1) << 16) | (uint32_t)__bfloat16_as_ushort(h0);
    lo = ((uint32_t)__bfloat16_as_ushort(l1) << 16) | (uint32_t)__bfloat16_as_ushort(l0);
}

#define MMA16(cc, a, b) \
    asm volatile("mma.sync.aligned.m16n8k16.row.col.f32.bf16.bf16.f32 " \
        "{%0,%1,%2,%3}, {%4,%5,%6,%7}, {%8,%9}, {%0,%1,%2,%3};" \
        : "+f"((cc)[0]), "+f"((cc)[1]), "+f"((cc)[2]), "+f"((cc)[3]) \
        : "r"((a)[0]), "r"((a)[1]), "r"((a)[2]), "r"((a)[3]), \
          "r"((b)[0]), "r"((b)[1]))

// ---------------- operand prep kernels ----------------------------------------
// W fp32 [K][N] row-major -> oH/oL [Npad][K/2] n-major k-pairs (zero pad n>=N)
__global__ void prepack_b(const float* __restrict__ W, uint32_t* __restrict__ oH,
                          uint32_t* __restrict__ oL, int K, int N, int Npad) {
    const int KP = K >> 1;
    const int total = Npad * KP;
    for (int idx = blockIdx.x*blockDim.x + threadIdx.x; idx < total;
         idx += gridDim.x*blockDim.x) {
        int kp = idx / Npad;
        int n  = idx % Npad;
        float x0 = 0.f, x1 = 0.f;
        if (n < N) {
            x0 = W[(size_t)(2*kp    )*N + n];
            x1 = W[(size_t)(2*kp + 1)*N + n];
        }
        uint32_t h, l;
        bpack(x0, x1, h, l);
        oH[(size_t)n*KP + kp] = h;
        oL[(size_t)n*KP + kp] = l;
    }
}

// A fp32 [M][K] -> g_aH/g_aL [M][K/2] packed k-pairs
__global__ void convert_a(const float* __restrict__ A, int n4) {
    for (int idx = blockIdx.x*blockDim.x + threadIdx.x; idx < n4;
         idx += gridDim.x*blockDim.x) {
        float4 v = reinterpret_cast<const float4*>(A)[idx];
        uint32_t h0, l0, h1, l1;
        bpack(v.x, v.y, h0, l0);
        bpack(v.z, v.w, h1, l1);
        g_aH[2*idx] = h0; g_aH[2*idx + 1] = h1;
        g_aL[2*idx] = l0; g_aL[2*idx + 1] = l1;
    }
}

// ============== bf16x3 mma.sync GEMM on pre-packed operands ===================
// CTA tile 128 x (32*NI), 8 warps (2x4), warp 64 x (8*NI), BK=32 (16 k-pairs).
// EPI: 0 none, 1 +bias, 2 +bias+GELU.  GUARD: ragged-N epilogue guard.
#define AU 20   // As u32 row stride
#define BU 17   // Bs u32 row stride (n-major)

template<int EPI, bool GUARD, int NI>
__global__ void __launch_bounds__(256, 2)
gemm_pk(int M, int N, int K,
        const uint32_t* __restrict__ aH, const uint32_t* __restrict__ aL,
        const uint32_t* __restrict__ bH, const uint32_t* __restrict__ bL,
        float* __restrict__ C, int ldc, const float* __restrict__ bias)
{
    constexpr int NTILE = 32*NI;
    __shared__ __align__(16) uint32_t As_hi[128*AU];
    __shared__ __align__(16) uint32_t As_lo[128*AU];
    __shared__ uint32_t Bs_hi[NTILE*BU];
    __shared__ uint32_t Bs_lo[NTILE*BU];

    const int KP   = K >> 1;
    const int tid  = threadIdx.x;
    const int wid  = tid >> 5, lane = tid & 31;
    const int g    = lane >> 2, t = lane & 3;
    const int bm   = blockIdx.y * 128, bn = blockIdx.x * NTILE;
    const int m0   = (wid >> 2) * 64, n0 = (wid & 3) * (8*NI);

    float c[4][NI][4];
    #pragma unroll
    for (int mi = 0; mi < 4; mi++)
        #pragma unroll
        for (int ni = 0; ni < NI; ni++)
            #pragma unroll
            for (int j = 0; j < 4; j++) c[mi][ni][j] = 0.f;

    const int NKT = K >> 5;
    for (int kt = 0; kt < NKT; kt++) {
        const int kp0 = kt << 4;
        // ---- A tile: 128 rows x 16 u32 (hi+lo), uint4 chunks ----
        #pragma unroll
        for (int i = 0; i < 2; i++) {
            int f = tid + i*256;                  // 0..511
            int r = f >> 2, cc = (f & 3) << 2;
            const size_t go = (size_t)(bm + r)*KP + kp0 + cc;
            uint4 vh = *reinterpret_cast<const uint4*>(aH + go);
            uint4 vl = *reinterpret_cast<const uint4*>(aL + go);
            *reinterpret_cast<uint4*>(As_hi + r*AU + cc) = vh;
            *reinterpret_cast<uint4*>(As_lo + r*AU + cc) = vl;
        }
        // ---- B tile: NTILE n-rows x 16 u32 (hi+lo) ----
        #pragma unroll
        for (int i = 0; i < NI/2; i++) {
            int f = tid + i*256;                  // NTILE*4 items
            int n = f >> 2, cc = (f & 3) << 2;
            const size_t go = (size_t)(bn + n)*KP + kp0 + cc;
            uint4 vh = *reinterpret_cast<const uint4*>(bH + go);
            uint4 vl = *reinterpret_cast<const uint4*>(bL + go);
            int so = n*BU + cc;
            Bs_hi[so] = vh.x; Bs_hi[so+1] = vh.y; Bs_hi[so+2] = vh.z; Bs_hi[so+3] = vh.w;
            Bs_lo[so] = vl.x; Bs_lo[so+1] = vl.y; Bs_lo[so+2] = vl.z; Bs_lo[so+3] = vl.w;
        }
        __syncthreads();

        #pragma unroll
        for (int ks = 0; ks < 2; ks++) {
            const int kb = ks*8;
            uint32_t bh[NI][2], bl[NI][2];
            #pragma unroll
            for (int ni = 0; ni < NI; ni++) {
                int col = (n0 + ni*8 + g)*BU + kb;
                bh[ni][0] = Bs_hi[col + t];
                bh[ni][1] = Bs_hi[col + t + 4];
                bl[ni][0] = Bs_lo[col + t];
                bl[ni][1] = Bs_lo[col + t + 4];
            }
            #pragma unroll
            for (int mi = 0; mi < 4; mi++) {
                int row = m0 + mi*16 + g;
                uint32_t ah[4], al[4];
                ah[0] = As_hi[(row    )*AU + kb + t];
                ah[1] = As_hi[(row + 8)*AU + kb + t];
                ah[2] = As_hi[(row    )*AU + kb + t + 4];
                ah[3] = As_hi[(row + 8)*AU + kb + t + 4];
                al[0] = As_lo[(row    )*AU + kb + t];
                al[1] = As_lo[(row + 8)*AU + kb + t];
                al[2] = As_lo[(row    )*AU + kb + t + 4];
                al[3] = As_lo[(row + 8)*AU + kb + t + 4];
                #pragma unroll
                for (int ni = 0; ni < NI; ni++) {
                    MMA16(c[mi][ni], ah, bh[ni]);   // hi*hi
                    MMA16(c[mi][ni], ah, bl[ni]);   // hi*lo
                    MMA16(c[mi][ni], al, bh[ni]);   // lo*hi
                }
            }
        }
        __syncthreads();
    }

    // ---- epilogue ----
    #pragma unroll
    for (int mi = 0; mi < 4; mi++) {
        const int r0 = bm + m0 + mi*16 + g;
        #pragma unroll
        for (int ni = 0; ni < NI; ni++) {
            const int c0 = bn + n0 + ni*8 + t*2;
            #pragma unroll
            for (int j = 0; j < 4; j++) {
                const int gr = r0 + (j >> 1)*8;
                const int gc = c0 + (j & 1);
                if (!GUARD || gc < N) {
                    float v = c[mi][ni][j];
                    if (EPI >= 1) v += bias[gc];
                    if (EPI == 2) v = 0.5f*v*(1.f + erff(v*0.70710678118654752f));
                    C[(size_t)gr*ldc + gc] = v;
                }
            }
        }
    }
}

// ---------------- weight repack: [L,H,D,DK] -> [L,D,(3*512)] fp32 -------------
__global__ void repack_qkv_kernel(const float* __restrict__ WQ,
                                  const float* __restrict__ WK,
                                  const float* __restrict__ WV) {
    const int total = L_*H_*D_*DK_;
    for (int i = blockIdx.x*blockDim.x + threadIdx.x; i < total; i += gridDim.x*blockDim.x) {
        int kk = i % DK_;
        int d  = (i / DK_) % D_;
        int h  = (i / (DK_*D_)) % H_;
        int l  =  i / (DK_*D_*H_);
        int dst = l*D_*QKVW_ + d*QKVW_ + h*DK_ + kk;
        g_wqkv[dst        ] = WQ[i];
        g_wqkv[dst +   D_ ] = WK[i];
        g_wqkv[dst + 2*D_ ] = WV[i];
    }
}

// ---------------- embedding -----------------------------------------------------
__global__ void embed_kernel(const int* __restrict__ ids,
                             const float* __restrict__ tok,
                             const float* __restrict__ pos) {
    int row = blockIdx.x;
    int t   = row % T_;
    int id  = ids[row];
    const float sc = 22.62741699796952f;   // sqrt(512)
    for (int d = threadIdx.x; d < D_; d += blockDim.x) {
        float e = (id == PAD_) ? 0.f : tok[(size_t)id*D_ + d];
        g_x[(size_t)row*D_ + d] = e*sc + pos[(size_t)t*D_ + d];
    }
}

// ================== fused flash attention (causal, 32-row tiles, balanced) =====
// grid (16, BH): CTA bx processes Q-tiles bx and 31-bx -> uniform 17 k-iterations.
#define FA_SMEM ((64*33 + 2*64*66 + 32*66)*4)   // 50688 bytes

__device__ __forceinline__ void fa_tile32(float* qs, float* ks, float* vs, float* ps,
                                          const float* qb, const float* kb, const float* vb,
                                          int q, int b, int h, int tid) {
    const int wy = tid >> 5;          // warp 0..7 -> rows wy*4+m
    const int tx = tid & 31;          // cols tx*2+{0,1}

    // Q rows q*32..+31, dim-major: qs[dk][r]
    for (int i = tid; i < 2048; i += 256) {
        int r = i >> 6, cc = i & 63;
        qs[cc*33 + r] = qb[(size_t)(q*32 + r)*QKVW_ + cc];
    }

    float m_i[4], l_i[4], o[4][2];
    #pragma unroll
    for (int m = 0; m < 4; m++) {
        m_i[m] = -CUDART_INF_F; l_i[m] = 0.f;
        o[m][0] = 0.f; o[m][1] = 0.f;
    }

    const int nkt = (q + 2) >> 1;
    for (int kt = 0; kt < nkt; kt++) {
        __syncthreads();
        for (int i = tid; i < 4096; i += 256) {
            int r = i >> 6, cc = i & 63;
            ks[cc*66 + r] = kb[(size_t)(kt*64 + r)*QKVW_ + cc];
            vs[r*66 + cc] = vb[(size_t)(kt*64 + r)*QKVW_ + cc];
        }
        __syncthreads();

        float s[4][2] = {};
        #pragma unroll
        for (int kk = 0; kk < 64; kk++) {
            float2 bv = *reinterpret_cast<const float2*>(ks + kk*66 + tx*2);
            #pragma unroll
            for (int m = 0; m < 4; m++) {
                float a = qs[kk*33 + wy*4 + m];
                s[m][0] = fmaf(a, bv.x, s[m][0]);
                s[m][1] = fmaf(a, bv.y, s[m][1]);
            }
        }
        const bool last = (kt == nkt - 1);
        #pragma unroll
        for (int m = 0; m < 4; m++) {
            const int grow = q*32 + wy*4 + m;
            #pragma unroll
            for (int n = 0; n < 2; n++) {
                s[m][n] *= 0.125f;
                if (last && (kt*64 + tx*2 + n > grow)) s[m][n] = -CUDART_INF_F;
            }
        }

        #pragma unroll
        for (int m = 0; m < 4; m++) {
            float rmax = fmaxf(s[m][0], s[m][1]);
            #pragma unroll
            for (int off = 1; off < 32; off <<= 1)
                rmax = fmaxf(rmax, __shfl_xor_sync(0xffffffffu, rmax, off));
            const float mn = fmaxf(m_i[m], rmax);
            const float corr = __expf(m_i[m] - mn);
            float p0 = __expf(s[m][0] - mn);
            float p1 = __expf(s[m][1] - mn);
            float rsum = p0 + p1;
            #pragma unroll
            for (int off = 1; off < 32; off <<= 1)
                rsum += __shfl_xor_sync(0xffffffffu, rsum, off);
            l_i[m] = l_i[m]*corr + rsum;
            o[m][0] *= corr; o[m][1] *= corr;
            m_i[m] = mn;
            *reinterpret_cast<float2*>(ps + (wy*4 + m)*66 + tx*2) = make_float2(p0, p1);
        }
        __syncthreads();

        #pragma unroll
        for (int kk = 0; kk < 64; kk++) {
            float2 bv = *reinterpret_cast<const float2*>(vs + kk*66 + tx*2);
            #pragma unroll
            for (int m = 0; m < 4; m++) {
                float a = ps[(wy*4 + m)*66 + kk];
                o[m][0] = fmaf(a, bv.x, o[m][0]);
                o[m][1] = fmaf(a, bv.y, o[m][1]);
            }
        }
    }

    #pragma unroll
    for (int m = 0; m < 4; m++) {
        const float inv = 1.f / l_i[m];
        const int gr = b*T_ + q*32 + wy*4 + m;
        float2 ov = make_float2(o[m][0]*inv, o[m][1]*inv);
        *reinterpret_cast<float2*>(g_ctx + (size_t)gr*D_ + h*DK_ + tx*2) = ov;
    }
}

__global__ void __launch_bounds__(256) fattn_kernel() {
    extern __shared__ float fs[];
    float* qs = fs;
    float* ks = qs + 64*33;
    float* vs = ks + 64*66;
    float* ps = vs + 64*66;

    const int bx = blockIdx.x;               // 0..15 -> tiles bx and 31-bx
    const int bh = blockIdx.y;
    const int b = bh / H_, h = bh % H_;
    const float* qb = g_qkv + (size_t)b*T_*QKVW_ + h*DK_;
    const float* kb = qb + D_;
    const float* vb = qb + 2*D_;
    const int tid = threadIdx.x;

    fa_tile32(qs, ks, vs, ps, qb, kb, vb, bx,      b, h, tid);
    __syncthreads();
    fa_tile32(qs, ks, vs, ps, qb, kb, vb, 31 - bx, b, h, tid);
}

// ---------------- fused residual add + LayerNorm (in-place on g_x) -------------
__global__ void __launch_bounds__(256) add_ln_kernel(const float* __restrict__ g,
                                                     const float* __restrict__ bta) {
    const int row = blockIdx.x;
    float* x = g_x + (size_t)row*D_;
    const float* dl = g_tmp + (size_t)row*D_;
    const int tid = threadIdx.x;
    __shared__ float red[256];

    float v0 = x[tid]       + dl[tid];
    float v1 = x[tid + 256] + dl[tid + 256];

    red[tid] = v0 + v1; __syncthreads();
    for (int off = 128; off > 0; off >>= 1) {
        if (tid < off) red[tid] += red[tid + off];
        __syncthreads();
    }
    const float mu = red[0] * (1.f/512.f); __syncthreads();

    float d0 = v0 - mu, d1 = v1 - mu;
    red[tid] = d0*d0 + d1*d1; __syncthreads();
    for (int off = 128; off > 0; off >>= 1) {
        if (tid < off) red[tid] += red[tid + off];
        __syncthreads();
    }
    const float inv = rsqrtf(red[0]*(1.f/512.f) + 1e-5f);

    x[tid]       = d0*inv*g[tid]       + bta[tid];
    x[tid + 256] = d1*inv*g[tid + 256] + bta[tid + 256];
}

// ---------------- launch ---------------------------------------------------------
extern "C" void kernel_launch(void* const* d_in, const int* in_sizes, int n_in,
                              void* d_out, int out_size) {
    const int*   ids  = (const int*)  d_in[0];
    const float* tok  = (const float*)d_in[1];
    const float* pos  = (const float*)d_in[2];
    const float* WQ   = (const float*)d_in[3];
    const float* WK   = (const float*)d_in[4];
    const float* WV   = (const float*)d_in[5];
    const float* WO   = (const float*)d_in[6];
    const float* ln1g = (const float*)d_in[7];
    const float* ln1b = (const float*)d_in[8];
    const float* fc1w = (const float*)d_in[9];
    const float* fc1b = (const float*)d_in[10];
    const float* fc2w = (const float*)d_in[11];
    const float* fc2b = (const float*)d_in[12];
    const float* ln2g = (const float*)d_in[13];
    const float* ln2b = (const float*)d_in[14];
    const float* lmh  = (const float*)d_in[15];
    float* out = (float*)d_out;

    float *px, *pqkv, *pwqkv, *pctx, *ptmp, *pffn;
    cudaGetSymbolAddress((void**)&px,    g_x);
    cudaGetSymbolAddress((void**)&pqkv,  g_qkv);
    cudaGetSymbolAddress((void**)&pwqkv, g_wqkv);
    cudaGetSymbolAddress((void**)&pctx,  g_ctx);
    cudaGetSymbolAddress((void**)&ptmp,  g_tmp);
    cudaGetSymbolAddress((void**)&pffn,  g_ffn);

    uint32_t *aH, *aL, *qkH, *qkL, *woH, *woL, *f1H, *f1L, *f2H, *f2L, *lmH, *lmL;
    cudaGetSymbolAddress((void**)&aH,  g_aH);
    cudaGetSymbolAddress((void**)&aL,  g_aL);
    cudaGetSymbolAddress((void**)&qkH, g_wqkvH);
    cudaGetSymbolAddress((void**)&qkL, g_wqkvL);
    cudaGetSymbolAddress((void**)&woH, g_woH);
    cudaGetSymbolAddress((void**)&woL, g_woL);
    cudaGetSymbolAddress((void**)&f1H, g_fc1H);
    cudaGetSymbolAddress((void**)&f1L, g_fc1L);
    cudaGetSymbolAddress((void**)&f2H, g_fc2H);
    cudaGetSymbolAddress((void**)&f2L, g_fc2L);
    cudaGetSymbolAddress((void**)&lmH, g_lmhH);
    cudaGetSymbolAddress((void**)&lmL, g_lmhL);

    cudaFuncSetAttribute((const void*)fattn_kernel,
                         cudaFuncAttributeMaxDynamicSharedMemorySize, FA_SMEM);

    // ---- one-time (per launch) weight prepack ----
    repack_qkv_kernel<<<256, 256>>>(WQ, WK, WV);
    for (int l = 0; l < L_; l++) {
        prepack_b<<<512, 256>>>(pwqkv + (size_t)l*D_*QKVW_, qkH + (size_t)l*QKVW_*256,
                                qkL + (size_t)l*QKVW_*256, D_, QKVW_, QKVW_);
        prepack_b<<<512, 256>>>(WO + (size_t)l*D_*D_, woH + (size_t)l*D_*256,
                                woL + (size_t)l*D_*256, D_, D_, D_);
        prepack_b<<<512, 256>>>(fc1w + (size_t)l*D_*DFF_, f1H + (size_t)l*DFF_*256,
                                f1L + (size_t)l*DFF_*256, D_, DFF_, DFF_);
        prepack_b<<<512, 256>>>(fc2w + (size_t)l*DFF_*D_, f2H + (size_t)l*D_*1024,
                                f2L + (size_t)l*D_*1024, DFF_, D_, D_);
    }
    prepack_b<<<2048, 256>>>(lmh, lmH, lmL, D_, V_, VP_);

    embed_kernel<<<BT_, 256>>>(ids, tok, pos);

    for (int l = 0; l < L_; l++) {
        convert_a<<<512, 256>>>(px, BT_*D_/4);
        gemm_pk<0,false,4><<<dim3(QKVW_/128, BT_/128), 256>>>(
            BT_, QKVW_, D_, aH, aL, qkH + (size_t)l*QKVW_*256, qkL + (size_t)l*QKVW_*256,
            pqkv, QKVW_, nullptr);

        fattn_kernel<<<dim3(16, B_*H_), 256, FA_SMEM>>>();

        convert_a<<<512, 256>>>(pctx, BT_*D_/4);
        gemm_pk<0,false,2><<<dim3(D_/64, BT_/128), 256>>>(
            BT_, D_, D_, aH, aL, woH + (size_t)l*D_*256, woL + (size_t)l*D_*256,
            ptmp, D_, nullptr);

        add_ln_kernel<<<BT_, 256>>>(ln1g + l*D_, ln1b + l*D_);

        convert_a<<<512, 256>>>(px, BT_*D_/4);
        gemm_pk<2,false,4><<<dim3(DFF_/128, BT_/128), 256>>>(
            BT_, DFF_, D_, aH, aL, f1H + (size_t)l*DFF_*256, f1L + (size_t)l*DFF_*256,
            pffn, DFF_, fc1b + l*DFF_);

        convert_a<<<1024, 256>>>(pffn, BT_*DFF_/4);
        gemm_pk<1,false,2><<<dim3(D_/64, BT_/128), 256>>>(
            BT_, D_, DFF_, aH, aL, f2H + (size_t)l*D_*1024, f2L + (size_t)l*D_*1024,
            ptmp, D_, fc2b + l*D_);

        add_ln_kernel<<<BT_, 256>>>(ln2g + l*D_, ln2b + l*D_);
    }

    convert_a<<<512, 256>>>(px, BT_*D_/4);
    gemm_pk<0,true,4><<<dim3(VP_/128, BT_/128), 256>>>(
        BT_, V_, D_, aH, aL, lmH, lmL, out, V_, nullptr);
}

// round 7
// speedup vs baseline: 2.8432x; 1.2648x over previous
#include <cuda_runtime.h>
#include <cuda_bf16.h>
#include <math.h>
#include <math_constants.h>
#include <stdint.h>

#define B_   2
#define T_   1024
#define D_   512
#define H_   8
#define DK_  64
#define DFF_ 2048
#define L_   6
#define V_   50257
#define VP_  50304   // V padded to 128
#define PAD_ 50256
#define BT_  (B_*T_)
#define QKVW_ (3*D_)   // 1536

// ---------------- scratch (device globals; no allocations allowed) ----------
__device__ float g_x[BT_*D_];
__device__ float g_qkv[BT_*QKVW_];
__device__ float g_tmp[BT_*D_];
__device__ float g_wqkv[L_*D_*QKVW_];

// packed bf16 hi/lo activation buffers (u32 = bf16x2 of adjacent k)
__device__ uint32_t g_xH[BT_*256],  g_xL[BT_*256];    // x packed (K=512)
__device__ uint32_t g_cH[BT_*256],  g_cL[BT_*256];    // ctx packed
__device__ uint32_t g_fH[BT_*1024], g_fL[BT_*1024];   // ffn hidden packed (K=2048)
// packed weights
__device__ uint32_t g_wqkvH[L_*QKVW_*256], g_wqkvL[L_*QKVW_*256];
__device__ uint32_t g_woH[L_*D_*256],      g_woL[L_*D_*256];
__device__ uint32_t g_fc1H[L_*DFF_*256],   g_fc1L[L_*DFF_*256];
__device__ uint32_t g_fc2H[L_*D_*1024],    g_fc2L[L_*D_*1024];
__device__ uint32_t g_lmhH[(size_t)VP_*256], g_lmhL[(size_t)VP_*256];

// ---------------- bf16x3 pack helper -----------------------------------------
__device__ __forceinline__ void bpack(float x0, float x1, uint32_t& hi, uint32_t& lo) {
    __nv_bfloat16 h0 = __float2bfloat16(x0);
    __nv_bfloat16 h1 = __float2bfloat16(x1);
    __nv_bfloat16 l0 = __float2bfloat16(x0 - __bfloat162float(h0));
    __nv_bfloat16 l1 = __float2bfloat16(x1 - __bfloat162float(h1));
    hi = ((uint32_t)__bfloat16_as_ushort(h1) << 16) | (uint32_t)__bfloat16_as_ushort(h0);
    lo = ((uint32_t)__bfloat16_as_ushort(l1) << 16) | (uint32_t)__bfloat16_as_ushort(l0);
}

#define MMA16(cc, a, b) \
    asm volatile("mma.sync.aligned.m16n8k16.row.col.f32.bf16.bf16.f32 " \
        "{%0,%1,%2,%3}, {%4,%5,%6,%7}, {%8,%9}, {%0,%1,%2,%3};" \
        : "+f"((cc)[0]), "+f"((cc)[1]), "+f"((cc)[2]), "+f"((cc)[3]) \
        : "r"((a)[0]), "r"((a)[1]), "r"((a)[2]), "r"((a)[3]), \
          "r"((b)[0]), "r"((b)[1]))

__device__ __forceinline__ void cpa16(uint32_t dst, const void* src) {
    asm volatile("cp.async.cg.shared.global [%0], [%1], 16;" :: "r"(dst), "l"(src));
}
#define CP_COMMIT() asm volatile("cp.async.commit_group;" ::: "memory")

// ---------------- prepack: W fp32 [K][N] -> [Npad][K/2] packed, coalesced ------
// 64n x 32kp transpose tile through smem.
__global__ void prepack_b(const float* __restrict__ W, uint32_t* __restrict__ oH,
                          uint32_t* __restrict__ oL, int K, int N, int Npad) {
    __shared__ uint32_t sh[64*33], sl[64*33];
    const int KP = K >> 1;
    const int n0 = blockIdx.x * 64, kp0 = blockIdx.y * 32;
    const int tid = threadIdx.x;

    #pragma unroll
    for (int i = 0; i < 8; i++) {
        int f = tid + i*256;
        int n = f & 63, kp = f >> 6;
        int gn = n0 + n;
        float x0 = 0.f, x1 = 0.f;
        if (gn < N) {
            int k2 = (kp0 + kp) * 2;
            x0 = W[(size_t)k2*N + gn];
            x1 = W[(size_t)(k2 + 1)*N + gn];
        }
        uint32_t h, l;
        bpack(x0, x1, h, l);
        sh[n*33 + kp] = h;
        sl[n*33 + kp] = l;
    }
    __syncthreads();
    #pragma unroll
    for (int i = 0; i < 8; i++) {
        int f = tid + i*256;
        int kp = f & 31, n = f >> 5;
        size_t go = (size_t)(n0 + n)*KP + kp0 + kp;
        oH[go] = sh[n*33 + kp];
        oL[go] = sl[n*33 + kp];
    }
}

// ============== bf16x3 mma.sync GEMM, cp.async double-buffered =================
// CTA tile 128 x (32*NI), 8 warps (2x4), warp 64 x (8*NI), BK=32 (16 k-pairs).
// OUT: 0 = fp32 C, 1 = packed hi/lo (k-pairs along N).
// EPI: 0 none, 1 +bias, 2 +bias+GELU.  GUARD: ragged-N store guard (fp32 out).
#define AU 20   // u32 row stride (16 data + 4 pad; keeps 16B alignment, no bank conflicts)

template<int OUT, int EPI, bool GUARD, int NI>
__global__ void __launch_bounds__(256, 2)
gemm_pk(int M, int N, int K,
        const uint32_t* __restrict__ aH, const uint32_t* __restrict__ aL,
        const uint32_t* __restrict__ bH, const uint32_t* __restrict__ bL,
        float* __restrict__ C, int ldc,
        uint32_t* __restrict__ oH, uint32_t* __restrict__ oL,
        const float* __restrict__ bias)
{
    constexpr int NTILE = 32*NI;
    extern __shared__ uint32_t su[];
    uint32_t* AsH = su;                         // [2][128*AU]
    uint32_t* AsL = su + 2*128*AU;
    uint32_t* BsH = su + 4*128*AU;              // [2][NTILE*AU]
    uint32_t* BsL = BsH + 2*NTILE*AU;
    const uint32_t sb = (uint32_t)__cvta_generic_to_shared(su);
    const uint32_t sbAH = sb;
    const uint32_t sbAL = sb + 2*128*AU*4;
    const uint32_t sbBH = sb + 4*128*AU*4;
    const uint32_t sbBL = sbBH + 2*NTILE*AU*4;

    const int KP   = K >> 1;
    const int tid  = threadIdx.x;
    const int wid  = tid >> 5, lane = tid & 31;
    const int g    = lane >> 2, t = lane & 3;
    const int bm   = blockIdx.y * 128, bn = blockIdx.x * NTILE;
    const int m0   = (wid >> 2) * 64, n0 = (wid & 3) * (8*NI);

    float c[4][NI][4];
    #pragma unroll
    for (int mi = 0; mi < 4; mi++)
        #pragma unroll
        for (int ni = 0; ni < NI; ni++)
            #pragma unroll
            for (int j = 0; j < 4; j++) c[mi][ni][j] = 0.f;

    const int NKT = K >> 5;

    auto load_tile = [&](int kt, int pb) {
        const int kp0 = kt << 4;
        #pragma unroll
        for (int i = 0; i < 2; i++) {            // A: 128 rows x 16 u32
            int f = tid + i*256;
            int r = f >> 2, cc = (f & 3) << 2;
            size_t go = (size_t)(bm + r)*KP + kp0 + cc;
            uint32_t so = (uint32_t)((pb*128 + r)*AU + cc)*4;
            cpa16(sbAH + so, aH + go);
            cpa16(sbAL + so, aL + go);
        }
        #pragma unroll
        for (int i = 0; i < NI/2; i++) {         // B: NTILE rows x 16 u32
            int f = tid + i*256;
            int n = f >> 2, cc = (f & 3) << 2;
            size_t go = (size_t)(bn + n)*KP + kp0 + cc;
            uint32_t so = (uint32_t)((pb*NTILE + n)*AU + cc)*4;
            cpa16(sbBH + so, bH + go);
            cpa16(sbBL + so, bL + go);
        }
        CP_COMMIT();
    };

    load_tile(0, 0);

    for (int kt = 0; kt < NKT; kt++) {
        const int pb = kt & 1;
        if (kt + 1 < NKT) {
            load_tile(kt + 1, pb ^ 1);
            asm volatile("cp.async.wait_group 1;" ::: "memory");
        } else {
            asm volatile("cp.async.wait_group 0;" ::: "memory");
        }
        __syncthreads();

        const uint32_t* ah_b = AsH + pb*128*AU;
        const uint32_t* al_b = AsL + pb*128*AU;
        const uint32_t* bh_b = BsH + pb*NTILE*AU;
        const uint32_t* bl_b = BsL + pb*NTILE*AU;

        #pragma unroll
        for (int ks = 0; ks < 2; ks++) {
            const int kb = ks*8;
            uint32_t bh[NI][2], bl[NI][2];
            #pragma unroll
            for (int ni = 0; ni < NI; ni++) {
                int col = (n0 + ni*8 + g)*AU + kb;
                bh[ni][0] = bh_b[col + t];
                bh[ni][1] = bh_b[col + t + 4];
                bl[ni][0] = bl_b[col + t];
                bl[ni][1] = bl_b[col + t + 4];
            }
            #pragma unroll
            for (int mi = 0; mi < 4; mi++) {
                int row = m0 + mi*16 + g;
                uint32_t ah[4], al[4];
                ah[0] = ah_b[(row    )*AU + kb + t];
                ah[1] = ah_b[(row + 8)*AU + kb + t];
                ah[2] = ah_b[(row    )*AU + kb + t + 4];
                ah[3] = ah_b[(row + 8)*AU + kb + t + 4];
                al[0] = al_b[(row    )*AU + kb + t];
                al[1] = al_b[(row + 8)*AU + kb + t];
                al[2] = al_b[(row    )*AU + kb + t + 4];
                al[3] = al_b[(row + 8)*AU + kb + t + 4];
                #pragma unroll
                for (int ni = 0; ni < NI; ni++) {
                    MMA16(c[mi][ni], ah, bh[ni]);   // hi*hi
                    MMA16(c[mi][ni], ah, bl[ni]);   // hi*lo
                    MMA16(c[mi][ni], al, bh[ni]);   // lo*hi
                }
            }
        }
        __syncthreads();
    }

    // ---- epilogue ----
    const int KP2 = N >> 1;                       // packed-out row stride
    #pragma unroll
    for (int mi = 0; mi < 4; mi++) {
        const int r0 = bm + m0 + mi*16 + g;
        #pragma unroll
        for (int ni = 0; ni < NI; ni++) {
            const int c0 = bn + n0 + ni*8 + t*2;
            #pragma unroll
            for (int half = 0; half < 2; half++) {
                const int gr = r0 + half*8;
                float v0 = c[mi][ni][2*half + 0];
                float v1 = c[mi][ni][2*half + 1];
                if (EPI >= 1) { v0 += bias[c0]; v1 += bias[c0 + 1]; }
                if (EPI == 2) {
                    v0 = 0.5f*v0*(1.f + erff(v0*0.70710678118654752f));
                    v1 = 0.5f*v1*(1.f + erff(v1*0.70710678118654752f));
                }
                if (OUT == 0) {
                    if (!GUARD || c0 < N)     C[(size_t)gr*ldc + c0]     = v0;
                    if (!GUARD || c0 + 1 < N) C[(size_t)gr*ldc + c0 + 1] = v1;
                } else {
                    uint32_t h, l;
                    bpack(v0, v1, h, l);
                    oH[(size_t)gr*KP2 + (c0 >> 1)] = h;
                    oL[(size_t)gr*KP2 + (c0 >> 1)] = l;
                }
            }
        }
    }
}

// ---------------- weight repack: [L,H,D,DK] -> [L,D,(3*512)] fp32 -------------
__global__ void repack_qkv_kernel(const float* __restrict__ WQ,
                                  const float* __restrict__ WK,
                                  const float* __restrict__ WV) {
    const int total = L_*H_*D_*DK_;
    for (int i = blockIdx.x*blockDim.x + threadIdx.x; i < total; i += gridDim.x*blockDim.x) {
        int kk = i % DK_;
        int d  = (i / DK_) % D_;
        int h  = (i / (DK_*D_)) % H_;
        int l  =  i / (DK_*D_*H_);
        int dst = l*D_*QKVW_ + d*QKVW_ + h*DK_ + kk;
        g_wqkv[dst        ] = WQ[i];
        g_wqkv[dst +   D_ ] = WK[i];
        g_wqkv[dst + 2*D_ ] = WV[i];
    }
}

// ---------------- embedding: fp32 x + packed x ---------------------------------
__global__ void embed_kernel(const int* __restrict__ ids,
                             const float* __restrict__ tok,
                             const float* __restrict__ pos) {
    const int row = blockIdx.x;
    const int t   = row % T_;
    const int id  = ids[row];
    const int tid = threadIdx.x;          // 256 threads, 2 elems each
    const float sc = 22.62741699796952f;  // sqrt(512)
    const int d = tid*2;
    float e0 = (id == PAD_) ? 0.f : tok[(size_t)id*D_ + d];
    float e1 = (id == PAD_) ? 0.f : tok[(size_t)id*D_ + d + 1];
    float v0 = e0*sc + pos[(size_t)t*D_ + d];
    float v1 = e1*sc + pos[(size_t)t*D_ + d + 1];
    *reinterpret_cast<float2*>(g_x + (size_t)row*D_ + d) = make_float2(v0, v1);
    uint32_t h, l;
    bpack(v0, v1, h, l);
    g_xH[row*256 + tid] = h;
    g_xL[row*256 + tid] = l;
}

// ================== fused flash attention (causal, 32-row tiles, balanced) =====
// grid (16, BH): CTA bx processes Q-tiles bx and 31-bx. Output packed (g_cH/g_cL).
#define FA_SMEM ((64*33 + 2*64*66 + 32*66)*4)   // 50688 bytes

__device__ __forceinline__ void fa_tile32(float* qs, float* ks, float* vs, float* ps,
                                          const float* qb, const float* kb, const float* vb,
                                          int q, int b, int h, int tid) {
    const int wy = tid >> 5;          // warp 0..7 -> rows wy*4+m
    const int tx = tid & 31;          // cols tx*2+{0,1}

    for (int i = tid; i < 2048; i += 256) {
        int r = i >> 6, cc = i & 63;
        qs[cc*33 + r] = qb[(size_t)(q*32 + r)*QKVW_ + cc];
    }

    float m_i[4], l_i[4], o[4][2];
    #pragma unroll
    for (int m = 0; m < 4; m++) {
        m_i[m] = -CUDART_INF_F; l_i[m] = 0.f;
        o[m][0] = 0.f; o[m][1] = 0.f;
    }

    const int nkt = (q + 2) >> 1;
    for (int kt = 0; kt < nkt; kt++) {
        __syncthreads();
        for (int i = tid; i < 4096; i += 256) {
            int r = i >> 6, cc = i & 63;
            ks[cc*66 + r] = kb[(size_t)(kt*64 + r)*QKVW_ + cc];
            vs[r*66 + cc] = vb[(size_t)(kt*64 + r)*QKVW_ + cc];
        }
        __syncthreads();

        float s[4][2] = {};
        #pragma unroll
        for (int kk = 0; kk < 64; kk++) {
            float2 bv = *reinterpret_cast<const float2*>(ks + kk*66 + tx*2);
            #pragma unroll
            for (int m = 0; m < 4; m++) {
                float a = qs[kk*33 + wy*4 + m];
                s[m][0] = fmaf(a, bv.x, s[m][0]);
                s[m][1] = fmaf(a, bv.y, s[m][1]);
            }
        }
        const bool last = (kt == nkt - 1);
        #pragma unroll
        for (int m = 0; m < 4; m++) {
            const int grow = q*32 + wy*4 + m;
            #pragma unroll
            for (int n = 0; n < 2; n++) {
                s[m][n] *= 0.125f;
                if (last && (kt*64 + tx*2 + n > grow)) s[m][n] = -CUDART_INF_F;
            }
        }

        #pragma unroll
        for (int m = 0; m < 4; m++) {
            float rmax = fmaxf(s[m][0], s[m][1]);
            #pragma unroll
            for (int off = 1; off < 32; off <<= 1)
                rmax = fmaxf(rmax, __shfl_xor_sync(0xffffffffu, rmax, off));
            const float mn = fmaxf(m_i[m], rmax);
            const float corr = __expf(m_i[m] - mn);
            float p0 = __expf(s[m][0] - mn);
            float p1 = __expf(s[m][1] - mn);
            float rsum = p0 + p1;
            #pragma unroll
            for (int off = 1; off < 32; off <<= 1)
                rsum += __shfl_xor_sync(0xffffffffu, rsum, off);
            l_i[m] = l_i[m]*corr + rsum;
            o[m][0] *= corr; o[m][1] *= corr;
            m_i[m] = mn;
            *reinterpret_cast<float2*>(ps + (wy*4 + m)*66 + tx*2) = make_float2(p0, p1);
        }
        __syncthreads();

        #pragma unroll
        for (int kk = 0; kk < 64; kk++) {
            float2 bv = *reinterpret_cast<const float2*>(vs + kk*66 + tx*2);
            #pragma unroll
            for (int m = 0; m < 4; m++) {
                float a = ps[(wy*4 + m)*66 + kk];
                o[m][0] = fmaf(a, bv.x, o[m][0]);
                o[m][1] = fmaf(a, bv.y, o[m][1]);
            }
        }
    }

    #pragma unroll
    for (int m = 0; m < 4; m++) {
        const float inv = 1.f / l_i[m];
        const int gr = b*T_ + q*32 + wy*4 + m;
        float v0 = o[m][0]*inv, v1 = o[m][1]*inv;
        uint32_t hh, ll;
        bpack(v0, v1, hh, ll);
        const int kp = (h*DK_ + tx*2) >> 1;
        g_cH[gr*256 + kp] = hh;
        g_cL[gr*256 + kp] = ll;
    }
}

__global__ void __launch_bounds__(256) fattn_kernel() {
    extern __shared__ float fs[];
    float* qs = fs;
    float* ks = qs + 64*33;
    float* vs = ks + 64*66;
    float* ps = vs + 64*66;

    const int bx = blockIdx.x;
    const int bh = blockIdx.y;
    const int b = bh / H_, h = bh % H_;
    const float* qb = g_qkv + (size_t)b*T_*QKVW_ + h*DK_;
    const float* kb = qb + D_;
    const float* vb = qb + 2*D_;
    const int tid = threadIdx.x;

    fa_tile32(qs, ks, vs, ps, qb, kb, vb, bx,      b, h, tid);
    __syncthreads();
    fa_tile32(qs, ks, vs, ps, qb, kb, vb, 31 - bx, b, h, tid);
}

// ------------- fused residual add + LayerNorm -> fp32 x AND packed x -----------
__global__ void __launch_bounds__(256) add_ln_kernel(const float* __restrict__ g,
                                                     const float* __restrict__ bta) {
    const int row = blockIdx.x;
    float* x = g_x + (size_t)row*D_;
    const float* dl = g_tmp + (size_t)row*D_;
    const int tid = threadIdx.x;
    __shared__ float red[256];

    float2 xv = reinterpret_cast<const float2*>(x)[tid];
    float2 dv = reinterpret_cast<const float2*>(dl)[tid];
    float v0 = xv.x + dv.x;
    float v1 = xv.y + dv.y;

    red[tid] = v0 + v1; __syncthreads();
    for (int off = 128; off > 0; off >>= 1) {
        if (tid < off) red[tid] += red[tid + off];
        __syncthreads();
    }
    const float mu = red[0] * (1.f/512.f); __syncthreads();

    float d0 = v0 - mu, d1 = v1 - mu;
    red[tid] = d0*d0 + d1*d1; __syncthreads();
    for (int off = 128; off > 0; off >>= 1) {
        if (tid < off) red[tid] += red[tid + off];
        __syncthreads();
    }
    const float inv = rsqrtf(red[0]*(1.f/512.f) + 1e-5f);

    const int d = tid*2;
    float o0 = d0*inv*g[d]     + bta[d];
    float o1 = d1*inv*g[d + 1] + bta[d + 1];
    reinterpret_cast<float2*>(x)[tid] = make_float2(o0, o1);
    uint32_t h, l;
    bpack(o0, o1, h, l);
    g_xH[row*256 + tid] = h;
    g_xL[row*256 + tid] = l;
}

// ---------------- launch ---------------------------------------------------------
#define SMEM_NI4 ((4*128*AU + 4*128*AU)*4)   // 81920
#define SMEM_NI2 ((4*128*AU + 4*64*AU)*4)    // 61440

extern "C" void kernel_launch(void* const* d_in, const int* in_sizes, int n_in,
                              void* d_out, int out_size) {
    const int*   ids  = (const int*)  d_in[0];
    const float* tok  = (const float*)d_in[1];
    const float* pos  = (const float*)d_in[2];
    const float* WQ   = (const float*)d_in[3];
    const float* WK   = (const float*)d_in[4];
    const float* WV   = (const float*)d_in[5];
    const float* WO   = (const float*)d_in[6];
    const float* ln1g = (const float*)d_in[7];
    const float* ln1b = (const float*)d_in[8];
    const float* fc1w = (const float*)d_in[9];
    const float* fc1b = (const float*)d_in[10];
    const float* fc2w = (const float*)d_in[11];
    const float* fc2b = (const float*)d_in[12];
    const float* ln2g = (const float*)d_in[13];
    const float* ln2b = (const float*)d_in[14];
    const float* lmh  = (const float*)d_in[15];
    float* out = (float*)d_out;

    float *px, *pqkv, *pwqkv, *ptmp;
    cudaGetSymbolAddress((void**)&px,    g_x);
    cudaGetSymbolAddress((void**)&pqkv,  g_qkv);
    cudaGetSymbolAddress((void**)&pwqkv, g_wqkv);
    cudaGetSymbolAddress((void**)&ptmp,  g_tmp);

    uint32_t *xH, *xL, *cH, *cL, *fH, *fL;
    uint32_t *qkH, *qkL, *woH, *woL, *f1H, *f1L, *f2H, *f2L, *lmH, *lmL;
    cudaGetSymbolAddress((void**)&xH,  g_xH);
    cudaGetSymbolAddress((void**)&xL,  g_xL);
    cudaGetSymbolAddress((void**)&cH,  g_cH);
    cudaGetSymbolAddress((void**)&cL,  g_cL);
    cudaGetSymbolAddress((void**)&fH,  g_fH);
    cudaGetSymbolAddress((void**)&fL,  g_fL);
    cudaGetSymbolAddress((void**)&qkH, g_wqkvH);
    cudaGetSymbolAddress((void**)&qkL, g_wqkvL);
    cudaGetSymbolAddress((void**)&woH, g_woH);
    cudaGetSymbolAddress((void**)&woL, g_woL);
    cudaGetSymbolAddress((void**)&f1H, g_fc1H);
    cudaGetSymbolAddress((void**)&f1L, g_fc1L);
    cudaGetSymbolAddress((void**)&f2H, g_fc2H);
    cudaGetSymbolAddress((void**)&f2L, g_fc2L);
    cudaGetSymbolAddress((void**)&lmH, g_lmhH);
    cudaGetSymbolAddress((void**)&lmL, g_lmhL);

    cudaFuncSetAttribute((const void*)fattn_kernel,
                         cudaFuncAttributeMaxDynamicSharedMemorySize, FA_SMEM);
    cudaFuncSetAttribute((const void*)gemm_pk<0,0,false,4>, cudaFuncAttributeMaxDynamicSharedMemorySize, SMEM_NI4);
    cudaFuncSetAttribute((const void*)gemm_pk<0,0,false,2>, cudaFuncAttributeMaxDynamicSharedMemorySize, SMEM_NI2);
    cudaFuncSetAttribute((const void*)gemm_pk<1,2,false,4>, cudaFuncAttributeMaxDynamicSharedMemorySize, SMEM_NI4);
    cudaFuncSetAttribute((const void*)gemm_pk<0,1,false,2>, cudaFuncAttributeMaxDynamicSharedMemorySize, SMEM_NI2);
    cudaFuncSetAttribute((const void*)gemm_pk<0,0,true,4>,  cudaFuncAttributeMaxDynamicSharedMemorySize, SMEM_NI4);

    // ---- weight prepack (coalesced transpose) ----
    repack_qkv_kernel<<<256, 256>>>(WQ, WK, WV);
    for (int l = 0; l < L_; l++) {
        prepack_b<<<dim3(QKVW_/64, 256/32), 256>>>(pwqkv + (size_t)l*D_*QKVW_,
            qkH + (size_t)l*QKVW_*256, qkL + (size_t)l*QKVW_*256, D_, QKVW_, QKVW_);
        prepack_b<<<dim3(D_/64, 256/32), 256>>>(WO + (size_t)l*D_*D_,
            woH + (size_t)l*D_*256, woL + (size_t)l*D_*256, D_, D_, D_);
        prepack_b<<<dim3(DFF_/64, 256/32), 256>>>(fc1w + (size_t)l*D_*DFF_,
            f1H + (size_t)l*DFF_*256, f1L + (size_t)l*DFF_*256, D_, DFF_, DFF_);
        prepack_b<<<dim3(D_/64, 1024/32), 256>>>(fc2w + (size_t)l*DFF_*D_,
            f2H + (size_t)l*D_*1024, f2L + (size_t)l*D_*1024, DFF_, D_, D_);
    }
    prepack_b<<<dim3(VP_/64, 256/32), 256>>>(lmh, lmH, lmL, D_, V_, VP_);

    embed_kernel<<<BT_, 256>>>(ids, tok, pos);

    for (int l = 0; l < L_; l++) {
        gemm_pk<0,0,false,4><<<dim3(QKVW_/128, BT_/128), 256, SMEM_NI4>>>(
            BT_, QKVW_, D_, xH, xL,
            qkH + (size_t)l*QKVW_*256, qkL + (size_t)l*QKVW_*256,
            pqkv, QKVW_, nullptr, nullptr, nullptr);

        fattn_kernel<<<dim3(16, B_*H_), 256, FA_SMEM>>>();

        gemm_pk<0,0,false,2><<<dim3(D_/64, BT_/128), 256, SMEM_NI2>>>(
            BT_, D_, D_, cH, cL,
            woH + (size_t)l*D_*256, woL + (size_t)l*D_*256,
            ptmp, D_, nullptr, nullptr, nullptr);

        add_ln_kernel<<<BT_, 256>>>(ln1g + l*D_, ln1b + l*D_);

        gemm_pk<1,2,false,4><<<dim3(DFF_/128, BT_/128), 256, SMEM_NI4>>>(
            BT_, DFF_, D_, xH, xL,
            f1H + (size_t)l*DFF_*256, f1L + (size_t)l*DFF_*256,
            nullptr, 0, fH, fL, fc1b + l*DFF_);

        gemm_pk<0,1,false,2><<<dim3(D_/64, BT_/128), 256, SMEM_NI2>>>(
            BT_, D_, DFF_, fH, fL,
            f2H + (size_t)l*D_*1024, f2L + (size_t)l*D_*1024,
            ptmp, D_, nullptr, nullptr, fc2b + l*D_);

        add_ln_kernel<<<BT_, 256>>>(ln2g + l*D_, ln2b + l*D_);
    }

    gemm_pk<0,0,true,4><<<dim3(VP_/128, BT_/128), 256, SMEM_NI4>>>(
        BT_, V_, D_, xH, xL, lmH, lmL, out, V_, nullptr, nullptr, nullptr);
}

// round 8
// speedup vs baseline: 3.4316x; 1.2070x over previous
#include <cuda_runtime.h>
#include <cuda_bf16.h>
#include <math.h>
#include <math_constants.h>
#include <stdint.h>

#define B_   2
#define T_   1024
#define D_   512
#define H_   8
#define DK_  64
#define DFF_ 2048
#define L_   6
#define V_   50257
#define VP_  50304   // V padded to 128
#define PAD_ 50256
#define BT_  (B_*T_)
#define QKVW_ (3*D_)   // 1536

// ---------------- scratch (device globals; no allocations allowed) ----------
__device__ float g_x[BT_*D_];
__device__ float g_v[BT_*D_];                          // V fp32 (per layer)
__device__ float g_tmp[BT_*D_];

// packed bf16 hi/lo activation buffers (u32 = bf16x2 of adjacent k)
__device__ uint32_t g_xH[BT_*256],  g_xL[BT_*256];     // x packed (K=512)
__device__ uint32_t g_cH[BT_*256],  g_cL[BT_*256];     // ctx packed
__device__ uint32_t g_fH[BT_*1024], g_fL[BT_*1024];    // ffn hidden packed
__device__ uint32_t g_qkpH[BT_*512], g_qkpL[BT_*512];  // Q,K packed (512 pairs/row)
// packed weights
__device__ uint32_t g_wqkvH[L_*QKVW_*256], g_wqkvL[L_*QKVW_*256];
__device__ uint32_t g_woH[L_*D_*256],      g_woL[L_*D_*256];
__device__ uint32_t g_fc1H[L_*DFF_*256],   g_fc1L[L_*DFF_*256];
__device__ uint32_t g_fc2H[L_*D_*1024],    g_fc2L[L_*D_*1024];
__device__ uint32_t g_lmhH[(size_t)VP_*256], g_lmhL[(size_t)VP_*256];

// ---------------- helpers ------------------------------------------------------
__device__ __forceinline__ void bpack(float x0, float x1, uint32_t& hi, uint32_t& lo) {
    __nv_bfloat16 h0 = __float2bfloat16(x0);
    __nv_bfloat16 h1 = __float2bfloat16(x1);
    __nv_bfloat16 l0 = __float2bfloat16(x0 - __bfloat162float(h0));
    __nv_bfloat16 l1 = __float2bfloat16(x1 - __bfloat162float(h1));
    hi = ((uint32_t)__bfloat16_as_ushort(h1) << 16) | (uint32_t)__bfloat16_as_ushort(h0);
    lo = ((uint32_t)__bfloat16_as_ushort(l1) << 16) | (uint32_t)__bfloat16_as_ushort(l0);
}

// fast exp on the FMA pipe (arg <= 0 path; clamps; ~2e-8 rel err)
__device__ __forceinline__ float fexp(float x) {
    x = fmaxf(x, -87.0f);
    float t = fmaf(x, 1.4426950408889634f, 12582912.0f);   // round-to-nearest int
    float r = t - 12582912.0f;
    float f = fmaf(x, 1.4426950408889634f, -r);
    float p =        1.3333558e-3f;
    p = fmaf(p, f, 9.6181291e-3f);
    p = fmaf(p, f, 5.5504109e-2f);
    p = fmaf(p, f, 2.4022651e-1f);
    p = fmaf(p, f, 6.9314718e-1f);
    p = fmaf(p, f, 1.0f);
    int e = (__float_as_int(t) + 127) << 23;
    return p * __int_as_float(e);
}

#define MMA16(cc, a, b) \
    asm volatile("mma.sync.aligned.m16n8k16.row.col.f32.bf16.bf16.f32 " \
        "{%0,%1,%2,%3}, {%4,%5,%6,%7}, {%8,%9}, {%0,%1,%2,%3};" \
        : "+f"((cc)[0]), "+f"((cc)[1]), "+f"((cc)[2]), "+f"((cc)[3]) \
        : "r"((a)[0]), "r"((a)[1]), "r"((a)[2]), "r"((a)[3]), \
          "r"((b)[0]), "r"((b)[1]))

__device__ __forceinline__ void cpa16(uint32_t dst, const void* src) {
    asm volatile("cp.async.cg.shared.global [%0], [%1], 16;" :: "r"(dst), "l"(src));
}
#define CP_COMMIT() asm volatile("cp.async.commit_group;" ::: "memory")

// ================ prepack kernels (coalesced transpose) ========================
// lm_head: W fp32 [K][N] -> [Npad][K/2] packed
__global__ void prepack_b(const float* __restrict__ W, uint32_t* __restrict__ oH,
                          uint32_t* __restrict__ oL, int K, int N, int Npad) {
    __shared__ uint32_t sh[64*33], sl[64*33];
    const int KP = K >> 1;
    const int n0 = blockIdx.x * 64, kp0 = blockIdx.y * 32;
    const int tid = threadIdx.x;
    #pragma unroll
    for (int i = 0; i < 8; i++) {
        int f = tid + i*256;
        int n = f & 63, kp = f >> 6;
        int gn = n0 + n;
        float x0 = 0.f, x1 = 0.f;
        if (gn < N) {
            int k2 = (kp0 + kp) * 2;
            x0 = W[(size_t)k2*N + gn];
            x1 = W[(size_t)(k2 + 1)*N + gn];
        }
        uint32_t h, l;
        bpack(x0, x1, h, l);
        sh[n*33 + kp] = h;
        sl[n*33 + kp] = l;
    }
    __syncthreads();
    #pragma unroll
    for (int i = 0; i < 8; i++) {
        int f = tid + i*256;
        int kp = f & 31, n = f >> 5;
        size_t go = (size_t)(n0 + n)*KP + kp0 + kp;
        oH[go] = sh[n*33 + kp];
        oL[go] = sl[n*33 + kp];
    }
}

// QKV weights straight from WQ/WK/WV [L,H,D,DK] -> [L][1536 n][256 kp] packed
__global__ void prepack_qkvw(const float* __restrict__ WQ,
                             const float* __restrict__ WK,
                             const float* __restrict__ WV) {
    __shared__ uint32_t sh[64*33], sl[64*33];
    const int l = blockIdx.z;
    const int n0 = blockIdx.x*64, kp0 = blockIdx.y*32;
    const int tid = threadIdx.x;
    #pragma unroll
    for (int i = 0; i < 8; i++) {
        int f = tid + i*256;
        int n = f & 63, kp = f >> 6;
        int gn = n0 + n;
        int part = gn >> 9, hh = (gn >> 6) & 7, kk = gn & 63;
        const float* W = part == 0 ? WQ : (part == 1 ? WK : WV);
        size_t base = (((size_t)l*H_ + hh)*D_ + 2*(kp0 + kp))*DK_ + kk;
        uint32_t h, l2;
        bpack(W[base], W[base + DK_], h, l2);
        sh[n*33 + kp] = h;
        sl[n*33 + kp] = l2;
    }
    __syncthreads();
    #pragma unroll
    for (int i = 0; i < 8; i++) {
        int f = tid + i*256;
        int kp = f & 31, n = f >> 5;
        size_t go = (size_t)l*QKVW_*256 + (size_t)(n0 + n)*256 + kp0 + kp;
        g_wqkvH[go] = sh[n*33 + kp];
        g_wqkvL[go] = sl[n*33 + kp];
    }
}

// WO/FC1/FC2 for all layers, z = type*L + l
__global__ void prepack_small(const float* __restrict__ WO,
                              const float* __restrict__ F1,
                              const float* __restrict__ F2) {
    __shared__ uint32_t sh[64*33], sl[64*33];
    const int z = blockIdx.z;
    const int type = z / L_, l = z % L_;
    int K, N; const float* W; uint32_t *oH, *oL;
    if (type == 0)      { K = D_;   N = D_;   W = WO + (size_t)l*D_*D_;    oH = g_woH  + (size_t)l*D_*256;   oL = g_woL  + (size_t)l*D_*256; }
    else if (type == 1) { K = D_;   N = DFF_; W = F1 + (size_t)l*D_*DFF_;  oH = g_fc1H + (size_t)l*DFF_*256; oL = g_fc1L + (size_t)l*DFF_*256; }
    else                { K = DFF_; N = D_;   W = F2 + (size_t)l*DFF_*D_;  oH = g_fc2H + (size_t)l*D_*1024;  oL = g_fc2L + (size_t)l*D_*1024; }
    const int KP = K >> 1;
    const int n0 = blockIdx.x*64, kp0 = blockIdx.y*32;
    if (n0 >= N || kp0 >= KP) return;
    const int tid = threadIdx.x;
    #pragma unroll
    for (int i = 0; i < 8; i++) {
        int f = tid + i*256;
        int n = f & 63, kp = f >> 6;
        int k2 = (kp0 + kp)*2;
        uint32_t h, l2;
        bpack(W[(size_t)k2*N + n0 + n], W[(size_t)(k2+1)*N + n0 + n], h, l2);
        sh[n*33 + kp] = h;
        sl[n*33 + kp] = l2;
    }
    __syncthreads();
    #pragma unroll
    for (int i = 0; i < 8; i++) {
        int f = tid + i*256;
        int kp = f & 31, n = f >> 5;
        size_t go = (size_t)(n0 + n)*KP + kp0 + kp;
        oH[go] = sh[n*33 + kp];
        oL[go] = sl[n*33 + kp];
    }
}

// ============== bf16x3 mma.sync GEMM, cp.async double-buffered =================
// OUT: 0 fp32 C, 1 packed hi/lo, 2 qkv-mode (c<1024 packed to Q/K buf, else fp32 V)
#define AU 20

template<int OUT, int EPI, bool GUARD, int NI>
__global__ void __launch_bounds__(256, 2)
gemm_pk(int M, int N, int K,
        const uint32_t* __restrict__ aH, const uint32_t* __restrict__ aL,
        const uint32_t* __restrict__ bH, const uint32_t* __restrict__ bL,
        float* __restrict__ C, int ldc,
        uint32_t* __restrict__ oH, uint32_t* __restrict__ oL,
        const float* __restrict__ bias)
{
    constexpr int NTILE = 32*NI;
    extern __shared__ uint32_t su[];
    uint32_t* AsH = su;
    uint32_t* AsL = su + 2*128*AU;
    uint32_t* BsH = su + 4*128*AU;
    uint32_t* BsL = BsH + 2*NTILE*AU;
    const uint32_t sb = (uint32_t)__cvta_generic_to_shared(su);
    const uint32_t sbAH = sb;
    const uint32_t sbAL = sb + 2*128*AU*4;
    const uint32_t sbBH = sb + 4*128*AU*4;
    const uint32_t sbBL = sbBH + 2*NTILE*AU*4;

    const int KP   = K >> 1;
    const int tid  = threadIdx.x;
    const int wid  = tid >> 5, lane = tid & 31;
    const int g    = lane >> 2, t = lane & 3;
    const int bm   = blockIdx.y * 128, bn = blockIdx.x * NTILE;
    const int m0   = (wid >> 2) * 64, n0 = (wid & 3) * (8*NI);

    float c[4][NI][4];
    #pragma unroll
    for (int mi = 0; mi < 4; mi++)
        #pragma unroll
        for (int ni = 0; ni < NI; ni++)
            #pragma unroll
            for (int j = 0; j < 4; j++) c[mi][ni][j] = 0.f;

    const int NKT = K >> 5;

    auto load_tile = [&](int kt, int pb) {
        const int kp0 = kt << 4;
        #pragma unroll
        for (int i = 0; i < 2; i++) {
            int f = tid + i*256;
            int r = f >> 2, cc = (f & 3) << 2;
            size_t go = (size_t)(bm + r)*KP + kp0 + cc;
            uint32_t so = (uint32_t)((pb*128 + r)*AU + cc)*4;
            cpa16(sbAH + so, aH + go);
            cpa16(sbAL + so, aL + go);
        }
        #pragma unroll
        for (int i = 0; i < NI/2; i++) {
            int f = tid + i*256;
            int n = f >> 2, cc = (f & 3) << 2;
            size_t go = (size_t)(bn + n)*KP + kp0 + cc;
            uint32_t so = (uint32_t)((pb*NTILE + n)*AU + cc)*4;
            cpa16(sbBH + so, bH + go);
            cpa16(sbBL + so, bL + go);
        }
        CP_COMMIT();
    };

    load_tile(0, 0);

    for (int kt = 0; kt < NKT; kt++) {
        const int pb = kt & 1;
        if (kt + 1 < NKT) {
            load_tile(kt + 1, pb ^ 1);
            asm volatile("cp.async.wait_group 1;" ::: "memory");
        } else {
            asm volatile("cp.async.wait_group 0;" ::: "memory");
        }
        __syncthreads();

        const uint32_t* ah_b = AsH + pb*128*AU;
        const uint32_t* al_b = AsL + pb*128*AU;
        const uint32_t* bh_b = BsH + pb*NTILE*AU;
        const uint32_t* bl_b = BsL + pb*NTILE*AU;

        #pragma unroll
        for (int ks = 0; ks < 2; ks++) {
            const int kb = ks*8;
            uint32_t bh[NI][2], bl[NI][2];
            #pragma unroll
            for (int ni = 0; ni < NI; ni++) {
                int col = (n0 + ni*8 + g)*AU + kb;
                bh[ni][0] = bh_b[col + t];
                bh[ni][1] = bh_b[col + t + 4];
                bl[ni][0] = bl_b[col + t];
                bl[ni][1] = bl_b[col + t + 4];
            }
            #pragma unroll
            for (int mi = 0; mi < 4; mi++) {
                int row = m0 + mi*16 + g;
                uint32_t ah[4], al[4];
                ah[0] = ah_b[(row    )*AU + kb + t];
                ah[1] = ah_b[(row + 8)*AU + kb + t];
                ah[2] = ah_b[(row    )*AU + kb + t + 4];
                ah[3] = ah_b[(row + 8)*AU + kb + t + 4];
                al[0] = al_b[(row    )*AU + kb + t];
                al[1] = al_b[(row + 8)*AU + kb + t];
                al[2] = al_b[(row    )*AU + kb + t + 4];
                al[3] = al_b[(row + 8)*AU + kb + t + 4];
                #pragma unroll
                for (int ni = 0; ni < NI; ni++) {
                    MMA16(c[mi][ni], ah, bh[ni]);
                    MMA16(c[mi][ni], ah, bl[ni]);
                    MMA16(c[mi][ni], al, bh[ni]);
                }
            }
        }
        __syncthreads();
    }

    const int KP2 = (OUT == 2) ? 512 : (N >> 1);
    #pragma unroll
    for (int mi = 0; mi < 4; mi++) {
        const int r0 = bm + m0 + mi*16 + g;
        #pragma unroll
        for (int ni = 0; ni < NI; ni++) {
            const int c0 = bn + n0 + ni*8 + t*2;
            #pragma unroll
            for (int half = 0; half < 2; half++) {
                const int gr = r0 + half*8;
                float v0 = c[mi][ni][2*half + 0];
                float v1 = c[mi][ni][2*half + 1];
                if (EPI >= 1) { v0 += bias[c0]; v1 += bias[c0 + 1]; }
                if (EPI == 2) {
                    v0 = 0.5f*v0*(1.f + erff(v0*0.70710678118654752f));
                    v1 = 0.5f*v1*(1.f + erff(v1*0.70710678118654752f));
                }
                if (OUT == 0) {
                    if (!GUARD || c0 < N)     C[(size_t)gr*ldc + c0]     = v0;
                    if (!GUARD || c0 + 1 < N) C[(size_t)gr*ldc + c0 + 1] = v1;
                } else if (OUT == 1) {
                    uint32_t h, l;
                    bpack(v0, v1, h, l);
                    oH[(size_t)gr*KP2 + (c0 >> 1)] = h;
                    oL[(size_t)gr*KP2 + (c0 >> 1)] = l;
                } else {
                    if (c0 < 1024) {
                        uint32_t h, l;
                        bpack(v0, v1, h, l);
                        oH[(size_t)gr*512 + (c0 >> 1)] = h;
                        oL[(size_t)gr*512 + (c0 >> 1)] = l;
                    } else {
                        C[(size_t)gr*512 + (c0 - 1024)]     = v0;
                        C[(size_t)gr*512 + (c0 - 1024) + 1] = v1;
                    }
                }
            }
        }
    }
}

// ---------------- embedding -----------------------------------------------------
__global__ void embed_kernel(const int* __restrict__ ids,
                             const float* __restrict__ tok,
                             const float* __restrict__ pos) {
    const int row = blockIdx.x;
    const int t   = row % T_;
    const int id  = ids[row];
    const int tid = threadIdx.x;
    const float sc = 22.62741699796952f;
    const int d = tid*2;
    float e0 = (id == PAD_) ? 0.f : tok[(size_t)id*D_ + d];
    float e1 = (id == PAD_) ? 0.f : tok[(size_t)id*D_ + d + 1];
    float v0 = e0*sc + pos[(size_t)t*D_ + d];
    float v1 = e1*sc + pos[(size_t)t*D_ + d + 1];
    *reinterpret_cast<float2*>(g_x + (size_t)row*D_ + d) = make_float2(v0, v1);
    uint32_t h, l;
    bpack(v0, v1, h, l);
    g_xH[row*256 + tid] = h;
    g_xL[row*256 + tid] = l;
}

// ================ fattn2: tensor-core bf16x3 flash attention ===================
// 4 warps, 64-row Q tiles; grid (8, 16) pairing tiles (p, 15-p) -> 17 iters each.
#define FA2_SMEM (6*2304*4)   // Q,K,V hi/lo @ 64 x 36 u32 each = 55296 bytes

__device__ __forceinline__ void fa2_tile(
    uint32_t* QH, uint32_t* QL, uint32_t* KH, uint32_t* KL,
    uint32_t* VH, uint32_t* VL, uint32_t sbase,
    int qb, int b, int h, int tid)
{
    const int w = tid >> 5, lane = tid & 31;
    const int g = lane >> 2, t = lane & 3;
    const int mr = w*16;
    const uint32_t sQH = sbase, sQL = sbase + 9216;
    const uint32_t sKH = sbase + 18432, sKL = sbase + 27648;

    // Q tile (packed pairs straight from qkv GEMM output)
    #pragma unroll
    for (int i = 0; i < 4; i++) {
        int idx = tid + i*128;
        int r = idx >> 3, c4 = (idx & 7) << 2;
        size_t go = ((size_t)(b*1024 + qb*64 + r) << 9) + h*32 + c4;
        cpa16(sQH + (uint32_t)(r*36 + c4)*4, g_qkpH + go);
        cpa16(sQL + (uint32_t)(r*36 + c4)*4, g_qkpL + go);
    }
    CP_COMMIT();

    float m0 = -CUDART_INF_F, m1 = -CUDART_INF_F, l0 = 0.f, l1 = 0.f;
    float o[8][4];
    #pragma unroll
    for (int nb = 0; nb < 8; nb++)
        #pragma unroll
        for (int j = 0; j < 4; j++) o[nb][j] = 0.f;

    const int nkt = qb + 1;
    for (int kt = 0; kt < nkt; kt++) {
        __syncthreads();   // prev iter PV done (and tile boundary)
        // K tile (packed)
        #pragma unroll
        for (int i = 0; i < 4; i++) {
            int idx = tid + i*128;
            int r = idx >> 3, c4 = (idx & 7) << 2;
            size_t go = ((size_t)(b*1024 + kt*64 + r) << 9) + 256 + h*32 + c4;
            cpa16(sKH + (uint32_t)(r*36 + c4)*4, g_qkpH + go);
            cpa16(sKL + (uint32_t)(r*36 + c4)*4, g_qkpL + go);
        }
        CP_COMMIT();
        // V tile fp32 -> transposed packed (dk rows, key pairs)
        #pragma unroll
        for (int i = 0; i < 16; i++) {
            int idx = tid + i*128;
            int n = idx & 63, r = idx >> 6;
            size_t base = ((size_t)(b*1024 + kt*64 + 2*r) << 9) + h*64 + n;
            uint32_t hh, ll;
            bpack(g_v[base], g_v[base + 512], hh, ll);
            VH[n*36 + r] = hh;
            VL[n*36 + r] = ll;
        }
        asm volatile("cp.async.wait_group 0;" ::: "memory");
        __syncthreads();

        // ---- S = Q K^T (bf16x3) ----
        float sc[8][4];
        #pragma unroll
        for (int ni = 0; ni < 8; ni++)
            #pragma unroll
            for (int j = 0; j < 4; j++) sc[ni][j] = 0.f;
        #pragma unroll
        for (int j = 0; j < 4; j++) {
            uint32_t ah[4], al[4];
            int rb = (mr + g)*36 + j*8 + t;
            ah[0] = QH[rb];           al[0] = QL[rb];
            ah[1] = QH[rb + 8*36];    al[1] = QL[rb + 8*36];
            ah[2] = QH[rb + 4];       al[2] = QL[rb + 4];
            ah[3] = QH[rb + 8*36 + 4]; al[3] = QL[rb + 8*36 + 4];
            #pragma unroll
            for (int ni = 0; ni < 8; ni++) {
                uint32_t bh2[2], bl2[2];
                int cb = (ni*8 + g)*36 + j*8 + t;
                bh2[0] = KH[cb]; bh2[1] = KH[cb + 4];
                bl2[0] = KL[cb]; bl2[1] = KL[cb + 4];
                MMA16(sc[ni], ah, bh2);
                MMA16(sc[ni], ah, bl2);
                MMA16(sc[ni], al, bh2);
            }
        }
        // scale + causal mask (only diagonal tile)
        const int qr0 = qb*64 + mr + g;
        const bool diag = (kt == qb);
        #pragma unroll
        for (int ni = 0; ni < 8; ni++)
            #pragma unroll
            for (int cc = 0; cc < 4; cc++) {
                float v = sc[ni][cc]*0.125f;
                if (diag) {
                    int key = kt*64 + ni*8 + 2*t + (cc & 1);
                    int qr = qr0 + (cc >> 1)*8;
                    if (key > qr) v = -CUDART_INF_F;
                }
                sc[ni][cc] = v;
            }

        // ---- online softmax (rows g and g+8, warp-local via t-bit shfl) ----
        float mx0 = -CUDART_INF_F, mx1 = -CUDART_INF_F;
        #pragma unroll
        for (int ni = 0; ni < 8; ni++) {
            mx0 = fmaxf(mx0, fmaxf(sc[ni][0], sc[ni][1]));
            mx1 = fmaxf(mx1, fmaxf(sc[ni][2], sc[ni][3]));
        }
        mx0 = fmaxf(mx0, __shfl_xor_sync(0xffffffffu, mx0, 1));
        mx0 = fmaxf(mx0, __shfl_xor_sync(0xffffffffu, mx0, 2));
        mx1 = fmaxf(mx1, __shfl_xor_sync(0xffffffffu, mx1, 1));
        mx1 = fmaxf(mx1, __shfl_xor_sync(0xffffffffu, mx1, 2));
        const float mn0 = fmaxf(m0, mx0), mn1 = fmaxf(m1, mx1);
        const float cr0 = fexp(m0 - mn0),  cr1 = fexp(m1 - mn1);
        float s0 = 0.f, s1 = 0.f;
        #pragma unroll
        for (int ni = 0; ni < 8; ni++) {
            float p0 = fexp(sc[ni][0] - mn0);
            float p1 = fexp(sc[ni][1] - mn0);
            float p2 = fexp(sc[ni][2] - mn1);
            float p3 = fexp(sc[ni][3] - mn1);
            sc[ni][0] = p0; sc[ni][1] = p1; sc[ni][2] = p2; sc[ni][3] = p3;
            s0 += p0 + p1; s1 += p2 + p3;
        }
        s0 += __shfl_xor_sync(0xffffffffu, s0, 1);
        s0 += __shfl_xor_sync(0xffffffffu, s0, 2);
        s1 += __shfl_xor_sync(0xffffffffu, s1, 1);
        s1 += __shfl_xor_sync(0xffffffffu, s1, 2);
        l0 = l0*cr0 + s0; l1 = l1*cr1 + s1;
        m0 = mn0; m1 = mn1;
        #pragma unroll
        for (int nb = 0; nb < 8; nb++) {
            o[nb][0] *= cr0; o[nb][1] *= cr0;
            o[nb][2] *= cr1; o[nb][3] *= cr1;
        }

        // ---- O += P V  (P fragments built in-register from S fragments) ----
        #pragma unroll
        for (int jj = 0; jj < 4; jj++) {
            uint32_t ah[4], al[4];
            bpack(sc[2*jj][0],   sc[2*jj][1],   ah[0], al[0]);
            bpack(sc[2*jj][2],   sc[2*jj][3],   ah[1], al[1]);
            bpack(sc[2*jj+1][0], sc[2*jj+1][1], ah[2], al[2]);
            bpack(sc[2*jj+1][2], sc[2*jj+1][3], ah[3], al[3]);
            #pragma unroll
            for (int nb = 0; nb < 8; nb++) {
                uint32_t bh2[2], bl2[2];
                int cb = (nb*8 + g)*36 + jj*8 + t;
                bh2[0] = VH[cb]; bh2[1] = VH[cb + 4];
                bl2[0] = VL[cb]; bl2[1] = VL[cb + 4];
                MMA16(o[nb], ah, bh2);
                MMA16(o[nb], ah, bl2);
                MMA16(o[nb], al, bh2);
            }
        }
    }

    // ---- write packed ctx ----
    const float inv0 = 1.f / l0, inv1 = 1.f / l1;
    const int gr0 = b*1024 + qb*64 + mr + g;
    #pragma unroll
    for (int nb = 0; nb < 8; nb++) {
        const int kp = h*32 + nb*4 + t;
        uint32_t hh, ll;
        bpack(o[nb][0]*inv0, o[nb][1]*inv0, hh, ll);
        g_cH[gr0*256 + kp] = hh;
        g_cL[gr0*256 + kp] = ll;
        bpack(o[nb][2]*inv1, o[nb][3]*inv1, hh, ll);
        g_cH[(gr0 + 8)*256 + kp] = hh;
        g_cL[(gr0 + 8)*256 + kp] = ll;
    }
}

__global__ void __launch_bounds__(128) fattn2_kernel() {
    extern __shared__ uint32_t fsm[];
    uint32_t* QH = fsm;
    uint32_t* QL = QH + 2304;
    uint32_t* KH = QL + 2304;
    uint32_t* KL = KH + 2304;
    uint32_t* VH = KL + 2304;
    uint32_t* VL = VH + 2304;
    const uint32_t sbase = (uint32_t)__cvta_generic_to_shared(fsm);

    const int p  = blockIdx.x;       // 0..7 -> q-tiles p and 15-p
    const int bh = blockIdx.y;
    const int b = bh >> 3, h = bh & 7;
    const int tid = threadIdx.x;

    fa2_tile(QH, QL, KH, KL, VH, VL, sbase, p,      b, h, tid);
    __syncthreads();
    fa2_tile(QH, QL, KH, KL, VH, VL, sbase, 15 - p, b, h, tid);
}

// ------------- fused residual add + LayerNorm -> fp32 x AND packed x -----------
__global__ void __launch_bounds__(256) add_ln_kernel(const float* __restrict__ g,
                                                     const float* __restrict__ bta) {
    const int row = blockIdx.x;
    float* x = g_x + (size_t)row*D_;
    const float* dl = g_tmp + (size_t)row*D_;
    const int tid = threadIdx.x;
    __shared__ float red[256];

    float2 xv = reinterpret_cast<const float2*>(x)[tid];
    float2 dv = reinterpret_cast<const float2*>(dl)[tid];
    float v0 = xv.x + dv.x;
    float v1 = xv.y + dv.y;

    red[tid] = v0 + v1; __syncthreads();
    for (int off = 128; off > 0; off >>= 1) {
        if (tid < off) red[tid] += red[tid + off];
        __syncthreads();
    }
    const float mu = red[0] * (1.f/512.f); __syncthreads();

    float d0 = v0 - mu, d1 = v1 - mu;
    red[tid] = d0*d0 + d1*d1; __syncthreads();
    for (int off = 128; off > 0; off >>= 1) {
        if (tid < off) red[tid] += red[tid + off];
        __syncthreads();
    }
    const float inv = rsqrtf(red[0]*(1.f/512.f) + 1e-5f);

    const int d = tid*2;
    float o0 = d0*inv*g[d]     + bta[d];
    float o1 = d1*inv*g[d + 1] + bta[d + 1];
    reinterpret_cast<float2*>(x)[tid] = make_float2(o0, o1);
    uint32_t h, l;
    bpack(o0, o1, h, l);
    g_xH[row*256 + tid] = h;
    g_xL[row*256 + tid] = l;
}

// ---------------- launch ---------------------------------------------------------
#define SMEM_NI4 ((4*128*AU + 4*128*AU)*4)   // 81920
#define SMEM_NI2 ((4*128*AU + 4*64*AU)*4)    // 61440

extern "C" void kernel_launch(void* const* d_in, const int* in_sizes, int n_in,
                              void* d_out, int out_size) {
    const int*   ids  = (const int*)  d_in[0];
    const float* tok  = (const float*)d_in[1];
    const float* pos  = (const float*)d_in[2];
    const float* WQ   = (const float*)d_in[3];
    const float* WK   = (const float*)d_in[4];
    const float* WV   = (const float*)d_in[5];
    const float* WO   = (const float*)d_in[6];
    const float* ln1g = (const float*)d_in[7];
    const float* ln1b = (const float*)d_in[8];
    const float* fc1w = (const float*)d_in[9];
    const float* fc1b = (const float*)d_in[10];
    const float* fc2w = (const float*)d_in[11];
    const float* fc2b = (const float*)d_in[12];
    const float* ln2g = (const float*)d_in[13];
    const float* ln2b = (const float*)d_in[14];
    const float* lmh  = (const float*)d_in[15];
    float* out = (float*)d_out;

    float *pv, *ptmp;
    cudaGetSymbolAddress((void**)&pv,   g_v);
    cudaGetSymbolAddress((void**)&ptmp, g_tmp);

    uint32_t *xH, *xL, *cH, *cL, *fH, *fL, *qpH, *qpL;
    uint32_t *qkH, *qkL, *woH, *woL, *f1H, *f1L, *f2H, *f2L, *lmH, *lmL;
    cudaGetSymbolAddress((void**)&xH,  g_xH);
    cudaGetSymbolAddress((void**)&xL,  g_xL);
    cudaGetSymbolAddress((void**)&cH,  g_cH);
    cudaGetSymbolAddress((void**)&cL,  g_cL);
    cudaGetSymbolAddress((void**)&fH,  g_fH);
    cudaGetSymbolAddress((void**)&fL,  g_fL);
    cudaGetSymbolAddress((void**)&qpH, g_qkpH);
    cudaGetSymbolAddress((void**)&qpL, g_qkpL);
    cudaGetSymbolAddress((void**)&qkH, g_wqkvH);
    cudaGetSymbolAddress((void**)&qkL, g_wqkvL);
    cudaGetSymbolAddress((void**)&woH, g_woH);
    cudaGetSymbolAddress((void**)&woL, g_woL);
    cudaGetSymbolAddress((void**)&f1H, g_fc1H);
    cudaGetSymbolAddress((void**)&f1L, g_fc1L);
    cudaGetSymbolAddress((void**)&f2H, g_fc2H);
    cudaGetSymbolAddress((void**)&f2L, g_fc2L);
    cudaGetSymbolAddress((void**)&lmH, g_lmhH);
    cudaGetSymbolAddress((void**)&lmL, g_lmhL);

    cudaFuncSetAttribute((const void*)fattn2_kernel,        cudaFuncAttributeMaxDynamicSharedMemorySize, FA2_SMEM);
    cudaFuncSetAttribute((const void*)gemm_pk<2,0,false,4>, cudaFuncAttributeMaxDynamicSharedMemorySize, SMEM_NI4);
    cudaFuncSetAttribute((const void*)gemm_pk<0,0,false,2>, cudaFuncAttributeMaxDynamicSharedMemorySize, SMEM_NI2);
    cudaFuncSetAttribute((const void*)gemm_pk<1,2,false,4>, cudaFuncAttributeMaxDynamicSharedMemorySize, SMEM_NI4);
    cudaFuncSetAttribute((const void*)gemm_pk<0,1,false,2>, cudaFuncAttributeMaxDynamicSharedMemorySize, SMEM_NI2);
    cudaFuncSetAttribute((const void*)gemm_pk<0,0,true,4>,  cudaFuncAttributeMaxDynamicSharedMemorySize, SMEM_NI4);

    // launch order keeps the 6th launch = fattn2 for ncu (-s 5 -c 1)
    embed_kernel<<<BT_, 256>>>(ids, tok, pos);                         // 1
    prepack_small<<<dim3(32, 32, 3*L_), 256>>>(WO, fc1w, fc2w);        // 2
    prepack_qkvw<<<dim3(QKVW_/64, 8, L_), 256>>>(WQ, WK, WV);          // 3
    prepack_b<<<dim3(VP_/64, 8), 256>>>(lmh, lmH, lmL, D_, V_, VP_);   // 4

    for (int l = 0; l < L_; l++) {
        gemm_pk<2,0,false,4><<<dim3(QKVW_/128, BT_/128), 256, SMEM_NI4>>>(
            BT_, QKVW_, D_, xH, xL,
            qkH + (size_t)l*QKVW_*256, qkL + (size_t)l*QKVW_*256,
            pv, 512, qpH, qpL, nullptr);                               // 5 (l=0)

        fattn2_kernel<<<dim3(8, B_*H_), 128, FA2_SMEM>>>();            // 6 (l=0)

        gemm_pk<0,0,false,2><<<dim3(D_/64, BT_/128), 256, SMEM_NI2>>>(
            BT_, D_, D_, cH, cL,
            woH + (size_t)l*D_*256, woL + (size_t)l*D_*256,
            ptmp, D_, nullptr, nullptr, nullptr);

        add_ln_kernel<<<BT_, 256>>>(ln1g + l*D_, ln1b + l*D_);

        gemm_pk<1,2,false,4><<<dim3(DFF_/128, BT_/128), 256, SMEM_NI4>>>(
            BT_, DFF_, D_, xH, xL,
            f1H + (size_t)l*DFF_*256, f1L + (size_t)l*DFF_*256,
            nullptr, 0, fH, fL, fc1b + l*DFF_);

        gemm_pk<0,1,false,2><<<dim3(D_/64, BT_/128), 256, SMEM_NI2>>>(
            BT_, D_, DFF_, fH, fL,
            f2H + (size_t)l*D_*1024, f2L + (size_t)l*D_*1024,
            ptmp, D_, nullptr, nullptr, fc2b + l*D_);

        add_ln_kernel<<<BT_, 256>>>(ln2g + l*D_, ln2b + l*D_);
    }

    gemm_pk<0,0,true,4><<<dim3(VP_/128, BT_/128), 256, SMEM_NI4>>>(
        BT_, V_, D_, xH, xL, lmH, lmL, out, V_, nullptr, nullptr, nullptr);
}

// round 10
// speedup vs baseline: 3.7415x; 1.0903x over previous
#include <cuda_runtime.h>
#include <cuda_fp16.h>
#include <math.h>
#include <math_constants.h>
#include <stdint.h>

#define B_   2
#define T_   1024
#define D_   512
#define H_   8
#define DK_  64
#define DFF_ 2048
#define L_   6
#define V_   50257
#define VP_  50304   // V padded to 128
#define PAD_ 50256
#define BT_  (B_*T_)
#define QKVW_ (3*D_)   // 1536

// ---------------- scratch (device globals; no allocations allowed) ----------
__device__ float g_x[BT_*D_];
__device__ float g_v[BT_*D_];                          // V fp32 (per layer)
__device__ float g_tmp[BT_*D_];

// packed fp16 hi/lo activation buffers (u32 = half2 of adjacent k)
__device__ uint32_t g_xH[BT_*256],  g_xL[BT_*256];     // x packed (K=512)
__device__ uint32_t g_cH[BT_*256],  g_cL[BT_*256];     // ctx packed
__device__ uint32_t g_fH[BT_*1024], g_fL[BT_*1024];    // ffn hidden packed
__device__ uint32_t g_qkpH[BT_*512], g_qkpL[BT_*512];  // Q,K packed (512 pairs/row)
// packed weights
__device__ uint32_t g_wqkvH[L_*QKVW_*256], g_wqkvL[L_*QKVW_*256];
__device__ uint32_t g_woH[L_*D_*256],      g_woL[L_*D_*256];
__device__ uint32_t g_fc1H[L_*DFF_*256],   g_fc1L[L_*DFF_*256];
__device__ uint32_t g_fc2H[L_*D_*1024],    g_fc2L[L_*D_*1024];
__device__ uint32_t g_lmhH[(size_t)VP_*256];           // lm_head single fp16 (x2 path)

// ---------------- helpers ------------------------------------------------------
__device__ __forceinline__ void hpack(float x0, float x1, uint32_t& hi, uint32_t& lo) {
    __half h0 = __float2half_rn(x0);
    __half h1 = __float2half_rn(x1);
    __half l0 = __float2half_rn(x0 - __half2float(h0));
    __half l1 = __float2half_rn(x1 - __half2float(h1));
    hi = ((uint32_t)__half_as_ushort(h1) << 16) | (uint32_t)__half_as_ushort(h0);
    lo = ((uint32_t)__half_as_ushort(l1) << 16) | (uint32_t)__half_as_ushort(l0);
}
__device__ __forceinline__ uint32_t hpack1(float x0, float x1) {
    return ((uint32_t)__half_as_ushort(__float2half_rn(x1)) << 16)
         |  (uint32_t)__half_as_ushort(__float2half_rn(x0));
}

// fast exp on the FMA pipe (arg <= 0 path; clamps; ~2e-8 rel err)
__device__ __forceinline__ float fexp(float x) {
    x = fmaxf(x, -87.0f);
    float t = fmaf(x, 1.4426950408889634f, 12582912.0f);
    float r = t - 12582912.0f;
    float f = fmaf(x, 1.4426950408889634f, -r);
    float p =        1.3333558e-3f;
    p = fmaf(p, f, 9.6181291e-3f);
    p = fmaf(p, f, 5.5504109e-2f);
    p = fmaf(p, f, 2.4022651e-1f);
    p = fmaf(p, f, 6.9314718e-1f);
    p = fmaf(p, f, 1.0f);
    int e = (__float_as_int(t) + 127) << 23;
    return p * __int_as_float(e);
}

#define MMA16(cc, a, b) \
    asm volatile("mma.sync.aligned.m16n8k16.row.col.f32.f16.f16.f32 " \
        "{%0,%1,%2,%3}, {%4,%5,%6,%7}, {%8,%9}, {%0,%1,%2,%3};" \
        : "+f"((cc)[0]), "+f"((cc)[1]), "+f"((cc)[2]), "+f"((cc)[3]) \
        : "r"((a)[0]), "r"((a)[1]), "r"((a)[2]), "r"((a)[3]), \
          "r"((b)[0]), "r"((b)[1]))

__device__ __forceinline__ void cpa16(uint32_t dst, const void* src) {
    asm volatile("cp.async.cg.shared.global [%0], [%1], 16;" :: "r"(dst), "l"(src));
}
#define CP_COMMIT() asm volatile("cp.async.commit_group;" ::: "memory")

// ================ prepack kernels (coalesced transpose) ========================
// lm_head: W fp32 [K][N] -> [Npad][K/2] single fp16 (hi only, for x2 path)
__global__ void prepack_b_hi(const float* __restrict__ W, uint32_t* __restrict__ oH,
                             int K, int N, int Npad) {
    __shared__ uint32_t sh[64*33];
    const int KP = K >> 1;
    const int n0 = blockIdx.x * 64, kp0 = blockIdx.y * 32;
    const int tid = threadIdx.x;
    #pragma unroll
    for (int i = 0; i < 8; i++) {
        int f = tid + i*256;
        int n = f & 63, kp = f >> 6;
        int gn = n0 + n;
        float x0 = 0.f, x1 = 0.f;
        if (gn < N) {
            int k2 = (kp0 + kp) * 2;
            x0 = W[(size_t)k2*N + gn];
            x1 = W[(size_t)(k2 + 1)*N + gn];
        }
        sh[n*33 + kp] = hpack1(x0, x1);
    }
    __syncthreads();
    #pragma unroll
    for (int i = 0; i < 8; i++) {
        int f = tid + i*256;
        int kp = f & 31, n = f >> 5;
        oH[(size_t)(n0 + n)*KP + kp0 + kp] = sh[n*33 + kp];
    }
}

// QKV weights straight from WQ/WK/WV [L,H,D,DK] -> [L][1536 n][256 kp] packed
__global__ void prepack_qkvw(const float* __restrict__ WQ,
                             const float* __restrict__ WK,
                             const float* __restrict__ WV) {
    __shared__ uint32_t sh[64*33], sl[64*33];
    const int l = blockIdx.z;
    const int n0 = blockIdx.x*64, kp0 = blockIdx.y*32;
    const int tid = threadIdx.x;
    #pragma unroll
    for (int i = 0; i < 8; i++) {
        int f = tid + i*256;
        int n = f & 63, kp = f >> 6;
        int gn = n0 + n;
        int part = gn >> 9, hh = (gn >> 6) & 7, kk = gn & 63;
        const float* W = part == 0 ? WQ : (part == 1 ? WK : WV);
        size_t base = (((size_t)l*H_ + hh)*D_ + 2*(kp0 + kp))*DK_ + kk;
        uint32_t h, l2;
        hpack(W[base], W[base + DK_], h, l2);
        sh[n*33 + kp] = h;
        sl[n*33 + kp] = l2;
    }
    __syncthreads();
    #pragma unroll
    for (int i = 0; i < 8; i++) {
        int f = tid + i*256;
        int kp = f & 31, n = f >> 5;
        size_t go = (size_t)l*QKVW_*256 + (size_t)(n0 + n)*256 + kp0 + kp;
        g_wqkvH[go] = sh[n*33 + kp];
        g_wqkvL[go] = sl[n*33 + kp];
    }
}

// WO/FC1/FC2 for all layers, z = type*L + l
__global__ void prepack_small(const float* __restrict__ WO,
                              const float* __restrict__ F1,
                              const float* __restrict__ F2) {
    __shared__ uint32_t sh[64*33], sl[64*33];
    const int z = blockIdx.z;
    const int type = z / L_, l = z % L_;
    int K, N; const float* W; uint32_t *oH, *oL;
    if (type == 0)      { K = D_;   N = D_;   W = WO + (size_t)l*D_*D_;    oH = g_woH  + (size_t)l*D_*256;   oL = g_woL  + (size_t)l*D_*256; }
    else if (type == 1) { K = D_;   N = DFF_; W = F1 + (size_t)l*D_*DFF_;  oH = g_fc1H + (size_t)l*DFF_*256; oL = g_fc1L + (size_t)l*DFF_*256; }
    else                { K = DFF_; N = D_;   W = F2 + (size_t)l*DFF_*D_;  oH = g_fc2H + (size_t)l*D_*1024;  oL = g_fc2L + (size_t)l*D_*1024; }
    const int KP = K >> 1;
    const int n0 = blockIdx.x*64, kp0 = blockIdx.y*32;
    if (n0 >= N || kp0 >= KP) return;
    const int tid = threadIdx.x;
    #pragma unroll
    for (int i = 0; i < 8; i++) {
        int f = tid + i*256;
        int n = f & 63, kp = f >> 6;
        int k2 = (kp0 + kp)*2;
        uint32_t h, l2;
        hpack(W[(size_t)k2*N + n0 + n], W[(size_t)(k2+1)*N + n0 + n], h, l2);
        sh[n*33 + kp] = h;
        sl[n*33 + kp] = l2;
    }
    __syncthreads();
    #pragma unroll
    for (int i = 0; i < 8; i++) {
        int f = tid + i*256;
        int kp = f & 31, n = f >> 5;
        size_t go = (size_t)(n0 + n)*KP + kp0 + kp;
        oH[go] = sh[n*33 + kp];
        oL[go] = sl[n*33 + kp];
    }
}

// ============== fp16-split mma.sync GEMM, cp.async double-buffered =============
// OUT: 0 fp32 C, 1 packed hi/lo, 2 qkv-mode (c<1024 packed Q/K, else fp32 V)
// BPASS: 3 = A,B both split; 2 = A split, B single fp16.
#define AU 20

template<int OUT, int EPI, bool GUARD, int NI, int BPASS>
__global__ void __launch_bounds__(256, 2)
gemm_pk(int M, int N, int K,
        const uint32_t* __restrict__ aH, const uint32_t* __restrict__ aL,
        const uint32_t* __restrict__ bH, const uint32_t* __restrict__ bL,
        float* __restrict__ C, int ldc,
        uint32_t* __restrict__ oH, uint32_t* __restrict__ oL,
        const float* __restrict__ bias)
{
    constexpr int NTILE = 32*NI;
    extern __shared__ uint32_t su[];
    uint32_t* AsH = su;
    uint32_t* AsL = su + 2*128*AU;
    uint32_t* BsH = su + 4*128*AU;
    uint32_t* BsL = BsH + 2*NTILE*AU;           // unused when BPASS==2
    const uint32_t sb = (uint32_t)__cvta_generic_to_shared(su);
    const uint32_t sbAH = sb;
    const uint32_t sbAL = sb + 2*128*AU*4;
    const uint32_t sbBH = sb + 4*128*AU*4;
    const uint32_t sbBL = sbBH + 2*NTILE*AU*4;

    const int KP   = K >> 1;
    const int tid  = threadIdx.x;
    const int wid  = tid >> 5, lane = tid & 31;
    const int g    = lane >> 2, t = lane & 3;
    const int bm   = blockIdx.y * 128, bn = blockIdx.x * NTILE;
    const int m0   = (wid >> 2) * 64, n0 = (wid & 3) * (8*NI);

    float c[4][NI][4];
    #pragma unroll
    for (int mi = 0; mi < 4; mi++)
        #pragma unroll
        for (int ni = 0; ni < NI; ni++)
            #pragma unroll
            for (int j = 0; j < 4; j++) c[mi][ni][j] = 0.f;

    const int NKT = K >> 5;

    auto load_tile = [&](int kt, int pb) {
        const int kp0 = kt << 4;
        #pragma unroll
        for (int i = 0; i < 2; i++) {
            int f = tid + i*256;
            int r = f >> 2, cc = (f & 3) << 2;
            size_t go = (size_t)(bm + r)*KP + kp0 + cc;
            uint32_t so = (uint32_t)((pb*128 + r)*AU + cc)*4;
            cpa16(sbAH + so, aH + go);
            cpa16(sbAL + so, aL + go);
        }
        #pragma unroll
        for (int i = 0; i < NI/2; i++) {
            int f = tid + i*256;
            int n = f >> 2, cc = (f & 3) << 2;
            size_t go = (size_t)(bn + n)*KP + kp0 + cc;
            uint32_t so = (uint32_t)((pb*NTILE + n)*AU + cc)*4;
            cpa16(sbBH + so, bH + go);
            if (BPASS == 3) cpa16(sbBL + so, bL + go);
        }
        CP_COMMIT();
    };

    load_tile(0, 0);

    for (int kt = 0; kt < NKT; kt++) {
        const int pb = kt & 1;
        if (kt + 1 < NKT) {
            load_tile(kt + 1, pb ^ 1);
            asm volatile("cp.async.wait_group 1;" ::: "memory");
        } else {
            asm volatile("cp.async.wait_group 0;" ::: "memory");
        }
        __syncthreads();

        const uint32_t* ah_b = AsH + pb*128*AU;
        const uint32_t* al_b = AsL + pb*128*AU;
        const uint32_t* bh_b = BsH + pb*NTILE*AU;
        const uint32_t* bl_b = BsL + pb*NTILE*AU;

        #pragma unroll
        for (int ks = 0; ks < 2; ks++) {
            const int kb = ks*8;
            uint32_t bh[NI][2], bl[NI][2];
            #pragma unroll
            for (int ni = 0; ni < NI; ni++) {
                int col = (n0 + ni*8 + g)*AU + kb;
                bh[ni][0] = bh_b[col + t];
                bh[ni][1] = bh_b[col + t + 4];
                if (BPASS == 3) {
                    bl[ni][0] = bl_b[col + t];
                    bl[ni][1] = bl_b[col + t + 4];
                }
            }
            #pragma unroll
            for (int mi = 0; mi < 4; mi++) {
                int row = m0 + mi*16 + g;
                uint32_t ah[4], al[4];
                ah[0] = ah_b[(row    )*AU + kb + t];
                ah[1] = ah_b[(row + 8)*AU + kb + t];
                ah[2] = ah_b[(row    )*AU + kb + t + 4];
                ah[3] = ah_b[(row + 8)*AU + kb + t + 4];
                al[0] = al_b[(row    )*AU + kb + t];
                al[1] = al_b[(row + 8)*AU + kb + t];
                al[2] = al_b[(row    )*AU + kb + t + 4];
                al[3] = al_b[(row + 8)*AU + kb + t + 4];
                #pragma unroll
                for (int ni = 0; ni < NI; ni++) {
                    MMA16(c[mi][ni], ah, bh[ni]);
                    if (BPASS == 3) MMA16(c[mi][ni], ah, bl[ni]);
                    MMA16(c[mi][ni], al, bh[ni]);
                }
            }
        }
        __syncthreads();
    }

    const int KP2 = (OUT == 2) ? 512 : (N >> 1);
    #pragma unroll
    for (int mi = 0; mi < 4; mi++) {
        const int r0 = bm + m0 + mi*16 + g;
        #pragma unroll
        for (int ni = 0; ni < NI; ni++) {
            const int c0 = bn + n0 + ni*8 + t*2;
            #pragma unroll
            for (int half = 0; half < 2; half++) {
                const int gr = r0 + half*8;
                float v0 = c[mi][ni][2*half + 0];
                float v1 = c[mi][ni][2*half + 1];
                if (EPI >= 1) { v0 += bias[c0]; v1 += bias[c0 + 1]; }
                if (EPI == 2) {
                    v0 = 0.5f*v0*(1.f + erff(v0*0.70710678118654752f));
                    v1 = 0.5f*v1*(1.f + erff(v1*0.70710678118654752f));
                }
                if (OUT == 0) {
                    if (!GUARD || c0 < N)     C[(size_t)gr*ldc + c0]     = v0;
                    if (!GUARD || c0 + 1 < N) C[(size_t)gr*ldc + c0 + 1] = v1;
                } else if (OUT == 1) {
                    uint32_t h, l;
                    hpack(v0, v1, h, l);
                    oH[(size_t)gr*KP2 + (c0 >> 1)] = h;
                    oL[(size_t)gr*KP2 + (c0 >> 1)] = l;
                } else {
                    if (c0 < 1024) {
                        uint32_t h, l;
                        hpack(v0, v1, h, l);
                        oH[(size_t)gr*512 + (c0 >> 1)] = h;
                        oL[(size_t)gr*512 + (c0 >> 1)] = l;
                    } else {
                        C[(size_t)gr*512 + (c0 - 1024)]     = v0;
                        C[(size_t)gr*512 + (c0 - 1024) + 1] = v1;
                    }
                }
            }
        }
    }
}

// ---------------- embedding -----------------------------------------------------
__global__ void embed_kernel(const int* __restrict__ ids,
                             const float* __restrict__ tok,
                             const float* __restrict__ pos) {
    const int row = blockIdx.x;
    const int t   = row % T_;
    const int id  = ids[row];
    const int tid = threadIdx.x;
    const float sc = 22.62741699796952f;
    const int d = tid*2;
    float e0 = (id == PAD_) ? 0.f : tok[(size_t)id*D_ + d];
    float e1 = (id == PAD_) ? 0.f : tok[(size_t)id*D_ + d + 1];
    float v0 = e0*sc + pos[(size_t)t*D_ + d];
    float v1 = e1*sc + pos[(size_t)t*D_ + d + 1];
    *reinterpret_cast<float2*>(g_x + (size_t)row*D_ + d) = make_float2(v0, v1);
    uint32_t h, l;
    hpack(v0, v1, h, l);
    g_xH[row*256 + tid] = h;
    g_xL[row*256 + tid] = l;
}

// ================ fattn2: tensor-core fp16x3 flash attention ===================
#define FA2_SMEM (6*2304*4)   // 55296 bytes

__device__ __forceinline__ void fa2_tile(
    uint32_t* QH, uint32_t* QL, uint32_t* KH, uint32_t* KL,
    uint32_t* VH, uint32_t* VL, uint32_t sbase,
    int qb, int b, int h, int tid)
{
    const int w = tid >> 5, lane = tid & 31;
    const int g = lane >> 2, t = lane & 3;
    const int mr = w*16;
    const uint32_t sQH = sbase, sQL = sbase + 9216;
    const uint32_t sKH = sbase + 18432, sKL = sbase + 27648;

    #pragma unroll
    for (int i = 0; i < 4; i++) {
        int idx = tid + i*128;
        int r = idx >> 3, c4 = (idx & 7) << 2;
        size_t go = ((size_t)(b*1024 + qb*64 + r) << 9) + h*32 + c4;
        cpa16(sQH + (uint32_t)(r*36 + c4)*4, g_qkpH + go);
        cpa16(sQL + (uint32_t)(r*36 + c4)*4, g_qkpL + go);
    }
    CP_COMMIT();

    float m0 = -CUDART_INF_F, m1 = -CUDART_INF_F, l0 = 0.f, l1 = 0.f;
    float o[8][4];
    #pragma unroll
    for (int nb = 0; nb < 8; nb++)
        #pragma unroll
        for (int j = 0; j < 4; j++) o[nb][j] = 0.f;

    const int nkt = qb + 1;
    for (int kt = 0; kt < nkt; kt++) {
        __syncthreads();
        #pragma unroll
        for (int i = 0; i < 4; i++) {
            int idx = tid + i*128;
            int r = idx >> 3, c4 = (idx & 7) << 2;
            size_t go = ((size_t)(b*1024 + kt*64 + r) << 9) + 256 + h*32 + c4;
            cpa16(sKH + (uint32_t)(r*36 + c4)*4, g_qkpH + go);
            cpa16(sKL + (uint32_t)(r*36 + c4)*4, g_qkpL + go);
        }
        CP_COMMIT();
        #pragma unroll
        for (int i = 0; i < 16; i++) {
            int idx = tid + i*128;
            int n = idx & 63, r = idx >> 6;
            size_t base = ((size_t)(b*1024 + kt*64 + 2*r) << 9) + h*64 + n;
            uint32_t hh, ll;
            hpack(g_v[base], g_v[base + 512], hh, ll);
            VH[n*36 + r] = hh;
            VL[n*36 + r] = ll;
        }
        asm volatile("cp.async.wait_group 0;" ::: "memory");
        __syncthreads();

        float sc[8][4];
        #pragma unroll
        for (int ni = 0; ni < 8; ni++)
            #pragma unroll
            for (int j = 0; j < 4; j++) sc[ni][j] = 0.f;
        #pragma unroll
        for (int j = 0; j < 4; j++) {
            uint32_t ah[4], al[4];
            int rb = (mr + g)*36 + j*8 + t;
            ah[0] = QH[rb];            al[0] = QL[rb];
            ah[1] = QH[rb + 8*36];     al[1] = QL[rb + 8*36];
            ah[2] = QH[rb + 4];        al[2] = QL[rb + 4];
            ah[3] = QH[rb + 8*36 + 4]; al[3] = QL[rb + 8*36 + 4];
            #pragma unroll
            for (int ni = 0; ni < 8; ni++) {
                uint32_t bh2[2], bl2[2];
                int cb = (ni*8 + g)*36 + j*8 + t;
                bh2[0] = KH[cb]; bh2[1] = KH[cb + 4];
                bl2[0] = KL[cb]; bl2[1] = KL[cb + 4];
                MMA16(sc[ni], ah, bh2);
                MMA16(sc[ni], ah, bl2);
                MMA16(sc[ni], al, bh2);
            }
        }
        const int qr0 = qb*64 + mr + g;
        const bool diag = (kt == qb);
        #pragma unroll
        for (int ni = 0; ni < 8; ni++)
            #pragma unroll
            for (int cc = 0; cc < 4; cc++) {
                float v = sc[ni][cc]*0.125f;
                if (diag) {
                    int key = kt*64 + ni*8 + 2*t + (cc & 1);
                    int qr = qr0 + (cc >> 1)*8;
                    if (key > qr) v = -CUDART_INF_F;
                }
                sc[ni][cc] = v;
            }

        float mx0 = -CUDART_INF_F, mx1 = -CUDART_INF_F;
        #pragma unroll
        for (int ni = 0; ni < 8; ni++) {
            mx0 = fmaxf(mx0, fmaxf(sc[ni][0], sc[ni][1]));
            mx1 = fmaxf(mx1, fmaxf(sc[ni][2], sc[ni][3]));
        }
        mx0 = fmaxf(mx0, __shfl_xor_sync(0xffffffffu, mx0, 1));
        mx0 = fmaxf(mx0, __shfl_xor_sync(0xffffffffu, mx0, 2));
        mx1 = fmaxf(mx1, __shfl_xor_sync(0xffffffffu, mx1, 1));
        mx1 = fmaxf(mx1, __shfl_xor_sync(0xffffffffu, mx1, 2));
        const float mn0 = fmaxf(m0, mx0), mn1 = fmaxf(m1, mx1);
        const float cr0 = fexp(m0 - mn0),  cr1 = fexp(m1 - mn1);
        float s0 = 0.f, s1 = 0.f;
        #pragma unroll
        for (int ni = 0; ni < 8; ni++) {
            float p0 = fexp(sc[ni][0] - mn0);
            float p1 = fexp(sc[ni][1] - mn0);
            float p2 = fexp(sc[ni][2] - mn1);
            float p3 = fexp(sc[ni][3] - mn1);
            sc[ni][0] = p0; sc[ni][1] = p1; sc[ni][2] = p2; sc[ni][3] = p3;
            s0 += p0 + p1; s1 += p2 + p3;
        }
        s0 += __shfl_xor_sync(0xffffffffu, s0, 1);
        s0 += __shfl_xor_sync(0xffffffffu, s0, 2);
        s1 += __shfl_xor_sync(0xffffffffu, s1, 1);
        s1 += __shfl_xor_sync(0xffffffffu, s1, 2);
        l0 = l0*cr0 + s0; l1 = l1*cr1 + s1;
        m0 = mn0; m1 = mn1;
        #pragma unroll
        for (int nb = 0; nb < 8; nb++) {
            o[nb][0] *= cr0; o[nb][1] *= cr0;
            o[nb][2] *= cr1; o[nb][3] *= cr1;
        }

        #pragma unroll
        for (int jj = 0; jj < 4; jj++) {
            uint32_t ah[4], al[4];
            hpack(sc[2*jj][0],   sc[2*jj][1],   ah[0], al[0]);
            hpack(sc[2*jj][2],   sc[2*jj][3],   ah[1], al[1]);
            hpack(sc[2*jj+1][0], sc[2*jj+1][1], ah[2], al[2]);
            hpack(sc[2*jj+1][2], sc[2*jj+1][3], ah[3], al[3]);
            #pragma unroll
            for (int nb = 0; nb < 8; nb++) {
                uint32_t bh2[2], bl2[2];
                int cb = (nb*8 + g)*36 + jj*8 + t;
                bh2[0] = VH[cb]; bh2[1] = VH[cb + 4];
                bl2[0] = VL[cb]; bl2[1] = VL[cb + 4];
                MMA16(o[nb], ah, bh2);
                MMA16(o[nb], ah, bl2);
                MMA16(o[nb], al, bh2);
            }
        }
    }

    const float inv0 = 1.f / l0, inv1 = 1.f / l1;
    const int gr0 = b*1024 + qb*64 + mr + g;
    #pragma unroll
    for (int nb = 0; nb < 8; nb++) {
        const int kp = h*32 + nb*4 + t;
        uint32_t hh, ll;
        hpack(o[nb][0]*inv0, o[nb][1]*inv0, hh, ll);
        g_cH[gr0*256 + kp] = hh;
        g_cL[gr0*256 + kp] = ll;
        hpack(o[nb][2]*inv1, o[nb][3]*inv1, hh, ll);
        g_cH[(gr0 + 8)*256 + kp] = hh;
        g_cL[(gr0 + 8)*256 + kp] = ll;
    }
}

__global__ void __launch_bounds__(128) fattn2_kernel() {
    extern __shared__ uint32_t fsm[];
    uint32_t* QH = fsm;
    uint32_t* QL = QH + 2304;
    uint32_t* KH = QL + 2304;
    uint32_t* KL = KH + 2304;
    uint32_t* VH = KL + 2304;
    uint32_t* VL = VH + 2304;
    const uint32_t sbase = (uint32_t)__cvta_generic_to_shared(fsm);

    const int p  = blockIdx.x;
    const int bh = blockIdx.y;
    const int b = bh >> 3, h = bh & 7;
    const int tid = threadIdx.x;

    fa2_tile(QH, QL, KH, KL, VH, VL, sbase, p,      b, h, tid);
    __syncthreads();
    fa2_tile(QH, QL, KH, KL, VH, VL, sbase, 15 - p, b, h, tid);
}

// ------------- fused residual add + LayerNorm -> fp32 x AND packed x -----------
__global__ void __launch_bounds__(256) add_ln_kernel(const float* __restrict__ g,
                                                     const float* __restrict__ bta) {
    const int row = blockIdx.x;
    float* x = g_x + (size_t)row*D_;
    const float* dl = g_tmp + (size_t)row*D_;
    const int tid = threadIdx.x;
    __shared__ float red[256];

    float2 xv = reinterpret_cast<const float2*>(x)[tid];
    float2 dv = reinterpret_cast<const float2*>(dl)[tid];
    float v0 = xv.x + dv.x;
    float v1 = xv.y + dv.y;

    red[tid] = v0 + v1; __syncthreads();
    for (int off = 128; off > 0; off >>= 1) {
        if (tid < off) red[tid] += red[tid + off];
        __syncthreads();
    }
    const float mu = red[0] * (1.f/512.f); __syncthreads();

    float d0 = v0 - mu, d1 = v1 - mu;
    red[tid] = d0*d0 + d1*d1; __syncthreads();
    for (int off = 128; off > 0; off >>= 1) {
        if (tid < off) red[tid] += red[tid + off];
        __syncthreads();
    }
    const float inv = rsqrtf(red[0]*(1.f/512.f) + 1e-5f);

    const int d = tid*2;
    float o0 = d0*inv*g[d]     + bta[d];
    float o1 = d1*inv*g[d + 1] + bta[d + 1];
    reinterpret_cast<float2*>(x)[tid] = make_float2(o0, o1);
    uint32_t h, l;
    hpack(o0, o1, h, l);
    g_xH[row*256 + tid] = h;
    g_xL[row*256 + tid] = l;
}

// ---------------- launch ---------------------------------------------------------
#define SMEM_NI4   ((4*128*AU + 4*128*AU)*4)   // 81920 (BPASS=3, NI=4)
#define SMEM_NI2   ((4*128*AU + 4*64*AU)*4)    // 61440 (BPASS=3, NI=2)
#define SMEM_NI4B2 ((4*128*AU + 2*128*AU)*4)   // 61440 (BPASS=2, NI=4)

extern "C" void kernel_launch(void* const* d_in, const int* in_sizes, int n_in,
                              void* d_out, int out_size) {
    const int*   ids  = (const int*)  d_in[0];
    const float* tok  = (const float*)d_in[1];
    const float* pos  = (const float*)d_in[2];
    const float* WQ   = (const float*)d_in[3];
    const float* WK   = (const float*)d_in[4];
    const float* WV   = (const float*)d_in[5];
    const float* WO   = (const float*)d_in[6];
    const float* ln1g = (const float*)d_in[7];
    const float* ln1b = (const float*)d_in[8];
    const float* fc1w = (const float*)d_in[9];
    const float* fc1b = (const float*)d_in[10];
    const float* fc2w = (const float*)d_in[11];
    const float* fc2b = (const float*)d_in[12];
    const float* ln2g = (const float*)d_in[13];
    const float* ln2b = (const float*)d_in[14];
    const float* lmh  = (const float*)d_in[15];
    float* out = (float*)d_out;

    float *pv, *ptmp;
    cudaGetSymbolAddress((void**)&pv,   g_v);
    cudaGetSymbolAddress((void**)&ptmp, g_tmp);

    uint32_t *xH, *xL, *cH, *cL, *fH, *fL, *qpH, *qpL;
    uint32_t *qkH, *qkL, *woH, *woL, *f1H, *f1L, *f2H, *f2L, *lmH;
    cudaGetSymbolAddress((void**)&xH,  g_xH);
    cudaGetSymbolAddress((void**)&xL,  g_xL);
    cudaGetSymbolAddress((void**)&cH,  g_cH);
    cudaGetSymbolAddress((void**)&cL,  g_cL);
    cudaGetSymbolAddress((void**)&fH,  g_fH);
    cudaGetSymbolAddress((void**)&fL,  g_fL);
    cudaGetSymbolAddress((void**)&qpH, g_qkpH);
    cudaGetSymbolAddress((void**)&qpL, g_qkpL);
    cudaGetSymbolAddress((void**)&qkH, g_wqkvH);
    cudaGetSymbolAddress((void**)&qkL, g_wqkvL);
    cudaGetSymbolAddress((void**)&woH, g_woH);
    cudaGetSymbolAddress((void**)&woL, g_woL);
    cudaGetSymbolAddress((void**)&f1H, g_fc1H);
    cudaGetSymbolAddress((void**)&f1L, g_fc1L);
    cudaGetSymbolAddress((void**)&f2H, g_fc2H);
    cudaGetSymbolAddress((void**)&f2L, g_fc2L);
    cudaGetSymbolAddress((void**)&lmH, g_lmhH);

    cudaFuncSetAttribute((const void*)fattn2_kernel,          cudaFuncAttributeMaxDynamicSharedMemorySize, FA2_SMEM);
    cudaFuncSetAttribute((const void*)gemm_pk<2,0,false,4,3>, cudaFuncAttributeMaxDynamicSharedMemorySize, SMEM_NI4);
    cudaFuncSetAttribute((const void*)gemm_pk<0,0,false,2,3>, cudaFuncAttributeMaxDynamicSharedMemorySize, SMEM_NI2);
    cudaFuncSetAttribute((const void*)gemm_pk<1,2,false,4,3>, cudaFuncAttributeMaxDynamicSharedMemorySize, SMEM_NI4);
    cudaFuncSetAttribute((const void*)gemm_pk<0,1,false,2,3>, cudaFuncAttributeMaxDynamicSharedMemorySize, SMEM_NI2);
    cudaFuncSetAttribute((const void*)gemm_pk<0,0,true,4,2>,  cudaFuncAttributeMaxDynamicSharedMemorySize, SMEM_NI4B2);

    // launch order keeps the 6th launch = fattn2 for ncu (-s 5 -c 1)
    embed_kernel<<<BT_, 256>>>(ids, tok, pos);                           // 1
    prepack_small<<<dim3(32, 32, 3*L_), 256>>>(WO, fc1w, fc2w);          // 2
    prepack_qkvw<<<dim3(QKVW_/64, 8, L_), 256>>>(WQ, WK, WV);            // 3
    prepack_b_hi<<<dim3(VP_/64, 8), 256>>>(lmh, lmH, D_, V_, VP_);       // 4

    for (int l = 0; l < L_; l++) {
        gemm_pk<2,0,false,4,3><<<dim3(QKVW_/128, BT_/128), 256, SMEM_NI4>>>(
            BT_, QKVW_, D_, xH, xL,
            qkH + (size_t)l*QKVW_*256, qkL + (size_t)l*QKVW_*256,
            pv, 512, qpH, qpL, nullptr);                                 // 5 (l=0)

        fattn2_kernel<<<dim3(8, B_*H_), 128, FA2_SMEM>>>();              // 6 (l=0)

        gemm_pk<0,0,false,2,3><<<dim3(D_/64, BT_/128), 256, SMEM_NI2>>>(
            BT_, D_, D_, cH, cL,
            woH + (size_t)l*D_*256, woL + (size_t)l*D_*256,
            ptmp, D_, nullptr, nullptr, nullptr);

        add_ln_kernel<<<BT_, 256>>>(ln1g + l*D_, ln1b + l*D_);

        gemm_pk<1,2,false,4,3><<<dim3(DFF_/128, BT_/128), 256, SMEM_NI4>>>(
            BT_, DFF_, D_, xH, xL,
            f1H + (size_t)l*DFF_*256, f1L + (size_t)l*DFF_*256,
            nullptr, 0, fH, fL, fc1b + l*DFF_);

        gemm_pk<0,1,false,2,3><<<dim3(D_/64, BT_/128), 256, SMEM_NI2>>>(
            BT_, D_, DFF_, fH, fL,
            f2H + (size_t)l*D_*1024, f2L + (size_t)l*D_*1024,
            ptmp, D_, nullptr, nullptr, fc2b + l*D_);

        add_ln_kernel<<<BT_, 256>>>(ln2g + l*D_, ln2b + l*D_);
    }

    // lm_head: fp16x2 (A split, B single fp16) — B-rounding lands once on output
    gemm_pk<0,0,true,4,2><<<dim3(VP_/128, BT_/128), 256, SMEM_NI4B2>>>(
        BT_, V_, D_, xH, xL, lmH, nullptr, out, V_, nullptr, nullptr, nullptr);
}

// round 11
// speedup vs baseline: 4.2169x; 1.1271x over previous
#include <cuda_runtime.h>
#include <cuda_fp16.h>
#include <math.h>
#include <math_constants.h>
#include <stdint.h>

#define B_   2
#define T_   1024
#define D_   512
#define H_   8
#define DK_  64
#define DFF_ 2048
#define L_   6
#define V_   50257
#define VP_  50304   // V padded to 128
#define PAD_ 50256
#define BT_  (B_*T_)
#define QKVW_ (3*D_)   // 1536

// ---------------- scratch (device globals; no allocations allowed) ----------
__device__ float g_x[BT_*D_];
__device__ float g_v[BT_*D_];                          // V fp32 (per layer)
__device__ float g_tmp[BT_*D_];

// packed fp16 hi/lo activation buffers (u32 = half2 of adjacent k)
__device__ uint32_t g_xH[BT_*256],  g_xL[BT_*256];     // x packed (K=512)
__device__ uint32_t g_cH[BT_*256],  g_cL[BT_*256];     // ctx packed
__device__ uint32_t g_fH[BT_*1024], g_fL[BT_*1024];    // ffn hidden packed
__device__ uint32_t g_qkpH[BT_*512], g_qkpL[BT_*512];  // Q,K packed (512 pairs/row)
// packed weights
__device__ uint32_t g_wqkvH[L_*QKVW_*256], g_wqkvL[L_*QKVW_*256];
__device__ uint32_t g_woH[L_*D_*256],      g_woL[L_*D_*256];
__device__ uint32_t g_fc1H[L_*DFF_*256],   g_fc1L[L_*DFF_*256];
__device__ uint32_t g_fc2H[L_*D_*1024],    g_fc2L[L_*D_*1024];
__device__ uint32_t g_lmhH[(size_t)VP_*256];           // lm_head single fp16 (x1 path)

// ---------------- helpers ------------------------------------------------------
__device__ __forceinline__ void hpack(float x0, float x1, uint32_t& hi, uint32_t& lo) {
    __half h0 = __float2half_rn(x0);
    __half h1 = __float2half_rn(x1);
    __half l0 = __float2half_rn(x0 - __half2float(h0));
    __half l1 = __float2half_rn(x1 - __half2float(h1));
    hi = ((uint32_t)__half_as_ushort(h1) << 16) | (uint32_t)__half_as_ushort(h0);
    lo = ((uint32_t)__half_as_ushort(l1) << 16) | (uint32_t)__half_as_ushort(l0);
}
__device__ __forceinline__ uint32_t hpack1(float x0, float x1) {
    return ((uint32_t)__half_as_ushort(__float2half_rn(x1)) << 16)
         |  (uint32_t)__half_as_ushort(__float2half_rn(x0));
}

// fast exp on the FMA pipe (arg <= 0 path; clamps; ~2e-8 rel err)
__device__ __forceinline__ float fexp(float x) {
    x = fmaxf(x, -87.0f);
    float t = fmaf(x, 1.4426950408889634f, 12582912.0f);
    float r = t - 12582912.0f;
    float f = fmaf(x, 1.4426950408889634f, -r);
    float p =        1.3333558e-3f;
    p = fmaf(p, f, 9.6181291e-3f);
    p = fmaf(p, f, 5.5504109e-2f);
    p = fmaf(p, f, 2.4022651e-1f);
    p = fmaf(p, f, 6.9314718e-1f);
    p = fmaf(p, f, 1.0f);
    int e = (__float_as_int(t) + 127) << 23;
    return p * __int_as_float(e);
}

#define MMA16(cc, a, b) \
    asm volatile("mma.sync.aligned.m16n8k16.row.col.f32.f16.f16.f32 " \
        "{%0,%1,%2,%3}, {%4,%5,%6,%7}, {%8,%9}, {%0,%1,%2,%3};" \
        : "+f"((cc)[0]), "+f"((cc)[1]), "+f"((cc)[2]), "+f"((cc)[3]) \
        : "r"((a)[0]), "r"((a)[1]), "r"((a)[2]), "r"((a)[3]), \
          "r"((b)[0]), "r"((b)[1]))

__device__ __forceinline__ void cpa16(uint32_t dst, const void* src) {
    asm volatile("cp.async.cg.shared.global [%0], [%1], 16;" :: "r"(dst), "l"(src));
}
#define CP_COMMIT() asm volatile("cp.async.commit_group;" ::: "memory")

// ================ prepack kernels (coalesced transpose) ========================
// lm_head: W fp32 [K][N] -> [Npad][K/2] single fp16 (hi only, for x1 path)
__global__ void prepack_b_hi(const float* __restrict__ W, uint32_t* __restrict__ oH,
                             int K, int N, int Npad) {
    __shared__ uint32_t sh[64*33];
    const int KP = K >> 1;
    const int n0 = blockIdx.x * 64, kp0 = blockIdx.y * 32;
    const int tid = threadIdx.x;
    #pragma unroll
    for (int i = 0; i < 8; i++) {
        int f = tid + i*256;
        int n = f & 63, kp = f >> 6;
        int gn = n0 + n;
        float x0 = 0.f, x1 = 0.f;
        if (gn < N) {
            int k2 = (kp0 + kp) * 2;
            x0 = W[(size_t)k2*N + gn];
            x1 = W[(size_t)(k2 + 1)*N + gn];
        }
        sh[n*33 + kp] = hpack1(x0, x1);
    }
    __syncthreads();
    #pragma unroll
    for (int i = 0; i < 8; i++) {
        int f = tid + i*256;
        int kp = f & 31, n = f >> 5;
        oH[(size_t)(n0 + n)*KP + kp0 + kp] = sh[n*33 + kp];
    }
}

// QKV weights straight from WQ/WK/WV [L,H,D,DK] -> [L][1536 n][256 kp] packed
__global__ void prepack_qkvw(const float* __restrict__ WQ,
                             const float* __restrict__ WK,
                             const float* __restrict__ WV) {
    __shared__ uint32_t sh[64*33], sl[64*33];
    const int l = blockIdx.z;
    const int n0 = blockIdx.x*64, kp0 = blockIdx.y*32;
    const int tid = threadIdx.x;
    #pragma unroll
    for (int i = 0; i < 8; i++) {
        int f = tid + i*256;
        int n = f & 63, kp = f >> 6;
        int gn = n0 + n;
        int part = gn >> 9, hh = (gn >> 6) & 7, kk = gn & 63;
        const float* W = part == 0 ? WQ : (part == 1 ? WK : WV);
        size_t base = (((size_t)l*H_ + hh)*D_ + 2*(kp0 + kp))*DK_ + kk;
        uint32_t h, l2;
        hpack(W[base], W[base + DK_], h, l2);
        sh[n*33 + kp] = h;
        sl[n*33 + kp] = l2;
    }
    __syncthreads();
    #pragma unroll
    for (int i = 0; i < 8; i++) {
        int f = tid + i*256;
        int kp = f & 31, n = f >> 5;
        size_t go = (size_t)l*QKVW_*256 + (size_t)(n0 + n)*256 + kp0 + kp;
        g_wqkvH[go] = sh[n*33 + kp];
        g_wqkvL[go] = sl[n*33 + kp];
    }
}

// WO/FC1/FC2 for all layers, z = type*L + l
__global__ void prepack_small(const float* __restrict__ WO,
                              const float* __restrict__ F1,
                              const float* __restrict__ F2) {
    __shared__ uint32_t sh[64*33], sl[64*33];
    const int z = blockIdx.z;
    const int type = z / L_, l = z % L_;
    int K, N; const float* W; uint32_t *oH, *oL;
    if (type == 0)      { K = D_;   N = D_;   W = WO + (size_t)l*D_*D_;    oH = g_woH  + (size_t)l*D_*256;   oL = g_woL  + (size_t)l*D_*256; }
    else if (type == 1) { K = D_;   N = DFF_; W = F1 + (size_t)l*D_*DFF_;  oH = g_fc1H + (size_t)l*DFF_*256; oL = g_fc1L + (size_t)l*DFF_*256; }
    else                { K = DFF_; N = D_;   W = F2 + (size_t)l*DFF_*D_;  oH = g_fc2H + (size_t)l*D_*1024;  oL = g_fc2L + (size_t)l*D_*1024; }
    const int KP = K >> 1;
    const int n0 = blockIdx.x*64, kp0 = blockIdx.y*32;
    if (n0 >= N || kp0 >= KP) return;
    const int tid = threadIdx.x;
    #pragma unroll
    for (int i = 0; i < 8; i++) {
        int f = tid + i*256;
        int n = f & 63, kp = f >> 6;
        int k2 = (kp0 + kp)*2;
        uint32_t h, l2;
        hpack(W[(size_t)k2*N + n0 + n], W[(size_t)(k2+1)*N + n0 + n], h, l2);
        sh[n*33 + kp] = h;
        sl[n*33 + kp] = l2;
    }
    __syncthreads();
    #pragma unroll
    for (int i = 0; i < 8; i++) {
        int f = tid + i*256;
        int kp = f & 31, n = f >> 5;
        size_t go = (size_t)(n0 + n)*KP + kp0 + kp;
        oH[go] = sh[n*33 + kp];
        oL[go] = sl[n*33 + kp];
    }
}

// ============== fp16-split mma.sync GEMM, cp.async double-buffered =============
// OUT: 0 fp32 C, 1 packed hi/lo, 2 qkv-mode (c<1024 packed Q/K, else fp32 V)
// BPASS: 3 = A,B both split (3 MMA); 1 = A single, B single (1 MMA).
#define AU 20

template<int OUT, int EPI, bool GUARD, int NI, int BPASS>
__global__ void __launch_bounds__(256, 2)
gemm_pk(int M, int N, int K,
        const uint32_t* __restrict__ aH, const uint32_t* __restrict__ aL,
        const uint32_t* __restrict__ bH, const uint32_t* __restrict__ bL,
        float* __restrict__ C, int ldc,
        uint32_t* __restrict__ oH, uint32_t* __restrict__ oL,
        const float* __restrict__ bias)
{
    constexpr int NTILE = 32*NI;
    extern __shared__ uint32_t su[];
    uint32_t* AsH = su;
    uint32_t* AsL = su + 2*128*AU;              // unused when BPASS==1
    uint32_t* BsH = su + (BPASS == 3 ? 4 : 2)*128*AU;
    uint32_t* BsL = BsH + 2*NTILE*AU;           // unused when BPASS==1
    const uint32_t sb = (uint32_t)__cvta_generic_to_shared(su);
    const uint32_t sbAH = sb;
    const uint32_t sbAL = sb + 2*128*AU*4;
    const uint32_t sbBH = sb + (BPASS == 3 ? 4 : 2)*128*AU*4;
    const uint32_t sbBL = sbBH + 2*NTILE*AU*4;

    const int KP   = K >> 1;
    const int tid  = threadIdx.x;
    const int wid  = tid >> 5, lane = tid & 31;
    const int g    = lane >> 2, t = lane & 3;
    const int bm   = blockIdx.y * 128, bn = blockIdx.x * NTILE;
    const int m0   = (wid >> 2) * 64, n0 = (wid & 3) * (8*NI);

    float c[4][NI][4];
    #pragma unroll
    for (int mi = 0; mi < 4; mi++)
        #pragma unroll
        for (int ni = 0; ni < NI; ni++)
            #pragma unroll
            for (int j = 0; j < 4; j++) c[mi][ni][j] = 0.f;

    const int NKT = K >> 5;

    auto load_tile = [&](int kt, int pb) {
        const int kp0 = kt << 4;
        #pragma unroll
        for (int i = 0; i < 2; i++) {
            int f = tid + i*256;
            int r = f >> 2, cc = (f & 3) << 2;
            size_t go = (size_t)(bm + r)*KP + kp0 + cc;
            uint32_t so = (uint32_t)((pb*128 + r)*AU + cc)*4;
            cpa16(sbAH + so, aH + go);
            if (BPASS == 3) cpa16(sbAL + so, aL + go);
        }
        #pragma unroll
        for (int i = 0; i < NI/2; i++) {
            int f = tid + i*256;
            int n = f >> 2, cc = (f & 3) << 2;
            size_t go = (size_t)(bn + n)*KP + kp0 + cc;
            uint32_t so = (uint32_t)((pb*NTILE + n)*AU + cc)*4;
            cpa16(sbBH + so, bH + go);
            if (BPASS == 3) cpa16(sbBL + so, bL + go);
        }
        CP_COMMIT();
    };

    load_tile(0, 0);

    for (int kt = 0; kt < NKT; kt++) {
        const int pb = kt & 1;
        if (kt + 1 < NKT) {
            load_tile(kt + 1, pb ^ 1);
            asm volatile("cp.async.wait_group 1;" ::: "memory");
        } else {
            asm volatile("cp.async.wait_group 0;" ::: "memory");
        }
        __syncthreads();

        const uint32_t* ah_b = AsH + pb*128*AU;
        const uint32_t* al_b = AsL + pb*128*AU;
        const uint32_t* bh_b = BsH + pb*NTILE*AU;
        const uint32_t* bl_b = BsL + pb*NTILE*AU;

        #pragma unroll
        for (int ks = 0; ks < 2; ks++) {
            const int kb = ks*8;
            uint32_t bh[NI][2], bl[NI][2];
            #pragma unroll
            for (int ni = 0; ni < NI; ni++) {
                int col = (n0 + ni*8 + g)*AU + kb;
                bh[ni][0] = bh_b[col + t];
                bh[ni][1] = bh_b[col + t + 4];
                if (BPASS == 3) {
                    bl[ni][0] = bl_b[col + t];
                    bl[ni][1] = bl_b[col + t + 4];
                }
            }
            #pragma unroll
            for (int mi = 0; mi < 4; mi++) {
                int row = m0 + mi*16 + g;
                uint32_t ah[4], al[4];
                ah[0] = ah_b[(row    )*AU + kb + t];
                ah[1] = ah_b[(row + 8)*AU + kb + t];
                ah[2] = ah_b[(row    )*AU + kb + t + 4];
                ah[3] = ah_b[(row + 8)*AU + kb + t + 4];
                if (BPASS == 3) {
                    al[0] = al_b[(row    )*AU + kb + t];
                    al[1] = al_b[(row + 8)*AU + kb + t];
                    al[2] = al_b[(row    )*AU + kb + t + 4];
                    al[3] = al_b[(row + 8)*AU + kb + t + 4];
                }
                #pragma unroll
                for (int ni = 0; ni < NI; ni++) {
                    MMA16(c[mi][ni], ah, bh[ni]);
                    if (BPASS == 3) {
                        MMA16(c[mi][ni], ah, bl[ni]);
                        MMA16(c[mi][ni], al, bh[ni]);
                    }
                }
            }
        }
        __syncthreads();
    }

    const int KP2 = (OUT == 2) ? 512 : (N >> 1);
    #pragma unroll
    for (int mi = 0; mi < 4; mi++) {
        const int r0 = bm + m0 + mi*16 + g;
        #pragma unroll
        for (int ni = 0; ni < NI; ni++) {
            const int c0 = bn + n0 + ni*8 + t*2;
            #pragma unroll
            for (int half = 0; half < 2; half++) {
                const int gr = r0 + half*8;
                float v0 = c[mi][ni][2*half + 0];
                float v1 = c[mi][ni][2*half + 1];
                if (EPI >= 1) { v0 += bias[c0]; v1 += bias[c0 + 1]; }
                if (EPI == 2) {
                    v0 = 0.5f*v0*(1.f + erff(v0*0.70710678118654752f));
                    v1 = 0.5f*v1*(1.f + erff(v1*0.70710678118654752f));
                }
                if (OUT == 0) {
                    if (!GUARD || c0 < N)     C[(size_t)gr*ldc + c0]     = v0;
                    if (!GUARD || c0 + 1 < N) C[(size_t)gr*ldc + c0 + 1] = v1;
                } else if (OUT == 1) {
                    uint32_t h, l;
                    hpack(v0, v1, h, l);
                    oH[(size_t)gr*KP2 + (c0 >> 1)] = h;
                    oL[(size_t)gr*KP2 + (c0 >> 1)] = l;
                } else {
                    if (c0 < 1024) {
                        uint32_t h, l;
                        hpack(v0, v1, h, l);
                        oH[(size_t)gr*512 + (c0 >> 1)] = h;
                        oL[(size_t)gr*512 + (c0 >> 1)] = l;
                    } else {
                        C[(size_t)gr*512 + (c0 - 1024)]     = v0;
                        C[(size_t)gr*512 + (c0 - 1024) + 1] = v1;
                    }
                }
            }
        }
    }
}

// ---------------- embedding -----------------------------------------------------
__global__ void embed_kernel(const int* __restrict__ ids,
                             const float* __restrict__ tok,
                             const float* __restrict__ pos) {
    const int row = blockIdx.x;
    const int t   = row % T_;
    const int id  = ids[row];
    const int tid = threadIdx.x;
    const float sc = 22.62741699796952f;
    const int d = tid*2;
    float e0 = (id == PAD_) ? 0.f : tok[(size_t)id*D_ + d];
    float e1 = (id == PAD_) ? 0.f : tok[(size_t)id*D_ + d + 1];
    float v0 = e0*sc + pos[(size_t)t*D_ + d];
    float v1 = e1*sc + pos[(size_t)t*D_ + d + 1];
    *reinterpret_cast<float2*>(g_x + (size_t)row*D_ + d) = make_float2(v0, v1);
    uint32_t h, l;
    hpack(v0, v1, h, l);
    g_xH[row*256 + tid] = h;
    g_xL[row*256 + tid] = l;
}

// ================ fattn2: tensor-core fp16x3 flash attention ===================
#define FA2_SMEM (6*2304*4)   // 55296 bytes

__device__ __forceinline__ void fa2_tile(
    uint32_t* QH, uint32_t* QL, uint32_t* KH, uint32_t* KL,
    uint32_t* VH, uint32_t* VL, uint32_t sbase,
    int qb, int b, int h, int tid)
{
    const int w = tid >> 5, lane = tid & 31;
    const int g = lane >> 2, t = lane & 3;
    const int mr = w*16;
    const uint32_t sQH = sbase, sQL = sbase + 9216;
    const uint32_t sKH = sbase + 18432, sKL = sbase + 27648;

    #pragma unroll
    for (int i = 0; i < 4; i++) {
        int idx = tid + i*128;
        int r = idx >> 3, c4 = (idx & 7) << 2;
        size_t go = ((size_t)(b*1024 + qb*64 + r) << 9) + h*32 + c4;
        cpa16(sQH + (uint32_t)(r*36 + c4)*4, g_qkpH + go);
        cpa16(sQL + (uint32_t)(r*36 + c4)*4, g_qkpL + go);
    }
    CP_COMMIT();

    float m0 = -CUDART_INF_F, m1 = -CUDART_INF_F, l0 = 0.f, l1 = 0.f;
    float o[8][4];
    #pragma unroll
    for (int nb = 0; nb < 8; nb++)
        #pragma unroll
        for (int j = 0; j < 4; j++) o[nb][j] = 0.f;

    const int nkt = qb + 1;
    for (int kt = 0; kt < nkt; kt++) {
        __syncthreads();
        #pragma unroll
        for (int i = 0; i < 4; i++) {
            int idx = tid + i*128;
            int r = idx >> 3, c4 = (idx & 7) << 2;
            size_t go = ((size_t)(b*1024 + kt*64 + r) << 9) + 256 + h*32 + c4;
            cpa16(sKH + (uint32_t)(r*36 + c4)*4, g_qkpH + go);
            cpa16(sKL + (uint32_t)(r*36 + c4)*4, g_qkpL + go);
        }
        CP_COMMIT();
        #pragma unroll
        for (int i = 0; i < 16; i++) {
            int idx = tid + i*128;
            int n = idx & 63, r = idx >> 6;
            size_t base = ((size_t)(b*1024 + kt*64 + 2*r) << 9) + h*64 + n;
            uint32_t hh, ll;
            hpack(g_v[base], g_v[base + 512], hh, ll);
            VH[n*36 + r] = hh;
            VL[n*36 + r] = ll;
        }
        asm volatile("cp.async.wait_group 0;" ::: "memory");
        __syncthreads();

        float sc[8][4];
        #pragma unroll
        for (int ni = 0; ni < 8; ni++)
            #pragma unroll
            for (int j = 0; j < 4; j++) sc[ni][j] = 0.f;
        #pragma unroll
        for (int j = 0; j < 4; j++) {
            uint32_t ah[4], al[4];
            int rb = (mr + g)*36 + j*8 + t;
            ah[0] = QH[rb];            al[0] = QL[rb];
            ah[1] = QH[rb + 8*36];     al[1] = QL[rb + 8*36];
            ah[2] = QH[rb + 4];        al[2] = QL[rb + 4];
            ah[3] = QH[rb + 8*36 + 4]; al[3] = QL[rb + 8*36 + 4];
            #pragma unroll
            for (int ni = 0; ni < 8; ni++) {
                uint32_t bh2[2], bl2[2];
                int cb = (ni*8 + g)*36 + j*8 + t;
                bh2[0] = KH[cb]; bh2[1] = KH[cb + 4];
                bl2[0] = KL[cb]; bl2[1] = KL[cb + 4];
                MMA16(sc[ni], ah, bh2);
                MMA16(sc[ni], ah, bl2);
                MMA16(sc[ni], al, bh2);
            }
        }
        const int qr0 = qb*64 + mr + g;
        const bool diag = (kt == qb);
        #pragma unroll
        for (int ni = 0; ni < 8; ni++)
            #pragma unroll
            for (int cc = 0; cc < 4; cc++) {
                float v = sc[ni][cc]*0.125f;
                if (diag) {
                    int key = kt*64 + ni*8 + 2*t + (cc & 1);
                    int qr = qr0 + (cc >> 1)*8;
                    if (key > qr) v = -CUDART_INF_F;
                }
                sc[ni][cc] = v;
            }

        float mx0 = -CUDART_INF_F, mx1 = -CUDART_INF_F;
        #pragma unroll
        for (int ni = 0; ni < 8; ni++) {
            mx0 = fmaxf(mx0, fmaxf(sc[ni][0], sc[ni][1]));
            mx1 = fmaxf(mx1, fmaxf(sc[ni][2], sc[ni][3]));
        }
        mx0 = fmaxf(mx0, __shfl_xor_sync(0xffffffffu, mx0, 1));
        mx0 = fmaxf(mx0, __shfl_xor_sync(0xffffffffu, mx0, 2));
        mx1 = fmaxf(mx1, __shfl_xor_sync(0xffffffffu, mx1, 1));
        mx1 = fmaxf(mx1, __shfl_xor_sync(0xffffffffu, mx1, 2));
        const float mn0 = fmaxf(m0, mx0), mn1 = fmaxf(m1, mx1);
        const float cr0 = fexp(m0 - mn0),  cr1 = fexp(m1 - mn1);
        float s0 = 0.f, s1 = 0.f;
        #pragma unroll
        for (int ni = 0; ni < 8; ni++) {
            float p0 = fexp(sc[ni][0] - mn0);
            float p1 = fexp(sc[ni][1] - mn0);
            float p2 = fexp(sc[ni][2] - mn1);
            float p3 = fexp(sc[ni][3] - mn1);
            sc[ni][0] = p0; sc[ni][1] = p1; sc[ni][2] = p2; sc[ni][3] = p3;
            s0 += p0 + p1; s1 += p2 + p3;
        }
        s0 += __shfl_xor_sync(0xffffffffu, s0, 1);
        s0 += __shfl_xor_sync(0xffffffffu, s0, 2);
        s1 += __shfl_xor_sync(0xffffffffu, s1, 1);
        s1 += __shfl_xor_sync(0xffffffffu, s1, 2);
        l0 = l0*cr0 + s0; l1 = l1*cr1 + s1;
        m0 = mn0; m1 = mn1;
        #pragma unroll
        for (int nb = 0; nb < 8; nb++) {
            o[nb][0] *= cr0; o[nb][1] *= cr0;
            o[nb][2] *= cr1; o[nb][3] *= cr1;
        }

        #pragma unroll
        for (int jj = 0; jj < 4; jj++) {
            uint32_t ah[4], al[4];
            hpack(sc[2*jj][0],   sc[2*jj][1],   ah[0], al[0]);
            hpack(sc[2*jj][2],   sc[2*jj][3],   ah[1], al[1]);
            hpack(sc[2*jj+1][0], sc[2*jj+1][1], ah[2], al[2]);
            hpack(sc[2*jj+1][2], sc[2*jj+1][3], ah[3], al[3]);
            #pragma unroll
            for (int nb = 0; nb < 8; nb++) {
                uint32_t bh2[2], bl2[2];
                int cb = (nb*8 + g)*36 + jj*8 + t;
                bh2[0] = VH[cb]; bh2[1] = VH[cb + 4];
                bl2[0] = VL[cb]; bl2[1] = VL[cb + 4];
                MMA16(o[nb], ah, bh2);
                MMA16(o[nb], ah, bl2);
                MMA16(o[nb], al, bh2);
            }
        }
    }

    const float inv0 = 1.f / l0, inv1 = 1.f / l1;
    const int gr0 = b*1024 + qb*64 + mr + g;
    #pragma unroll
    for (int nb = 0; nb < 8; nb++) {
        const int kp = h*32 + nb*4 + t;
        uint32_t hh, ll;
        hpack(o[nb][0]*inv0, o[nb][1]*inv0, hh, ll);
        g_cH[gr0*256 + kp] = hh;
        g_cL[gr0*256 + kp] = ll;
        hpack(o[nb][2]*inv1, o[nb][3]*inv1, hh, ll);
        g_cH[(gr0 + 8)*256 + kp] = hh;
        g_cL[(gr0 + 8)*256 + kp] = ll;
    }
}

__global__ void __launch_bounds__(128) fattn2_kernel() {
    extern __shared__ uint32_t fsm[];
    uint32_t* QH = fsm;
    uint32_t* QL = QH + 2304;
    uint32_t* KH = QL + 2304;
    uint32_t* KL = KH + 2304;
    uint32_t* VH = KL + 2304;
    uint32_t* VL = VH + 2304;
    const uint32_t sbase = (uint32_t)__cvta_generic_to_shared(fsm);

    const int p  = blockIdx.x;
    const int bh = blockIdx.y;
    const int b = bh >> 3, h = bh & 7;
    const int tid = threadIdx.x;

    fa2_tile(QH, QL, KH, KL, VH, VL, sbase, p,      b, h, tid);
    __syncthreads();
    fa2_tile(QH, QL, KH, KL, VH, VL, sbase, 15 - p, b, h, tid);
}

// ------------- fused residual add + LayerNorm -> fp32 x AND packed x -----------
__global__ void __launch_bounds__(256) add_ln_kernel(const float* __restrict__ g,
                                                     const float* __restrict__ bta) {
    const int row = blockIdx.x;
    float* x = g_x + (size_t)row*D_;
    const float* dl = g_tmp + (size_t)row*D_;
    const int tid = threadIdx.x;
    __shared__ float red[256];

    float2 xv = reinterpret_cast<const float2*>(x)[tid];
    float2 dv = reinterpret_cast<const float2*>(dl)[tid];
    float v0 = xv.x + dv.x;
    float v1 = xv.y + dv.y;

    red[tid] = v0 + v1; __syncthreads();
    for (int off = 128; off > 0; off >>= 1) {
        if (tid < off) red[tid] += red[tid + off];
        __syncthreads();
    }
    const float mu = red[0] * (1.f/512.f); __syncthreads();

    float d0 = v0 - mu, d1 = v1 - mu;
    red[tid] = d0*d0 + d1*d1; __syncthreads();
    for (int off = 128; off > 0; off >>= 1) {
        if (tid < off) red[tid] += red[tid + off];
        __syncthreads();
    }
    const float inv = rsqrtf(red[0]*(1.f/512.f) + 1e-5f);

    const int d = tid*2;
    float o0 = d0*inv*g[d]     + bta[d];
    float o1 = d1*inv*g[d + 1] + bta[d + 1];
    reinterpret_cast<float2*>(x)[tid] = make_float2(o0, o1);
    uint32_t h, l;
    hpack(o0, o1, h, l);
    g_xH[row*256 + tid] = h;
    g_xL[row*256 + tid] = l;
}

// ---------------- launch ---------------------------------------------------------
#define SMEM_NI4   ((4*128*AU + 4*128*AU)*4)   // 81920 (BPASS=3, NI=4)
#define SMEM_NI2   ((4*128*AU + 4*64*AU)*4)    // 61440 (BPASS=3, NI=2)
#define SMEM_NI4B1 ((2*128*AU + 2*128*AU)*4)   // 40960 (BPASS=1, NI=4)

extern "C" void kernel_launch(void* const* d_in, const int* in_sizes, int n_in,
                              void* d_out, int out_size) {
    const int*   ids  = (const int*)  d_in[0];
    const float* tok  = (const float*)d_in[1];
    const float* pos  = (const float*)d_in[2];
    const float* WQ   = (const float*)d_in[3];
    const float* WK   = (const float*)d_in[4];
    const float* WV   = (const float*)d_in[5];
    const float* WO   = (const float*)d_in[6];
    const float* ln1g = (const float*)d_in[7];
    const float* ln1b = (const float*)d_in[8];
    const float* fc1w = (const float*)d_in[9];
    const float* fc1b = (const float*)d_in[10];
    const float* fc2w = (const float*)d_in[11];
    const float* fc2b = (const float*)d_in[12];
    const float* ln2g = (const float*)d_in[13];
    const float* ln2b = (const float*)d_in[14];
    const float* lmh  = (const float*)d_in[15];
    float* out = (float*)d_out;

    float *pv, *ptmp;
    cudaGetSymbolAddress((void**)&pv,   g_v);
    cudaGetSymbolAddress((void**)&ptmp, g_tmp);

    uint32_t *xH, *xL, *cH, *cL, *fH, *fL, *qpH, *qpL;
    uint32_t *qkH, *qkL, *woH, *woL, *f1H, *f1L, *f2H, *f2L, *lmH;
    cudaGetSymbolAddress((void**)&xH,  g_xH);
    cudaGetSymbolAddress((void**)&xL,  g_xL);
    cudaGetSymbolAddress((void**)&cH,  g_cH);
    cudaGetSymbolAddress((void**)&cL,  g_cL);
    cudaGetSymbolAddress((void**)&fH,  g_fH);
    cudaGetSymbolAddress((void**)&fL,  g_fL);
    cudaGetSymbolAddress((void**)&qpH, g_qkpH);
    cudaGetSymbolAddress((void**)&qpL, g_qkpL);
    cudaGetSymbolAddress((void**)&qkH, g_wqkvH);
    cudaGetSymbolAddress((void**)&qkL, g_wqkvL);
    cudaGetSymbolAddress((void**)&woH, g_woH);
    cudaGetSymbolAddress((void**)&woL, g_woL);
    cudaGetSymbolAddress((void**)&f1H, g_fc1H);
    cudaGetSymbolAddress((void**)&f1L, g_fc1L);
    cudaGetSymbolAddress((void**)&f2H, g_fc2H);
    cudaGetSymbolAddress((void**)&f2L, g_fc2L);
    cudaGetSymbolAddress((void**)&lmH, g_lmhH);

    cudaFuncSetAttribute((const void*)fattn2_kernel,          cudaFuncAttributeMaxDynamicSharedMemorySize, FA2_SMEM);
    cudaFuncSetAttribute((const void*)gemm_pk<2,0,false,4,3>, cudaFuncAttributeMaxDynamicSharedMemorySize, SMEM_NI4);
    cudaFuncSetAttribute((const void*)gemm_pk<0,0,false,2,3>, cudaFuncAttributeMaxDynamicSharedMemorySize, SMEM_NI2);
    cudaFuncSetAttribute((const void*)gemm_pk<1,2,false,4,3>, cudaFuncAttributeMaxDynamicSharedMemorySize, SMEM_NI4);
    cudaFuncSetAttribute((const void*)gemm_pk<0,1,false,2,3>, cudaFuncAttributeMaxDynamicSharedMemorySize, SMEM_NI2);
    cudaFuncSetAttribute((const void*)gemm_pk<0,0,true,4,1>,  cudaFuncAttributeMaxDynamicSharedMemorySize, SMEM_NI4B1);

    // launch order keeps the 6th launch = fattn2 for ncu (-s 5 -c 1)
    embed_kernel<<<BT_, 256>>>(ids, tok, pos);                           // 1
    prepack_small<<<dim3(32, 32, 3*L_), 256>>>(WO, fc1w, fc2w);          // 2
    prepack_qkvw<<<dim3(QKVW_/64, 8, L_), 256>>>(WQ, WK, WV);            // 3
    prepack_b_hi<<<dim3(VP_/64, 8), 256>>>(lmh, lmH, D_, V_, VP_);       // 4

    for (int l = 0; l < L_; l++) {
        gemm_pk<2,0,false,4,3><<<dim3(QKVW_/128, BT_/128), 256, SMEM_NI4>>>(
            BT_, QKVW_, D_, xH, xL,
            qkH + (size_t)l*QKVW_*256, qkL + (size_t)l*QKVW_*256,
            pv, 512, qpH, qpL, nullptr);                                 // 5 (l=0)

        fattn2_kernel<<<dim3(8, B_*H_), 128, FA2_SMEM>>>();              // 6 (l=0)

        gemm_pk<0,0,false,2,3><<<dim3(D_/64, BT_/128), 256, SMEM_NI2>>>(
            BT_, D_, D_, cH, cL,
            woH + (size_t)l*D_*256, woL + (size_t)l*D_*256,
            ptmp, D_, nullptr, nullptr, nullptr);

        add_ln_kernel<<<BT_, 256>>>(ln1g + l*D_, ln1b + l*D_);

        gemm_pk<1,2,false,4,3><<<dim3(DFF_/128, BT_/128), 256, SMEM_NI4>>>(
            BT_, DFF_, D_, xH, xL,
            f1H + (size_t)l*DFF_*256, f1L + (size_t)l*DFF_*256,
            nullptr, 0, fH, fL, fc1b + l*DFF_);

        gemm_pk<0,1,false,2,3><<<dim3(D_/64, BT_/128), 256, SMEM_NI2>>>(
            BT_, D_, DFF_, fH, fL,
            f2H + (size_t)l*D_*1024, f2L + (size_t)l*D_*1024,
            ptmp, D_, nullptr, nullptr, fc2b + l*D_);

        add_ln_kernel<<<BT_, 256>>>(ln2g + l*D_, ln2b + l*D_);
    }

    // lm_head: fp16x1 (A single, B single) — both rounding terms land once on output
    gemm_pk<0,0,true,4,1><<<dim3(VP_/128, BT_/128), 256, SMEM_NI4B1>>>(
        BT_, V_, D_, xH, nullptr, lmH, nullptr, out, V_, nullptr, nullptr, nullptr);
}

// round 12
// speedup vs baseline: 4.4470x; 1.0546x over previous
#include <cuda_runtime.h>
#include <cuda_fp16.h>
#include <math.h>
#include <math_constants.h>
#include <stdint.h>

#define B_   2
#define T_   1024
#define D_   512
#define H_   8
#define DK_  64
#define DFF_ 2048
#define L_   6
#define V_   50257
#define VP_  50304   // V padded to 128
#define PAD_ 50256
#define BT_  (B_*T_)
#define QKVW_ (3*D_)   // 1536

// ---------------- scratch (device globals; no allocations allowed) ----------
__device__ float g_x[BT_*D_];
__device__ float g_v[BT_*D_];                          // V fp32 (per layer)
__device__ float g_tmp[BT_*D_];

// packed fp16 hi/lo activation buffers (u32 = half2 of adjacent k)
__device__ uint32_t g_xH[BT_*256],  g_xL[BT_*256];     // x packed (K=512)
__device__ uint32_t g_cH[BT_*256],  g_cL[BT_*256];     // ctx packed
__device__ uint32_t g_fH[BT_*1024], g_fL[BT_*1024];    // ffn hidden packed
__device__ uint32_t g_qkpH[BT_*512], g_qkpL[BT_*512];  // Q,K packed (512 pairs/row)
// packed weights
__device__ uint32_t g_wqkvH[L_*QKVW_*256], g_wqkvL[L_*QKVW_*256];
__device__ uint32_t g_woH[L_*D_*256],      g_woL[L_*D_*256];
__device__ uint32_t g_fc1H[L_*DFF_*256],   g_fc1L[L_*DFF_*256];
__device__ uint32_t g_fc2H[L_*D_*1024],    g_fc2L[L_*D_*1024];
__device__ uint32_t g_lmhH[(size_t)VP_*256];           // lm_head single fp16 (x1 path)

// ---------------- helpers ------------------------------------------------------
__device__ __forceinline__ void hpack(float x0, float x1, uint32_t& hi, uint32_t& lo) {
    __half h0 = __float2half_rn(x0);
    __half h1 = __float2half_rn(x1);
    __half l0 = __float2half_rn(x0 - __half2float(h0));
    __half l1 = __float2half_rn(x1 - __half2float(h1));
    hi = ((uint32_t)__half_as_ushort(h1) << 16) | (uint32_t)__half_as_ushort(h0);
    lo = ((uint32_t)__half_as_ushort(l1) << 16) | (uint32_t)__half_as_ushort(l0);
}
__device__ __forceinline__ uint32_t hpack1(float x0, float x1) {
    return ((uint32_t)__half_as_ushort(__float2half_rn(x1)) << 16)
         |  (uint32_t)__half_as_ushort(__float2half_rn(x0));
}

// fast exp on the FMA pipe (arg <= 0 path; clamps; ~2e-8 rel err)
__device__ __forceinline__ float fexp(float x) {
    x = fmaxf(x, -87.0f);
    float t = fmaf(x, 1.4426950408889634f, 12582912.0f);
    float r = t - 12582912.0f;
    float f = fmaf(x, 1.4426950408889634f, -r);
    float p =        1.3333558e-3f;
    p = fmaf(p, f, 9.6181291e-3f);
    p = fmaf(p, f, 5.5504109e-2f);
    p = fmaf(p, f, 2.4022651e-1f);
    p = fmaf(p, f, 6.9314718e-1f);
    p = fmaf(p, f, 1.0f);
    int e = (__float_as_int(t) + 127) << 23;
    return p * __int_as_float(e);
}

#define MMA16(cc, a, b) \
    asm volatile("mma.sync.aligned.m16n8k16.row.col.f32.f16.f16.f32 " \
        "{%0,%1,%2,%3}, {%4,%5,%6,%7}, {%8,%9}, {%0,%1,%2,%3};" \
        : "+f"((cc)[0]), "+f"((cc)[1]), "+f"((cc)[2]), "+f"((cc)[3]) \
        : "r"((a)[0]), "r"((a)[1]), "r"((a)[2]), "r"((a)[3]), \
          "r"((b)[0]), "r"((b)[1]))

__device__ __forceinline__ void cpa16(uint32_t dst, const void* src) {
    asm volatile("cp.async.cg.shared.global [%0], [%1], 16;" :: "r"(dst), "l"(src));
}
#define CP_COMMIT() asm volatile("cp.async.commit_group;" ::: "memory")

// ================ prepack kernels (coalesced transpose) ========================
// lm_head: W fp32 [K][N] -> [Npad][K/2] single fp16 (hi only, for x1 path)
__global__ void prepack_b_hi(const float* __restrict__ W, uint32_t* __restrict__ oH,
                             int K, int N, int Npad) {
    __shared__ uint32_t sh[64*33];
    const int KP = K >> 1;
    const int n0 = blockIdx.x * 64, kp0 = blockIdx.y * 32;
    const int tid = threadIdx.x;
    #pragma unroll
    for (int i = 0; i < 8; i++) {
        int f = tid + i*256;
        int n = f & 63, kp = f >> 6;
        int gn = n0 + n;
        float x0 = 0.f, x1 = 0.f;
        if (gn < N) {
            int k2 = (kp0 + kp) * 2;
            x0 = W[(size_t)k2*N + gn];
            x1 = W[(size_t)(k2 + 1)*N + gn];
        }
        sh[n*33 + kp] = hpack1(x0, x1);
    }
    __syncthreads();
    #pragma unroll
    for (int i = 0; i < 8; i++) {
        int f = tid + i*256;
        int kp = f & 31, n = f >> 5;
        oH[(size_t)(n0 + n)*KP + kp0 + kp] = sh[n*33 + kp];
    }
}

// QKV weights straight from WQ/WK/WV [L,H,D,DK] -> [L][1536 n][256 kp] packed
__global__ void prepack_qkvw(const float* __restrict__ WQ,
                             const float* __restrict__ WK,
                             const float* __restrict__ WV) {
    __shared__ uint32_t sh[64*33], sl[64*33];
    const int l = blockIdx.z;
    const int n0 = blockIdx.x*64, kp0 = blockIdx.y*32;
    const int tid = threadIdx.x;
    #pragma unroll
    for (int i = 0; i < 8; i++) {
        int f = tid + i*256;
        int n = f & 63, kp = f >> 6;
        int gn = n0 + n;
        int part = gn >> 9, hh = (gn >> 6) & 7, kk = gn & 63;
        const float* W = part == 0 ? WQ : (part == 1 ? WK : WV);
        size_t base = (((size_t)l*H_ + hh)*D_ + 2*(kp0 + kp))*DK_ + kk;
        uint32_t h, l2;
        hpack(W[base], W[base + DK_], h, l2);
        sh[n*33 + kp] = h;
        sl[n*33 + kp] = l2;
    }
    __syncthreads();
    #pragma unroll
    for (int i = 0; i < 8; i++) {
        int f = tid + i*256;
        int kp = f & 31, n = f >> 5;
        size_t go = (size_t)l*QKVW_*256 + (size_t)(n0 + n)*256 + kp0 + kp;
        g_wqkvH[go] = sh[n*33 + kp];
        g_wqkvL[go] = sl[n*33 + kp];
    }
}

// WO/FC1/FC2 for all layers, z = type*L + l
__global__ void prepack_small(const float* __restrict__ WO,
                              const float* __restrict__ F1,
                              const float* __restrict__ F2) {
    __shared__ uint32_t sh[64*33], sl[64*33];
    const int z = blockIdx.z;
    const int type = z / L_, l = z % L_;
    int K, N; const float* W; uint32_t *oH, *oL;
    if (type == 0)      { K = D_;   N = D_;   W = WO + (size_t)l*D_*D_;    oH = g_woH  + (size_t)l*D_*256;   oL = g_woL  + (size_t)l*D_*256; }
    else if (type == 1) { K = D_;   N = DFF_; W = F1 + (size_t)l*D_*DFF_;  oH = g_fc1H + (size_t)l*DFF_*256; oL = g_fc1L + (size_t)l*DFF_*256; }
    else                { K = DFF_; N = D_;   W = F2 + (size_t)l*DFF_*D_;  oH = g_fc2H + (size_t)l*D_*1024;  oL = g_fc2L + (size_t)l*D_*1024; }
    const int KP = K >> 1;
    const int n0 = blockIdx.x*64, kp0 = blockIdx.y*32;
    if (n0 >= N || kp0 >= KP) return;
    const int tid = threadIdx.x;
    #pragma unroll
    for (int i = 0; i < 8; i++) {
        int f = tid + i*256;
        int n = f & 63, kp = f >> 6;
        int k2 = (kp0 + kp)*2;
        uint32_t h, l2;
        hpack(W[(size_t)k2*N + n0 + n], W[(size_t)(k2+1)*N + n0 + n], h, l2);
        sh[n*33 + kp] = h;
        sl[n*33 + kp] = l2;
    }
    __syncthreads();
    #pragma unroll
    for (int i = 0; i < 8; i++) {
        int f = tid + i*256;
        int kp = f & 31, n = f >> 5;
        size_t go = (size_t)(n0 + n)*KP + kp0 + kp;
        oH[go] = sh[n*33 + kp];
        oL[go] = sl[n*33 + kp];
    }
}

// ============== fp16-split mma.sync GEMM, cp.async double-buffered =============
// OUT: 0 fp32 C, 1 packed hi/lo, 2 qkv-mode (c<1024 packed Q/K, else fp32 V)
// BPASS: 3 = A,B split (3 MMA); 2 = A split, B single (2 MMA); 1 = both single.
// BPASS==1 also swaps grid dims (bm from x) for L2 B-reuse on huge-N GEMMs.
#define AU 20

template<int OUT, int EPI, bool GUARD, int NI, int BPASS>
__global__ void __launch_bounds__(256, 2)
gemm_pk(int M, int N, int K,
        const uint32_t* __restrict__ aH, const uint32_t* __restrict__ aL,
        const uint32_t* __restrict__ bH, const uint32_t* __restrict__ bL,
        float* __restrict__ C, int ldc,
        uint32_t* __restrict__ oH, uint32_t* __restrict__ oL,
        const float* __restrict__ bias)
{
    constexpr int NTILE = 32*NI;
    constexpr int ABUFS = (BPASS >= 2) ? 4 : 2;   // A hi(2) [+ lo(2)]
    extern __shared__ uint32_t su[];
    uint32_t* AsH = su;
    uint32_t* AsL = su + 2*128*AU;              // used when BPASS>=2
    uint32_t* BsH = su + ABUFS*128*AU;
    uint32_t* BsL = BsH + 2*NTILE*AU;           // used when BPASS==3
    const uint32_t sb = (uint32_t)__cvta_generic_to_shared(su);
    const uint32_t sbAH = sb;
    const uint32_t sbAL = sb + 2*128*AU*4;
    const uint32_t sbBH = sb + ABUFS*128*AU*4;
    const uint32_t sbBL = sbBH + 2*NTILE*AU*4;

    const int KP   = K >> 1;
    const int tid  = threadIdx.x;
    const int wid  = tid >> 5, lane = tid & 31;
    const int g    = lane >> 2, t = lane & 3;
    const int bm   = (BPASS == 1 ? blockIdx.x : blockIdx.y) * 128;
    const int bn   = (BPASS == 1 ? blockIdx.y : blockIdx.x) * NTILE;
    const int m0   = (wid >> 2) * 64, n0 = (wid & 3) * (8*NI);

    float c[4][NI][4];
    #pragma unroll
    for (int mi = 0; mi < 4; mi++)
        #pragma unroll
        for (int ni = 0; ni < NI; ni++)
            #pragma unroll
            for (int j = 0; j < 4; j++) c[mi][ni][j] = 0.f;

    const int NKT = K >> 5;

    auto load_tile = [&](int kt, int pb) {
        const int kp0 = kt << 4;
        #pragma unroll
        for (int i = 0; i < 2; i++) {
            int f = tid + i*256;
            int r = f >> 2, cc = (f & 3) << 2;
            size_t go = (size_t)(bm + r)*KP + kp0 + cc;
            uint32_t so = (uint32_t)((pb*128 + r)*AU + cc)*4;
            cpa16(sbAH + so, aH + go);
            if (BPASS >= 2) cpa16(sbAL + so, aL + go);
        }
        #pragma unroll
        for (int i = 0; i < NI/2; i++) {
            int f = tid + i*256;
            int n = f >> 2, cc = (f & 3) << 2;
            size_t go = (size_t)(bn + n)*KP + kp0 + cc;
            uint32_t so = (uint32_t)((pb*NTILE + n)*AU + cc)*4;
            cpa16(sbBH + so, bH + go);
            if (BPASS == 3) cpa16(sbBL + so, bL + go);
        }
        CP_COMMIT();
    };

    load_tile(0, 0);

    for (int kt = 0; kt < NKT; kt++) {
        const int pb = kt & 1;
        if (kt + 1 < NKT) {
            load_tile(kt + 1, pb ^ 1);
            asm volatile("cp.async.wait_group 1;" ::: "memory");
        } else {
            asm volatile("cp.async.wait_group 0;" ::: "memory");
        }
        __syncthreads();

        const uint32_t* ah_b = AsH + pb*128*AU;
        const uint32_t* al_b = AsL + pb*128*AU;
        const uint32_t* bh_b = BsH + pb*NTILE*AU;
        const uint32_t* bl_b = BsL + pb*NTILE*AU;

        #pragma unroll
        for (int ks = 0; ks < 2; ks++) {
            const int kb = ks*8;
            uint32_t bh[NI][2], bl[NI][2];
            #pragma unroll
            for (int ni = 0; ni < NI; ni++) {
                int col = (n0 + ni*8 + g)*AU + kb;
                bh[ni][0] = bh_b[col + t];
                bh[ni][1] = bh_b[col + t + 4];
                if (BPASS == 3) {
                    bl[ni][0] = bl_b[col + t];
                    bl[ni][1] = bl_b[col + t + 4];
                }
            }
            #pragma unroll
            for (int mi = 0; mi < 4; mi++) {
                int row = m0 + mi*16 + g;
                uint32_t ah[4], al[4];
                ah[0] = ah_b[(row    )*AU + kb + t];
                ah[1] = ah_b[(row + 8)*AU + kb + t];
                ah[2] = ah_b[(row    )*AU + kb + t + 4];
                ah[3] = ah_b[(row + 8)*AU + kb + t + 4];
                if (BPASS >= 2) {
                    al[0] = al_b[(row    )*AU + kb + t];
                    al[1] = al_b[(row + 8)*AU + kb + t];
                    al[2] = al_b[(row    )*AU + kb + t + 4];
                    al[3] = al_b[(row + 8)*AU + kb + t + 4];
                }
                #pragma unroll
                for (int ni = 0; ni < NI; ni++) {
                    MMA16(c[mi][ni], ah, bh[ni]);
                    if (BPASS == 3) MMA16(c[mi][ni], ah, bl[ni]);
                    if (BPASS >= 2) MMA16(c[mi][ni], al, bh[ni]);
                }
            }
        }
        __syncthreads();
    }

    const int KP2 = (OUT == 2) ? 512 : (N >> 1);
    #pragma unroll
    for (int mi = 0; mi < 4; mi++) {
        const int r0 = bm + m0 + mi*16 + g;
        #pragma unroll
        for (int ni = 0; ni < NI; ni++) {
            const int c0 = bn + n0 + ni*8 + t*2;
            #pragma unroll
            for (int half = 0; half < 2; half++) {
                const int gr = r0 + half*8;
                float v0 = c[mi][ni][2*half + 0];
                float v1 = c[mi][ni][2*half + 1];
                if (EPI >= 1) { v0 += bias[c0]; v1 += bias[c0 + 1]; }
                if (EPI == 2) {
                    v0 = 0.5f*v0*(1.f + erff(v0*0.70710678118654752f));
                    v1 = 0.5f*v1*(1.f + erff(v1*0.70710678118654752f));
                }
                if (OUT == 0) {
                    if (!GUARD || c0 < N)     C[(size_t)gr*ldc + c0]     = v0;
                    if (!GUARD || c0 + 1 < N) C[(size_t)gr*ldc + c0 + 1] = v1;
                } else if (OUT == 1) {
                    uint32_t h, l;
                    hpack(v0, v1, h, l);
                    oH[(size_t)gr*KP2 + (c0 >> 1)] = h;
                    oL[(size_t)gr*KP2 + (c0 >> 1)] = l;
                } else {
                    if (c0 < 1024) {
                        uint32_t h, l;
                        hpack(v0, v1, h, l);
                        oH[(size_t)gr*512 + (c0 >> 1)] = h;
                        oL[(size_t)gr*512 + (c0 >> 1)] = l;
                    } else {
                        C[(size_t)gr*512 + (c0 - 1024)]     = v0;
                        C[(size_t)gr*512 + (c0 - 1024) + 1] = v1;
                    }
                }
            }
        }
    }
}

// ---------------- embedding -----------------------------------------------------
__global__ void embed_kernel(const int* __restrict__ ids,
                             const float* __restrict__ tok,
                             const float* __restrict__ pos) {
    const int row = blockIdx.x;
    const int t   = row % T_;
    const int id  = ids[row];
    const int tid = threadIdx.x;
    const float sc = 22.62741699796952f;
    const int d = tid*2;
    float e0 = (id == PAD_) ? 0.f : tok[(size_t)id*D_ + d];
    float e1 = (id == PAD_) ? 0.f : tok[(size_t)id*D_ + d + 1];
    float v0 = e0*sc + pos[(size_t)t*D_ + d];
    float v1 = e1*sc + pos[(size_t)t*D_ + d + 1];
    *reinterpret_cast<float2*>(g_x + (size_t)row*D_ + d) = make_float2(v0, v1);
    uint32_t h, l;
    hpack(v0, v1, h, l);
    g_xH[row*256 + tid] = h;
    g_xL[row*256 + tid] = l;
}

// ================ fattn2: tensor-core fp16x3 flash attention ===================
#define FA2_SMEM (6*2304*4)   // 55296 bytes

__device__ __forceinline__ void fa2_tile(
    uint32_t* QH, uint32_t* QL, uint32_t* KH, uint32_t* KL,
    uint32_t* VH, uint32_t* VL, uint32_t sbase,
    int qb, int b, int h, int tid)
{
    const int w = tid >> 5, lane = tid & 31;
    const int g = lane >> 2, t = lane & 3;
    const int mr = w*16;
    const uint32_t sQH = sbase, sQL = sbase + 9216;
    const uint32_t sKH = sbase + 18432, sKL = sbase + 27648;

    #pragma unroll
    for (int i = 0; i < 4; i++) {
        int idx = tid + i*128;
        int r = idx >> 3, c4 = (idx & 7) << 2;
        size_t go = ((size_t)(b*1024 + qb*64 + r) << 9) + h*32 + c4;
        cpa16(sQH + (uint32_t)(r*36 + c4)*4, g_qkpH + go);
        cpa16(sQL + (uint32_t)(r*36 + c4)*4, g_qkpL + go);
    }
    CP_COMMIT();

    float m0 = -CUDART_INF_F, m1 = -CUDART_INF_F, l0 = 0.f, l1 = 0.f;
    float o[8][4];
    #pragma unroll
    for (int nb = 0; nb < 8; nb++)
        #pragma unroll
        for (int j = 0; j < 4; j++) o[nb][j] = 0.f;

    const int nkt = qb + 1;
    for (int kt = 0; kt < nkt; kt++) {
        __syncthreads();
        #pragma unroll
        for (int i = 0; i < 4; i++) {
            int idx = tid + i*128;
            int r = idx >> 3, c4 = (idx & 7) << 2;
            size_t go = ((size_t)(b*1024 + kt*64 + r) << 9) + 256 + h*32 + c4;
            cpa16(sKH + (uint32_t)(r*36 + c4)*4, g_qkpH + go);
            cpa16(sKL + (uint32_t)(r*36 + c4)*4, g_qkpL + go);
        }
        CP_COMMIT();
        #pragma unroll
        for (int i = 0; i < 16; i++) {
            int idx = tid + i*128;
            int n = idx & 63, r = idx >> 6;
            size_t base = ((size_t)(b*1024 + kt*64 + 2*r) << 9) + h*64 + n;
            uint32_t hh, ll;
            hpack(g_v[base], g_v[base + 512], hh, ll);
            VH[n*36 + r] = hh;
            VL[n*36 + r] = ll;
        }
        asm volatile("cp.async.wait_group 0;" ::: "memory");
        __syncthreads();

        float sc[8][4];
        #pragma unroll
        for (int ni = 0; ni < 8; ni++)
            #pragma unroll
            for (int j = 0; j < 4; j++) sc[ni][j] = 0.f;
        #pragma unroll
        for (int j = 0; j < 4; j++) {
            uint32_t ah[4], al[4];
            int rb = (mr + g)*36 + j*8 + t;
            ah[0] = QH[rb];            al[0] = QL[rb];
            ah[1] = QH[rb + 8*36];     al[1] = QL[rb + 8*36];
            ah[2] = QH[rb + 4];        al[2] = QL[rb + 4];
            ah[3] = QH[rb + 8*36 + 4]; al[3] = QL[rb + 8*36 + 4];
            #pragma unroll
            for (int ni = 0; ni < 8; ni++) {
                uint32_t bh2[2], bl2[2];
                int cb = (ni*8 + g)*36 + j*8 + t;
                bh2[0] = KH[cb]; bh2[1] = KH[cb + 4];
                bl2[0] = KL[cb]; bl2[1] = KL[cb + 4];
                MMA16(sc[ni], ah, bh2);
                MMA16(sc[ni], ah, bl2);
                MMA16(sc[ni], al, bh2);
            }
        }
        const int qr0 = qb*64 + mr + g;
        const bool diag = (kt == qb);
        #pragma unroll
        for (int ni = 0; ni < 8; ni++)
            #pragma unroll
            for (int cc = 0; cc < 4; cc++) {
                float v = sc[ni][cc]*0.125f;
                if (diag) {
                    int key = kt*64 + ni*8 + 2*t + (cc & 1);
                    int qr = qr0 + (cc >> 1)*8;
                    if (key > qr) v = -CUDART_INF_F;
                }
                sc[ni][cc] = v;
            }

        float mx0 = -CUDART_INF_F, mx1 = -CUDART_INF_F;
        #pragma unroll
        for (int ni = 0; ni < 8; ni++) {
            mx0 = fmaxf(mx0, fmaxf(sc[ni][0], sc[ni][1]));
            mx1 = fmaxf(mx1, fmaxf(sc[ni][2], sc[ni][3]));
        }
        mx0 = fmaxf(mx0, __shfl_xor_sync(0xffffffffu, mx0, 1));
        mx0 = fmaxf(mx0, __shfl_xor_sync(0xffffffffu, mx0, 2));
        mx1 = fmaxf(mx1, __shfl_xor_sync(0xffffffffu, mx1, 1));
        mx1 = fmaxf(mx1, __shfl_xor_sync(0xffffffffu, mx1, 2));
        const float mn0 = fmaxf(m0, mx0), mn1 = fmaxf(m1, mx1);
        const float cr0 = fexp(m0 - mn0),  cr1 = fexp(m1 - mn1);
        float s0 = 0.f, s1 = 0.f;
        #pragma unroll
        for (int ni = 0; ni < 8; ni++) {
            float p0 = fexp(sc[ni][0] - mn0);
            float p1 = fexp(sc[ni][1] - mn0);
            float p2 = fexp(sc[ni][2] - mn1);
            float p3 = fexp(sc[ni][3] - mn1);
            sc[ni][0] = p0; sc[ni][1] = p1; sc[ni][2] = p2; sc[ni][3] = p3;
            s0 += p0 + p1; s1 += p2 + p3;
        }
        s0 += __shfl_xor_sync(0xffffffffu, s0, 1);
        s0 += __shfl_xor_sync(0xffffffffu, s0, 2);
        s1 += __shfl_xor_sync(0xffffffffu, s1, 1);
        s1 += __shfl_xor_sync(0xffffffffu, s1, 2);
        l0 = l0*cr0 + s0; l1 = l1*cr1 + s1;
        m0 = mn0; m1 = mn1;
        #pragma unroll
        for (int nb = 0; nb < 8; nb++) {
            o[nb][0] *= cr0; o[nb][1] *= cr0;
            o[nb][2] *= cr1; o[nb][3] *= cr1;
        }

        #pragma unroll
        for (int jj = 0; jj < 4; jj++) {
            uint32_t ah[4], al[4];
            hpack(sc[2*jj][0],   sc[2*jj][1],   ah[0], al[0]);
            hpack(sc[2*jj][2],   sc[2*jj][3],   ah[1], al[1]);
            hpack(sc[2*jj+1][0], sc[2*jj+1][1], ah[2], al[2]);
            hpack(sc[2*jj+1][2], sc[2*jj+1][3], ah[3], al[3]);
            #pragma unroll
            for (int nb = 0; nb < 8; nb++) {
                uint32_t bh2[2], bl2[2];
                int cb = (nb*8 + g)*36 + jj*8 + t;
                bh2[0] = VH[cb]; bh2[1] = VH[cb + 4];
                bl2[0] = VL[cb]; bl2[1] = VL[cb + 4];
                MMA16(o[nb], ah, bh2);
                MMA16(o[nb], ah, bl2);
                MMA16(o[nb], al, bh2);
            }
        }
    }

    const float inv0 = 1.f / l0, inv1 = 1.f / l1;
    const int gr0 = b*1024 + qb*64 + mr + g;
    #pragma unroll
    for (int nb = 0; nb < 8; nb++) {
        const int kp = h*32 + nb*4 + t;
        uint32_t hh, ll;
        hpack(o[nb][0]*inv0, o[nb][1]*inv0, hh, ll);
        g_cH[gr0*256 + kp] = hh;
        g_cL[gr0*256 + kp] = ll;
        hpack(o[nb][2]*inv1, o[nb][3]*inv1, hh, ll);
        g_cH[(gr0 + 8)*256 + kp] = hh;
        g_cL[(gr0 + 8)*256 + kp] = ll;
    }
}

__global__ void __launch_bounds__(128) fattn2_kernel() {
    extern __shared__ uint32_t fsm[];
    uint32_t* QH = fsm;
    uint32_t* QL = QH + 2304;
    uint32_t* KH = QL + 2304;
    uint32_t* KL = KH + 2304;
    uint32_t* VH = KL + 2304;
    uint32_t* VL = VH + 2304;
    const uint32_t sbase = (uint32_t)__cvta_generic_to_shared(fsm);

    const int p  = blockIdx.x;
    const int bh = blockIdx.y;
    const int b = bh >> 3, h = bh & 7;
    const int tid = threadIdx.x;

    fa2_tile(QH, QL, KH, KL, VH, VL, sbase, p,      b, h, tid);
    __syncthreads();
    fa2_tile(QH, QL, KH, KL, VH, VL, sbase, 15 - p, b, h, tid);
}

// ------------- fused residual add + LayerNorm -> fp32 x AND packed x -----------
__global__ void __launch_bounds__(256) add_ln_kernel(const float* __restrict__ g,
                                                     const float* __restrict__ bta) {
    const int row = blockIdx.x;
    float* x = g_x + (size_t)row*D_;
    const float* dl = g_tmp + (size_t)row*D_;
    const int tid = threadIdx.x;
    __shared__ float red[256];

    float2 xv = reinterpret_cast<const float2*>(x)[tid];
    float2 dv = reinterpret_cast<const float2*>(dl)[tid];
    float v0 = xv.x + dv.x;
    float v1 = xv.y + dv.y;

    red[tid] = v0 + v1; __syncthreads();
    for (int off = 128; off > 0; off >>= 1) {
        if (tid < off) red[tid] += red[tid + off];
        __syncthreads();
    }
    const float mu = red[0] * (1.f/512.f); __syncthreads();

    float d0 = v0 - mu, d1 = v1 - mu;
    red[tid] = d0*d0 + d1*d1; __syncthreads();
    for (int off = 128; off > 0; off >>= 1) {
        if (tid < off) red[tid] += red[tid + off];
        __syncthreads();
    }
    const float inv = rsqrtf(red[0]*(1.f/512.f) + 1e-5f);

    const int d = tid*2;
    float o0 = d0*inv*g[d]     + bta[d];
    float o1 = d1*inv*g[d + 1] + bta[d + 1];
    reinterpret_cast<float2*>(x)[tid] = make_float2(o0, o1);
    uint32_t h, l;
    hpack(o0, o1, h, l);
    g_xH[row*256 + tid] = h;
    g_xL[row*256 + tid] = l;
}

// ---------------- launch ---------------------------------------------------------
#define SMEM_NI4B3 ((4*128*AU + 4*128*AU)*4)   // 81920
#define SMEM_NI2B3 ((4*128*AU + 4*64*AU)*4)    // 61440
#define SMEM_NI4B2 ((4*128*AU + 2*128*AU)*4)   // 61440
#define SMEM_NI2B2 ((4*128*AU + 2*64*AU)*4)    // 51200
#define SMEM_NI4B1 ((2*128*AU + 2*128*AU)*4)   // 40960

extern "C" void kernel_launch(void* const* d_in, const int* in_sizes, int n_in,
                              void* d_out, int out_size) {
    const int*   ids  = (const int*)  d_in[0];
    const float* tok  = (const float*)d_in[1];
    const float* pos  = (const float*)d_in[2];
    const float* WQ   = (const float*)d_in[3];
    const float* WK   = (const float*)d_in[4];
    const float* WV   = (const float*)d_in[5];
    const float* WO   = (const float*)d_in[6];
    const float* ln1g = (const float*)d_in[7];
    const float* ln1b = (const float*)d_in[8];
    const float* fc1w = (const float*)d_in[9];
    const float* fc1b = (const float*)d_in[10];
    const float* fc2w = (const float*)d_in[11];
    const float* fc2b = (const float*)d_in[12];
    const float* ln2g = (const float*)d_in[13];
    const float* ln2b = (const float*)d_in[14];
    const float* lmh  = (const float*)d_in[15];
    float* out = (float*)d_out;

    float *pv, *ptmp;
    cudaGetSymbolAddress((void**)&pv,   g_v);
    cudaGetSymbolAddress((void**)&ptmp, g_tmp);

    uint32_t *xH, *xL, *cH, *cL, *fH, *fL, *qpH, *qpL;
    uint32_t *qkH, *qkL, *woH, *woL, *f1H, *f1L, *f2H, *f2L, *lmH;
    cudaGetSymbolAddress((void**)&xH,  g_xH);
    cudaGetSymbolAddress((void**)&xL,  g_xL);
    cudaGetSymbolAddress((void**)&cH,  g_cH);
    cudaGetSymbolAddress((void**)&cL,  g_cL);
    cudaGetSymbolAddress((void**)&fH,  g_fH);
    cudaGetSymbolAddress((void**)&fL,  g_fL);
    cudaGetSymbolAddress((void**)&qpH, g_qkpH);
    cudaGetSymbolAddress((void**)&qpL, g_qkpL);
    cudaGetSymbolAddress((void**)&qkH, g_wqkvH);
    cudaGetSymbolAddress((void**)&qkL, g_wqkvL);
    cudaGetSymbolAddress((void**)&woH, g_woH);
    cudaGetSymbolAddress((void**)&woL, g_woL);
    cudaGetSymbolAddress((void**)&f1H, g_fc1H);
    cudaGetSymbolAddress((void**)&f1L, g_fc1L);
    cudaGetSymbolAddress((void**)&f2H, g_fc2H);
    cudaGetSymbolAddress((void**)&f2L, g_fc2L);
    cudaGetSymbolAddress((void**)&lmH, g_lmhH);

    cudaFuncSetAttribute((const void*)fattn2_kernel,          cudaFuncAttributeMaxDynamicSharedMemorySize, FA2_SMEM);
    cudaFuncSetAttribute((const void*)gemm_pk<2,0,false,4,3>, cudaFuncAttributeMaxDynamicSharedMemorySize, SMEM_NI4B3);
    cudaFuncSetAttribute((const void*)gemm_pk<0,0,false,2,3>, cudaFuncAttributeMaxDynamicSharedMemorySize, SMEM_NI2B3);
    cudaFuncSetAttribute((const void*)gemm_pk<1,2,false,4,2>, cudaFuncAttributeMaxDynamicSharedMemorySize, SMEM_NI4B2);
    cudaFuncSetAttribute((const void*)gemm_pk<0,1,false,2,2>, cudaFuncAttributeMaxDynamicSharedMemorySize, SMEM_NI2B2);
    cudaFuncSetAttribute((const void*)gemm_pk<0,0,true,4,1>,  cudaFuncAttributeMaxDynamicSharedMemorySize, SMEM_NI4B1);

    embed_kernel<<<BT_, 256>>>(ids, tok, pos);
    prepack_small<<<dim3(32, 32, 3*L_), 256>>>(WO, fc1w, fc2w);
    prepack_qkvw<<<dim3(QKVW_/64, 8, L_), 256>>>(WQ, WK, WV);
    prepack_b_hi<<<dim3(VP_/64, 8), 256>>>(lmh, lmH, D_, V_, VP_);

    for (int l = 0; l < L_; l++) {
        gemm_pk<2,0,false,4,3><<<dim3(QKVW_/128, BT_/128), 256, SMEM_NI4B3>>>(
            BT_, QKVW_, D_, xH, xL,
            qkH + (size_t)l*QKVW_*256, qkL + (size_t)l*QKVW_*256,
            pv, 512, qpH, qpL, nullptr);

        fattn2_kernel<<<dim3(8, B_*H_), 128, FA2_SMEM>>>();

        gemm_pk<0,0,false,2,3><<<dim3(D_/64, BT_/128), 256, SMEM_NI2B3>>>(
            BT_, D_, D_, cH, cL,
            woH + (size_t)l*D_*256, woL + (size_t)l*D_*256,
            ptmp, D_, nullptr, nullptr, nullptr);

        add_ln_kernel<<<BT_, 256>>>(ln1g + l*D_, ln1b + l*D_);

        // FC1: fp16x2 (A split, B single-rounded weight)
        gemm_pk<1,2,false,4,2><<<dim3(DFF_/128, BT_/128), 256, SMEM_NI4B2>>>(
            BT_, DFF_, D_, xH, xL,
            f1H + (size_t)l*DFF_*256, nullptr,
            nullptr, 0, fH, fL, fc1b + l*DFF_);

        // FC2: fp16x2
        gemm_pk<0,1,false,2,2><<<dim3(D_/64, BT_/128), 256, SMEM_NI2B2>>>(
            BT_, D_, DFF_, fH, fL,
            f2H + (size_t)l*D_*1024, nullptr,
            ptmp, D_, nullptr, nullptr, fc2b + l*D_);

        add_ln_kernel<<<BT_, 256>>>(ln2g + l*D_, ln2b + l*D_);
    }

    // lm_head: fp16x1, grid swapped (M fast) so a wave holds all 16 M-tiles -> 16x B L2-reuse
    gemm_pk<0,0,true,4,1><<<dim3(BT_/128, VP_/128), 256, SMEM_NI4B1>>>(
        BT_, V_, D_, xH, nullptr, lmH, nullptr, out, V_, nullptr, nullptr, nullptr);
}

// round 13
// speedup vs baseline: 4.8648x; 1.0939x over previous
#include <cuda_runtime.h>
#include <cuda_fp16.h>
#include <math.h>
#include <math_constants.h>
#include <stdint.h>

#define B_   2
#define T_   1024
#define D_   512
#define H_   8
#define DK_  64
#define DFF_ 2048
#define L_   6
#define V_   50257
#define VP_  50304   // V padded to 128
#define PAD_ 50256
#define BT_  (B_*T_)
#define QKVW_ (3*D_)   // 1536

// ---------------- scratch (device globals; no allocations allowed) ----------
__device__ float g_x[BT_*D_];
__device__ float g_v[BT_*D_];                          // V fp32 (per layer)
__device__ float g_tmp[BT_*D_];

// packed fp16 hi/lo activation buffers (u32 = half2 of adjacent k)
__device__ uint32_t g_xH[BT_*256],  g_xL[BT_*256];     // x packed (K=512)
__device__ uint32_t g_cH[BT_*256],  g_cL[BT_*256];     // ctx packed
__device__ uint32_t g_fH[BT_*1024], g_fL[BT_*1024];    // ffn hidden packed
__device__ uint32_t g_qkpH[BT_*512], g_qkpL[BT_*512];  // Q,K packed (512 pairs/row)
// packed weights (hi only — all weight operands are single-pass fp16 now)
__device__ uint32_t g_wqkvH[L_*QKVW_*256];
__device__ uint32_t g_woH[L_*D_*256];
__device__ uint32_t g_fc1H[L_*DFF_*256];
__device__ uint32_t g_fc2H[L_*D_*1024];
__device__ uint32_t g_lmhH[(size_t)VP_*256];

// ---------------- helpers ------------------------------------------------------
__device__ __forceinline__ void hpack(float x0, float x1, uint32_t& hi, uint32_t& lo) {
    __half h0 = __float2half_rn(x0);
    __half h1 = __float2half_rn(x1);
    __half l0 = __float2half_rn(x0 - __half2float(h0));
    __half l1 = __float2half_rn(x1 - __half2float(h1));
    hi = ((uint32_t)__half_as_ushort(h1) << 16) | (uint32_t)__half_as_ushort(h0);
    lo = ((uint32_t)__half_as_ushort(l1) << 16) | (uint32_t)__half_as_ushort(l0);
}
__device__ __forceinline__ uint32_t hpack1(float x0, float x1) {
    return ((uint32_t)__half_as_ushort(__float2half_rn(x1)) << 16)
         |  (uint32_t)__half_as_ushort(__float2half_rn(x0));
}

// fast exp on the FMA pipe (arg <= 0 path; clamps; ~2e-8 rel err)
__device__ __forceinline__ float fexp(float x) {
    x = fmaxf(x, -87.0f);
    float t = fmaf(x, 1.4426950408889634f, 12582912.0f);
    float r = t - 12582912.0f;
    float f = fmaf(x, 1.4426950408889634f, -r);
    float p =        1.3333558e-3f;
    p = fmaf(p, f, 9.6181291e-3f);
    p = fmaf(p, f, 5.5504109e-2f);
    p = fmaf(p, f, 2.4022651e-1f);
    p = fmaf(p, f, 6.9314718e-1f);
    p = fmaf(p, f, 1.0f);
    int e = (__float_as_int(t) + 127) << 23;
    return p * __int_as_float(e);
}

#define MMA16(cc, a, b) \
    asm volatile("mma.sync.aligned.m16n8k16.row.col.f32.f16.f16.f32 " \
        "{%0,%1,%2,%3}, {%4,%5,%6,%7}, {%8,%9}, {%0,%1,%2,%3};" \
        : "+f"((cc)[0]), "+f"((cc)[1]), "+f"((cc)[2]), "+f"((cc)[3]) \
        : "r"((a)[0]), "r"((a)[1]), "r"((a)[2]), "r"((a)[3]), \
          "r"((b)[0]), "r"((b)[1]))

__device__ __forceinline__ void cpa16(uint32_t dst, const void* src) {
    asm volatile("cp.async.cg.shared.global [%0], [%1], 16;" :: "r"(dst), "l"(src));
}
#define CP_COMMIT() asm volatile("cp.async.commit_group;" ::: "memory")

// ================ prepack kernels (coalesced transpose, hi-only) ===============
// generic: W fp32 [K][N] -> [Npad][K/2] single fp16
__global__ void prepack_b_hi(const float* __restrict__ W, uint32_t* __restrict__ oH,
                             int K, int N, int Npad) {
    __shared__ uint32_t sh[64*33];
    const int KP = K >> 1;
    const int n0 = blockIdx.x * 64, kp0 = blockIdx.y * 32;
    const int tid = threadIdx.x;
    #pragma unroll
    for (int i = 0; i < 8; i++) {
        int f = tid + i*256;
        int n = f & 63, kp = f >> 6;
        int gn = n0 + n;
        float x0 = 0.f, x1 = 0.f;
        if (gn < N) {
            int k2 = (kp0 + kp) * 2;
            x0 = W[(size_t)k2*N + gn];
            x1 = W[(size_t)(k2 + 1)*N + gn];
        }
        sh[n*33 + kp] = hpack1(x0, x1);
    }
    __syncthreads();
    #pragma unroll
    for (int i = 0; i < 8; i++) {
        int f = tid + i*256;
        int kp = f & 31, n = f >> 5;
        oH[(size_t)(n0 + n)*KP + kp0 + kp] = sh[n*33 + kp];
    }
}

// QKV weights straight from WQ/WK/WV [L,H,D,DK] -> [L][1536 n][256 kp], hi only
__global__ void prepack_qkvw(const float* __restrict__ WQ,
                             const float* __restrict__ WK,
                             const float* __restrict__ WV) {
    __shared__ uint32_t sh[64*33];
    const int l = blockIdx.z;
    const int n0 = blockIdx.x*64, kp0 = blockIdx.y*32;
    const int tid = threadIdx.x;
    #pragma unroll
    for (int i = 0; i < 8; i++) {
        int f = tid + i*256;
        int n = f & 63, kp = f >> 6;
        int gn = n0 + n;
        int part = gn >> 9, hh = (gn >> 6) & 7, kk = gn & 63;
        const float* W = part == 0 ? WQ : (part == 1 ? WK : WV);
        size_t base = (((size_t)l*H_ + hh)*D_ + 2*(kp0 + kp))*DK_ + kk;
        sh[n*33 + kp] = hpack1(W[base], W[base + DK_]);
    }
    __syncthreads();
    #pragma unroll
    for (int i = 0; i < 8; i++) {
        int f = tid + i*256;
        int kp = f & 31, n = f >> 5;
        g_wqkvH[(size_t)l*QKVW_*256 + (size_t)(n0 + n)*256 + kp0 + kp] = sh[n*33 + kp];
    }
}

// WO/FC1/FC2 for all layers, hi only, z = type*L + l
__global__ void prepack_small(const float* __restrict__ WO,
                              const float* __restrict__ F1,
                              const float* __restrict__ F2) {
    __shared__ uint32_t sh[64*33];
    const int z = blockIdx.z;
    const int type = z / L_, l = z % L_;
    int K, N; const float* W; uint32_t* oH;
    if (type == 0)      { K = D_;   N = D_;   W = WO + (size_t)l*D_*D_;   oH = g_woH  + (size_t)l*D_*256; }
    else if (type == 1) { K = D_;   N = DFF_; W = F1 + (size_t)l*D_*DFF_; oH = g_fc1H + (size_t)l*DFF_*256; }
    else                { K = DFF_; N = D_;   W = F2 + (size_t)l*DFF_*D_; oH = g_fc2H + (size_t)l*D_*1024; }
    const int KP = K >> 1;
    const int n0 = blockIdx.x*64, kp0 = blockIdx.y*32;
    if (n0 >= N || kp0 >= KP) return;
    const int tid = threadIdx.x;
    #pragma unroll
    for (int i = 0; i < 8; i++) {
        int f = tid + i*256;
        int n = f & 63, kp = f >> 6;
        int k2 = (kp0 + kp)*2;
        sh[n*33 + kp] = hpack1(W[(size_t)k2*N + n0 + n], W[(size_t)(k2+1)*N + n0 + n]);
    }
    __syncthreads();
    #pragma unroll
    for (int i = 0; i < 8; i++) {
        int f = tid + i*256;
        int kp = f & 31, n = f >> 5;
        oH[(size_t)(n0 + n)*KP + kp0 + kp] = sh[n*33 + kp];
    }
}

// ============== fp16-split mma.sync GEMM, cp.async double-buffered =============
// OUT: 0 fp32 C, 1 packed hi/lo, 2 qkv-mode (c<1024 packed Q/K, else fp32 V)
// BPASS: 2 = A split, B single (2 MMA); 1 = both single (1 MMA).
// BPASS==1 swaps grid dims (bm from x) for L2 B-reuse on huge-N GEMMs.
#define AU 20

template<int OUT, int EPI, bool GUARD, int NI, int BPASS>
__global__ void __launch_bounds__(256, 2)
gemm_pk(int M, int N, int K,
        const uint32_t* __restrict__ aH, const uint32_t* __restrict__ aL,
        const uint32_t* __restrict__ bH,
        float* __restrict__ C, int ldc,
        uint32_t* __restrict__ oH, uint32_t* __restrict__ oL,
        const float* __restrict__ bias)
{
    constexpr int NTILE = 32*NI;
    constexpr int ABUFS = (BPASS >= 2) ? 4 : 2;
    extern __shared__ uint32_t su[];
    uint32_t* AsH = su;
    uint32_t* AsL = su + 2*128*AU;
    uint32_t* BsH = su + ABUFS*128*AU;
    const uint32_t sb = (uint32_t)__cvta_generic_to_shared(su);
    const uint32_t sbAH = sb;
    const uint32_t sbAL = sb + 2*128*AU*4;
    const uint32_t sbBH = sb + ABUFS*128*AU*4;

    const int KP   = K >> 1;
    const int tid  = threadIdx.x;
    const int wid  = tid >> 5, lane = tid & 31;
    const int g    = lane >> 2, t = lane & 3;
    const int bm   = (BPASS == 1 ? blockIdx.x : blockIdx.y) * 128;
    const int bn   = (BPASS == 1 ? blockIdx.y : blockIdx.x) * NTILE;
    const int m0   = (wid >> 2) * 64, n0 = (wid & 3) * (8*NI);

    float c[4][NI][4];
    #pragma unroll
    for (int mi = 0; mi < 4; mi++)
        #pragma unroll
        for (int ni = 0; ni < NI; ni++)
            #pragma unroll
            for (int j = 0; j < 4; j++) c[mi][ni][j] = 0.f;

    const int NKT = K >> 5;

    auto load_tile = [&](int kt, int pb) {
        const int kp0 = kt << 4;
        #pragma unroll
        for (int i = 0; i < 2; i++) {
            int f = tid + i*256;
            int r = f >> 2, cc = (f & 3) << 2;
            size_t go = (size_t)(bm + r)*KP + kp0 + cc;
            uint32_t so = (uint32_t)((pb*128 + r)*AU + cc)*4;
            cpa16(sbAH + so, aH + go);
            if (BPASS >= 2) cpa16(sbAL + so, aL + go);
        }
        #pragma unroll
        for (int i = 0; i < NI/2; i++) {
            int f = tid + i*256;
            int n = f >> 2, cc = (f & 3) << 2;
            size_t go = (size_t)(bn + n)*KP + kp0 + cc;
            uint32_t so = (uint32_t)((pb*NTILE + n)*AU + cc)*4;
            cpa16(sbBH + so, bH + go);
        }
        CP_COMMIT();
    };

    load_tile(0, 0);

    for (int kt = 0; kt < NKT; kt++) {
        const int pb = kt & 1;
        if (kt + 1 < NKT) {
            load_tile(kt + 1, pb ^ 1);
            asm volatile("cp.async.wait_group 1;" ::: "memory");
        } else {
            asm volatile("cp.async.wait_group 0;" ::: "memory");
        }
        __syncthreads();

        const uint32_t* ah_b = AsH + pb*128*AU;
        const uint32_t* al_b = AsL + pb*128*AU;
        const uint32_t* bh_b = BsH + pb*NTILE*AU;

        #pragma unroll
        for (int ks = 0; ks < 2; ks++) {
            const int kb = ks*8;
            uint32_t bh[NI][2];
            #pragma unroll
            for (int ni = 0; ni < NI; ni++) {
                int col = (n0 + ni*8 + g)*AU + kb;
                bh[ni][0] = bh_b[col + t];
                bh[ni][1] = bh_b[col + t + 4];
            }
            #pragma unroll
            for (int mi = 0; mi < 4; mi++) {
                int row = m0 + mi*16 + g;
                uint32_t ah[4], al[4];
                ah[0] = ah_b[(row    )*AU + kb + t];
                ah[1] = ah_b[(row + 8)*AU + kb + t];
                ah[2] = ah_b[(row    )*AU + kb + t + 4];
                ah[3] = ah_b[(row + 8)*AU + kb + t + 4];
                if (BPASS >= 2) {
                    al[0] = al_b[(row    )*AU + kb + t];
                    al[1] = al_b[(row + 8)*AU + kb + t];
                    al[2] = al_b[(row    )*AU + kb + t + 4];
                    al[3] = al_b[(row + 8)*AU + kb + t + 4];
                }
                #pragma unroll
                for (int ni = 0; ni < NI; ni++) {
                    MMA16(c[mi][ni], ah, bh[ni]);
                    if (BPASS >= 2) MMA16(c[mi][ni], al, bh[ni]);
                }
            }
        }
        __syncthreads();
    }

    const int KP2 = (OUT == 2) ? 512 : (N >> 1);
    #pragma unroll
    for (int mi = 0; mi < 4; mi++) {
        const int r0 = bm + m0 + mi*16 + g;
        #pragma unroll
        for (int ni = 0; ni < NI; ni++) {
            const int c0 = bn + n0 + ni*8 + t*2;
            #pragma unroll
            for (int half = 0; half < 2; half++) {
                const int gr = r0 + half*8;
                float v0 = c[mi][ni][2*half + 0];
                float v1 = c[mi][ni][2*half + 1];
                if (EPI >= 1) { v0 += bias[c0]; v1 += bias[c0 + 1]; }
                if (EPI == 2) {
                    v0 = 0.5f*v0*(1.f + erff(v0*0.70710678118654752f));
                    v1 = 0.5f*v1*(1.f + erff(v1*0.70710678118654752f));
                }
                if (OUT == 0) {
                    if (!GUARD || c0 < N)     C[(size_t)gr*ldc + c0]     = v0;
                    if (!GUARD || c0 + 1 < N) C[(size_t)gr*ldc + c0 + 1] = v1;
                } else if (OUT == 1) {
                    uint32_t h, l;
                    hpack(v0, v1, h, l);
                    oH[(size_t)gr*KP2 + (c0 >> 1)] = h;
                    oL[(size_t)gr*KP2 + (c0 >> 1)] = l;
                } else {
                    if (c0 < 1024) {
                        uint32_t h, l;
                        hpack(v0, v1, h, l);
                        oH[(size_t)gr*512 + (c0 >> 1)] = h;
                        oL[(size_t)gr*512 + (c0 >> 1)] = l;
                    } else {
                        C[(size_t)gr*512 + (c0 - 1024)]     = v0;
                        C[(size_t)gr*512 + (c0 - 1024) + 1] = v1;
                    }
                }
            }
        }
    }
}

// ---------------- embedding -----------------------------------------------------
__global__ void embed_kernel(const int* __restrict__ ids,
                             const float* __restrict__ tok,
                             const float* __restrict__ pos) {
    const int row = blockIdx.x;
    const int t   = row % T_;
    const int id  = ids[row];
    const int tid = threadIdx.x;
    const float sc = 22.62741699796952f;
    const int d = tid*2;
    float e0 = (id == PAD_) ? 0.f : tok[(size_t)id*D_ + d];
    float e1 = (id == PAD_) ? 0.f : tok[(size_t)id*D_ + d + 1];
    float v0 = e0*sc + pos[(size_t)t*D_ + d];
    float v1 = e1*sc + pos[(size_t)t*D_ + d + 1];
    *reinterpret_cast<float2*>(g_x + (size_t)row*D_ + d) = make_float2(v0, v1);
    uint32_t h, l;
    hpack(v0, v1, h, l);
    g_xH[row*256 + tid] = h;
    g_xL[row*256 + tid] = l;
}

// ================ fattn2: tensor-core fp16x2 flash attention ===================
// Q split (hi+lo), K single, V single. 4 warps, 64-row Q tiles, paired (p,15-p).
#define FA2_SMEM (4*2304*4)   // QH,QL,KH,VH = 36864 bytes

__device__ __forceinline__ void fa2_tile(
    uint32_t* QH, uint32_t* QL, uint32_t* KH, uint32_t* VH, uint32_t sbase,
    int qb, int b, int h, int tid)
{
    const int w = tid >> 5, lane = tid & 31;
    const int g = lane >> 2, t = lane & 3;
    const int mr = w*16;
    const uint32_t sQH = sbase, sQL = sbase + 9216;
    const uint32_t sKH = sbase + 18432;

    #pragma unroll
    for (int i = 0; i < 4; i++) {
        int idx = tid + i*128;
        int r = idx >> 3, c4 = (idx & 7) << 2;
        size_t go = ((size_t)(b*1024 + qb*64 + r) << 9) + h*32 + c4;
        cpa16(sQH + (uint32_t)(r*36 + c4)*4, g_qkpH + go);
        cpa16(sQL + (uint32_t)(r*36 + c4)*4, g_qkpL + go);
    }
    CP_COMMIT();

    float m0 = -CUDART_INF_F, m1 = -CUDART_INF_F, l0 = 0.f, l1 = 0.f;
    float o[8][4];
    #pragma unroll
    for (int nb = 0; nb < 8; nb++)
        #pragma unroll
        for (int j = 0; j < 4; j++) o[nb][j] = 0.f;

    const int nkt = qb + 1;
    for (int kt = 0; kt < nkt; kt++) {
        __syncthreads();
        #pragma unroll
        for (int i = 0; i < 4; i++) {
            int idx = tid + i*128;
            int r = idx >> 3, c4 = (idx & 7) << 2;
            size_t go = ((size_t)(b*1024 + kt*64 + r) << 9) + 256 + h*32 + c4;
            cpa16(sKH + (uint32_t)(r*36 + c4)*4, g_qkpH + go);
        }
        CP_COMMIT();
        #pragma unroll
        for (int i = 0; i < 16; i++) {
            int idx = tid + i*128;
            int n = idx & 63, r = idx >> 6;
            size_t base = ((size_t)(b*1024 + kt*64 + 2*r) << 9) + h*64 + n;
            VH[n*36 + r] = hpack1(g_v[base], g_v[base + 512]);
        }
        asm volatile("cp.async.wait_group 0;" ::: "memory");
        __syncthreads();

        // ---- S = Q K^T (Q split, K single: 2 MMA) ----
        float sc[8][4];
        #pragma unroll
        for (int ni = 0; ni < 8; ni++)
            #pragma unroll
            for (int j = 0; j < 4; j++) sc[ni][j] = 0.f;
        #pragma unroll
        for (int j = 0; j < 4; j++) {
            uint32_t ah[4], al[4];
            int rb = (mr + g)*36 + j*8 + t;
            ah[0] = QH[rb];            al[0] = QL[rb];
            ah[1] = QH[rb + 8*36];     al[1] = QL[rb + 8*36];
            ah[2] = QH[rb + 4];        al[2] = QL[rb + 4];
            ah[3] = QH[rb + 8*36 + 4]; al[3] = QL[rb + 8*36 + 4];
            #pragma unroll
            for (int ni = 0; ni < 8; ni++) {
                uint32_t bh2[2];
                int cb = (ni*8 + g)*36 + j*8 + t;
                bh2[0] = KH[cb]; bh2[1] = KH[cb + 4];
                MMA16(sc[ni], ah, bh2);
                MMA16(sc[ni], al, bh2);
            }
        }
        const int qr0 = qb*64 + mr + g;
        const bool diag = (kt == qb);
        #pragma unroll
        for (int ni = 0; ni < 8; ni++)
            #pragma unroll
            for (int cc = 0; cc < 4; cc++) {
                float v = sc[ni][cc]*0.125f;
                if (diag) {
                    int key = kt*64 + ni*8 + 2*t + (cc & 1);
                    int qr = qr0 + (cc >> 1)*8;
                    if (key > qr) v = -CUDART_INF_F;
                }
                sc[ni][cc] = v;
            }

        float mx0 = -CUDART_INF_F, mx1 = -CUDART_INF_F;
        #pragma unroll
        for (int ni = 0; ni < 8; ni++) {
            mx0 = fmaxf(mx0, fmaxf(sc[ni][0], sc[ni][1]));
            mx1 = fmaxf(mx1, fmaxf(sc[ni][2], sc[ni][3]));
        }
        mx0 = fmaxf(mx0, __shfl_xor_sync(0xffffffffu, mx0, 1));
        mx0 = fmaxf(mx0, __shfl_xor_sync(0xffffffffu, mx0, 2));
        mx1 = fmaxf(mx1, __shfl_xor_sync(0xffffffffu, mx1, 1));
        mx1 = fmaxf(mx1, __shfl_xor_sync(0xffffffffu, mx1, 2));
        const float mn0 = fmaxf(m0, mx0), mn1 = fmaxf(m1, mx1);
        const float cr0 = fexp(m0 - mn0),  cr1 = fexp(m1 - mn1);
        float s0 = 0.f, s1 = 0.f;
        #pragma unroll
        for (int ni = 0; ni < 8; ni++) {
            float p0 = fexp(sc[ni][0] - mn0);
            float p1 = fexp(sc[ni][1] - mn0);
            float p2 = fexp(sc[ni][2] - mn1);
            float p3 = fexp(sc[ni][3] - mn1);
            sc[ni][0] = p0; sc[ni][1] = p1; sc[ni][2] = p2; sc[ni][3] = p3;
            s0 += p0 + p1; s1 += p2 + p3;
        }
        s0 += __shfl_xor_sync(0xffffffffu, s0, 1);
        s0 += __shfl_xor_sync(0xffffffffu, s0, 2);
        s1 += __shfl_xor_sync(0xffffffffu, s1, 1);
        s1 += __shfl_xor_sync(0xffffffffu, s1, 2);
        l0 = l0*cr0 + s0; l1 = l1*cr1 + s1;
        m0 = mn0; m1 = mn1;
        #pragma unroll
        for (int nb = 0; nb < 8; nb++) {
            o[nb][0] *= cr0; o[nb][1] *= cr0;
            o[nb][2] *= cr1; o[nb][3] *= cr1;
        }

        // ---- O += P V (P split, V single: 2 MMA) ----
        #pragma unroll
        for (int jj = 0; jj < 4; jj++) {
            uint32_t ah[4], al[4];
            hpack(sc[2*jj][0],   sc[2*jj][1],   ah[0], al[0]);
            hpack(sc[2*jj][2],   sc[2*jj][3],   ah[1], al[1]);
            hpack(sc[2*jj+1][0], sc[2*jj+1][1], ah[2], al[2]);
            hpack(sc[2*jj+1][2], sc[2*jj+1][3], ah[3], al[3]);
            #pragma unroll
            for (int nb = 0; nb < 8; nb++) {
                uint32_t bh2[2];
                int cb = (nb*8 + g)*36 + jj*8 + t;
                bh2[0] = VH[cb]; bh2[1] = VH[cb + 4];
                MMA16(o[nb], ah, bh2);
                MMA16(o[nb], al, bh2);
            }
        }
    }

    const float inv0 = 1.f / l0, inv1 = 1.f / l1;
    const int gr0 = b*1024 + qb*64 + mr + g;
    #pragma unroll
    for (int nb = 0; nb < 8; nb++) {
        const int kp = h*32 + nb*4 + t;
        uint32_t hh, ll;
        hpack(o[nb][0]*inv0, o[nb][1]*inv0, hh, ll);
        g_cH[gr0*256 + kp] = hh;
        g_cL[gr0*256 + kp] = ll;
        hpack(o[nb][2]*inv1, o[nb][3]*inv1, hh, ll);
        g_cH[(gr0 + 8)*256 + kp] = hh;
        g_cL[(gr0 + 8)*256 + kp] = ll;
    }
}

__global__ void __launch_bounds__(128) fattn2_kernel() {
    extern __shared__ uint32_t fsm[];
    uint32_t* QH = fsm;
    uint32_t* QL = QH + 2304;
    uint32_t* KH = QL + 2304;
    uint32_t* VH = KH + 2304;
    const uint32_t sbase = (uint32_t)__cvta_generic_to_shared(fsm);

    const int p  = blockIdx.x;
    const int bh = blockIdx.y;
    const int b = bh >> 3, h = bh & 7;
    const int tid = threadIdx.x;

    fa2_tile(QH, QL, KH, VH, sbase, p,      b, h, tid);
    __syncthreads();
    fa2_tile(QH, QL, KH, VH, sbase, 15 - p, b, h, tid);
}

// ------------- fused residual add + LayerNorm -> fp32 x AND packed x -----------
__global__ void __launch_bounds__(256) add_ln_kernel(const float* __restrict__ g,
                                                     const float* __restrict__ bta) {
    const int row = blockIdx.x;
    float* x = g_x + (size_t)row*D_;
    const float* dl = g_tmp + (size_t)row*D_;
    const int tid = threadIdx.x;
    __shared__ float red[256];

    float2 xv = reinterpret_cast<const float2*>(x)[tid];
    float2 dv = reinterpret_cast<const float2*>(dl)[tid];
    float v0 = xv.x + dv.x;
    float v1 = xv.y + dv.y;

    red[tid] = v0 + v1; __syncthreads();
    for (int off = 128; off > 0; off >>= 1) {
        if (tid < off) red[tid] += red[tid + off];
        __syncthreads();
    }
    const float mu = red[0] * (1.f/512.f); __syncthreads();

    float d0 = v0 - mu, d1 = v1 - mu;
    red[tid] = d0*d0 + d1*d1; __syncthreads();
    for (int off = 128; off > 0; off >>= 1) {
        if (tid < off) red[tid] += red[tid + off];
        __syncthreads();
    }
    const float inv = rsqrtf(red[0]*(1.f/512.f) + 1e-5f);

    const int d = tid*2;
    float o0 = d0*inv*g[d]     + bta[d];
    float o1 = d1*inv*g[d + 1] + bta[d + 1];
    reinterpret_cast<float2*>(x)[tid] = make_float2(o0, o1);
    uint32_t h, l;
    hpack(o0, o1, h, l);
    g_xH[row*256 + tid] = h;
    g_xL[row*256 + tid] = l;
}

// ---------------- launch ---------------------------------------------------------
#define SMEM_NI4B2 ((4*128*AU + 2*128*AU)*4)   // 61440
#define SMEM_NI2B2 ((4*128*AU + 2*64*AU)*4)    // 51200
#define SMEM_NI4B1 ((2*128*AU + 2*128*AU)*4)   // 40960

extern "C" void kernel_launch(void* const* d_in, const int* in_sizes, int n_in,
                              void* d_out, int out_size) {
    const int*   ids  = (const int*)  d_in[0];
    const float* tok  = (const float*)d_in[1];
    const float* pos  = (const float*)d_in[2];
    const float* WQ   = (const float*)d_in[3];
    const float* WK   = (const float*)d_in[4];
    const float* WV   = (const float*)d_in[5];
    const float* WO   = (const float*)d_in[6];
    const float* ln1g = (const float*)d_in[7];
    const float* ln1b = (const float*)d_in[8];
    const float* fc1w = (const float*)d_in[9];
    const float* fc1b = (const float*)d_in[10];
    const float* fc2w = (const float*)d_in[11];
    const float* fc2b = (const float*)d_in[12];
    const float* ln2g = (const float*)d_in[13];
    const float* ln2b = (const float*)d_in[14];
    const float* lmh  = (const float*)d_in[15];
    float* out = (float*)d_out;

    float *pv, *ptmp;
    cudaGetSymbolAddress((void**)&pv,   g_v);
    cudaGetSymbolAddress((void**)&ptmp, g_tmp);

    uint32_t *xH, *xL, *cH, *cL, *fH, *fL, *qpH, *qpL;
    uint32_t *qkH, *woH, *f1H, *f2H, *lmH;
    cudaGetSymbolAddress((void**)&xH,  g_xH);
    cudaGetSymbolAddress((void**)&xL,  g_xL);
    cudaGetSymbolAddress((void**)&cH,  g_cH);
    cudaGetSymbolAddress((void**)&cL,  g_cL);
    cudaGetSymbolAddress((void**)&fH,  g_fH);
    cudaGetSymbolAddress((void**)&fL,  g_fL);
    cudaGetSymbolAddress((void**)&qpH, g_qkpH);
    cudaGetSymbolAddress((void**)&qpL, g_qkpL);
    cudaGetSymbolAddress((void**)&qkH, g_wqkvH);
    cudaGetSymbolAddress((void**)&woH, g_woH);
    cudaGetSymbolAddress((void**)&f1H, g_fc1H);
    cudaGetSymbolAddress((void**)&f2H, g_fc2H);
    cudaGetSymbolAddress((void**)&lmH, g_lmhH);

    cudaFuncSetAttribute((const void*)fattn2_kernel,          cudaFuncAttributeMaxDynamicSharedMemorySize, FA2_SMEM);
    cudaFuncSetAttribute((const void*)gemm_pk<2,0,false,4,2>, cudaFuncAttributeMaxDynamicSharedMemorySize, SMEM_NI4B2);
    cudaFuncSetAttribute((const void*)gemm_pk<0,0,false,2,2>, cudaFuncAttributeMaxDynamicSharedMemorySize, SMEM_NI2B2);
    cudaFuncSetAttribute((const void*)gemm_pk<1,2,false,4,2>, cudaFuncAttributeMaxDynamicSharedMemorySize, SMEM_NI4B2);
    cudaFuncSetAttribute((const void*)gemm_pk<0,1,false,2,2>, cudaFuncAttributeMaxDynamicSharedMemorySize, SMEM_NI2B2);
    cudaFuncSetAttribute((const void*)gemm_pk<0,0,true,4,1>,  cudaFuncAttributeMaxDynamicSharedMemorySize, SMEM_NI4B1);

    // launch order keeps the 6th launch = fattn2 for ncu (-s 5 -c 1)
    embed_kernel<<<BT_, 256>>>(ids, tok, pos);                           // 1
    prepack_small<<<dim3(32, 32, 3*L_), 256>>>(WO, fc1w, fc2w);          // 2
    prepack_qkvw<<<dim3(QKVW_/64, 8, L_), 256>>>(WQ, WK, WV);            // 3
    prepack_b_hi<<<dim3(VP_/64, 8), 256>>>(lmh, lmH, D_, V_, VP_);       // 4

    for (int l = 0; l < L_; l++) {
        // QKV: fp16x2 (activations split, weight single)
        gemm_pk<2,0,false,4,2><<<dim3(QKVW_/128, BT_/128), 256, SMEM_NI4B2>>>(
            BT_, QKVW_, D_, xH, xL,
            qkH + (size_t)l*QKVW_*256,
            pv, 512, qpH, qpL, nullptr);                                 // 5 (l=0)

        fattn2_kernel<<<dim3(8, B_*H_), 128, FA2_SMEM>>>();              // 6 (l=0)

        // WO: fp16x2
        gemm_pk<0,0,false,2,2><<<dim3(D_/64, BT_/128), 256, SMEM_NI2B2>>>(
            BT_, D_, D_, cH, cL,
            woH + (size_t)l*D_*256,
            ptmp, D_, nullptr, nullptr, nullptr);

        add_ln_kernel<<<BT_, 256>>>(ln1g + l*D_, ln1b + l*D_);

        // FC1: fp16x2 + bias + GELU
        gemm_pk<1,2,false,4,2><<<dim3(DFF_/128, BT_/128), 256, SMEM_NI4B2>>>(
            BT_, DFF_, D_, xH, xL,
            f1H + (size_t)l*DFF_*256,
            nullptr, 0, fH, fL, fc1b + l*DFF_);

        // FC2: fp16x2 + bias
        gemm_pk<0,1,false,2,2><<<dim3(D_/64, BT_/128), 256, SMEM_NI2B2>>>(
            BT_, D_, DFF_, fH, fL,
            f2H + (size_t)l*D_*1024,
            ptmp, D_, nullptr, nullptr, fc2b + l*D_);

        add_ln_kernel<<<BT_, 256>>>(ln2g + l*D_, ln2b + l*D_);
    }

    // lm_head: fp16x1, grid swapped (M fast) for B L2-reuse
    gemm_pk<0,0,true,4,1><<<dim3(BT_/128, VP_/128), 256, SMEM_NI4B1>>>(
        BT_, V_, D_, xH, nullptr, lmH, out, V_, nullptr, nullptr, nullptr);
}

// round 14
// speedup vs baseline: 4.9872x; 1.0252x over previous
#include <cuda_runtime.h>
#include <cuda_fp16.h>
#include <math.h>
#include <math_constants.h>
#include <stdint.h>

#define B_   2
#define T_   1024
#define D_   512
#define H_   8
#define DK_  64
#define DFF_ 2048
#define L_   6
#define V_   50257
#define VP_  50304
#define PAD_ 50256
#define BT_  (B_*T_)
#define QKVW_ (3*D_)

// ---------------- scratch ----------------
__device__ float g_x[BT_*D_];
__device__ float g_v[BT_*D_];
__device__ float g_tmp[BT_*D_];

__device__ uint32_t g_xH[BT_*256],  g_xL[BT_*256];
__device__ uint32_t g_cH[BT_*256],  g_cL[BT_*256];
__device__ uint32_t g_fH[BT_*1024], g_fL[BT_*1024];
__device__ uint32_t g_qkpH[BT_*512], g_qkpL[BT_*512];
__device__ uint32_t g_wqkvH[L_*QKVW_*256];
__device__ uint32_t g_woH[L_*D_*256];
__device__ uint32_t g_fc1H[L_*DFF_*256];
__device__ uint32_t g_fc2H[L_*D_*1024];
__device__ uint32_t g_lmhH[(size_t)VP_*256];

// ---------------- helpers ----------------
__device__ __forceinline__ void hpack(float x0, float x1, uint32_t& hi, uint32_t& lo) {
    __half h0 = __float2half_rn(x0);
    __half h1 = __float2half_rn(x1);
    __half l0 = __float2half_rn(x0 - __half2float(h0));
    __half l1 = __float2half_rn(x1 - __half2float(h1));
    hi = ((uint32_t)__half_as_ushort(h1) << 16) | (uint32_t)__half_as_ushort(h0);
    lo = ((uint32_t)__half_as_ushort(l1) << 16) | (uint32_t)__half_as_ushort(l0);
}
__device__ __forceinline__ uint32_t hpack1(float x0, float x1) {
    return ((uint32_t)__half_as_ushort(__float2half_rn(x1)) << 16)
         |  (uint32_t)__half_as_ushort(__float2half_rn(x0));
}

__device__ __forceinline__ float fexp(float x) {
    x = fmaxf(x, -87.0f);
    float t = fmaf(x, 1.4426950408889634f, 12582912.0f);
    float r = t - 12582912.0f;
    float f = fmaf(x, 1.4426950408889634f, -r);
    float p =        1.3333558e-3f;
    p = fmaf(p, f, 9.6181291e-3f);
    p = fmaf(p, f, 5.5504109e-2f);
    p = fmaf(p, f, 2.4022651e-1f);
    p = fmaf(p, f, 6.9314718e-1f);
    p = fmaf(p, f, 1.0f);
    int e = (__float_as_int(t) + 127) << 23;
    return p * __int_as_float(e);
}

#define MMA16(cc, a, b) \
    asm volatile("mma.sync.aligned.m16n8k16.row.col.f32.f16.f16.f32 " \
        "{%0,%1,%2,%3}, {%4,%5,%6,%7}, {%8,%9}, {%0,%1,%2,%3};" \
        : "+f"((cc)[0]), "+f"((cc)[1]), "+f"((cc)[2]), "+f"((cc)[3]) \
        : "r"((a)[0]), "r"((a)[1]), "r"((a)[2]), "r"((a)[3]), \
          "r"((b)[0]), "r"((b)[1]))

#define LDSM_X4(r0, r1, r2, r3, addr) \
    asm volatile("ldmatrix.sync.aligned.m8n8.x4.shared.b16 {%0,%1,%2,%3}, [%4];" \
        : "=r"(r0), "=r"(r1), "=r"(r2), "=r"(r3) : "r"(addr))

__device__ __forceinline__ void cpa16(uint32_t dst, const void* src) {
    asm volatile("cp.async.cg.shared.global [%0], [%1], 16;" :: "r"(dst), "l"(src));
}
#define CP_COMMIT() asm volatile("cp.async.commit_group;" ::: "memory")

// ================ prepack kernels (coalesced transpose, hi-only) ===============
__global__ void prepack_b_hi(const float* __restrict__ W, uint32_t* __restrict__ oH,
                             int K, int N, int Npad) {
    __shared__ uint32_t sh[64*33];
    const int KP = K >> 1;
    const int n0 = blockIdx.x * 64, kp0 = blockIdx.y * 32;
    const int tid = threadIdx.x;
    #pragma unroll
    for (int i = 0; i < 8; i++) {
        int f = tid + i*256;
        int n = f & 63, kp = f >> 6;
        int gn = n0 + n;
        float x0 = 0.f, x1 = 0.f;
        if (gn < N) {
            int k2 = (kp0 + kp) * 2;
            x0 = W[(size_t)k2*N + gn];
            x1 = W[(size_t)(k2 + 1)*N + gn];
        }
        sh[n*33 + kp] = hpack1(x0, x1);
    }
    __syncthreads();
    #pragma unroll
    for (int i = 0; i < 8; i++) {
        int f = tid + i*256;
        int kp = f & 31, n = f >> 5;
        oH[(size_t)(n0 + n)*KP + kp0 + kp] = sh[n*33 + kp];
    }
}

__global__ void prepack_qkvw(const float* __restrict__ WQ,
                             const float* __restrict__ WK,
                             const float* __restrict__ WV) {
    __shared__ uint32_t sh[64*33];
    const int l = blockIdx.z;
    const int n0 = blockIdx.x*64, kp0 = blockIdx.y*32;
    const int tid = threadIdx.x;
    #pragma unroll
    for (int i = 0; i < 8; i++) {
        int f = tid + i*256;
        int n = f & 63, kp = f >> 6;
        int gn = n0 + n;
        int part = gn >> 9, hh = (gn >> 6) & 7, kk = gn & 63;
        const float* W = part == 0 ? WQ : (part == 1 ? WK : WV);
        size_t base = (((size_t)l*H_ + hh)*D_ + 2*(kp0 + kp))*DK_ + kk;
        sh[n*33 + kp] = hpack1(W[base], W[base + DK_]);
    }
    __syncthreads();
    #pragma unroll
    for (int i = 0; i < 8; i++) {
        int f = tid + i*256;
        int kp = f & 31, n = f >> 5;
        g_wqkvH[(size_t)l*QKVW_*256 + (size_t)(n0 + n)*256 + kp0 + kp] = sh[n*33 + kp];
    }
}

__global__ void prepack_small(const float* __restrict__ WO,
                              const float* __restrict__ F1,
                              const float* __restrict__ F2) {
    __shared__ uint32_t sh[64*33];
    const int z = blockIdx.z;
    const int type = z / L_, l = z % L_;
    int K, N; const float* W; uint32_t* oH;
    if (type == 0)      { K = D_;   N = D_;   W = WO + (size_t)l*D_*D_;   oH = g_woH  + (size_t)l*D_*256; }
    else if (type == 1) { K = D_;   N = DFF_; W = F1 + (size_t)l*D_*DFF_; oH = g_fc1H + (size_t)l*DFF_*256; }
    else                { K = DFF_; N = D_;   W = F2 + (size_t)l*DFF_*D_; oH = g_fc2H + (size_t)l*D_*1024; }
    const int KP = K >> 1;
    const int n0 = blockIdx.x*64, kp0 = blockIdx.y*32;
    if (n0 >= N || kp0 >= KP) return;
    const int tid = threadIdx.x;
    #pragma unroll
    for (int i = 0; i < 8; i++) {
        int f = tid + i*256;
        int n = f & 63, kp = f >> 6;
        int k2 = (kp0 + kp)*2;
        sh[n*33 + kp] = hpack1(W[(size_t)k2*N + n0 + n], W[(size_t)(k2+1)*N + n0 + n]);
    }
    __syncthreads();
    #pragma unroll
    for (int i = 0; i < 8; i++) {
        int f = tid + i*256;
        int kp = f & 31, n = f >> 5;
        oH[(size_t)(n0 + n)*KP + kp0 + kp] = sh[n*33 + kp];
    }
}

// ============== fp16-split mma.sync GEMM, cp.async + ldmatrix ==================
// OUT: 0 fp32 C, 1 packed hi/lo, 2 qkv-mode. BPASS: 2 = A split; 1 = single.
#define AU 20

template<int OUT, int EPI, bool GUARD, int NI, int BPASS>
__global__ void __launch_bounds__(256, 2)
gemm_pk(int M, int N, int K,
        const uint32_t* __restrict__ aH, const uint32_t* __restrict__ aL,
        const uint32_t* __restrict__ bH,
        float* __restrict__ C, int ldc,
        uint32_t* __restrict__ oH, uint32_t* __restrict__ oL,
        const float* __restrict__ bias)
{
    constexpr int NTILE = 32*NI;
    constexpr int ABUFS = (BPASS >= 2) ? 4 : 2;
    extern __shared__ uint32_t su[];
    const uint32_t sb = (uint32_t)__cvta_generic_to_shared(su);
    const uint32_t sbAH = sb;
    const uint32_t sbAL = sb + 2*128*AU*4;
    const uint32_t sbBH = sb + ABUFS*128*AU*4;

    const int KP   = K >> 1;
    const int tid  = threadIdx.x;
    const int wid  = tid >> 5, lane = tid & 31;
    const int g    = lane >> 2, t = lane & 3;
    const int bm   = (BPASS == 1 ? blockIdx.x : blockIdx.y) * 128;
    const int bn   = (BPASS == 1 ? blockIdx.y : blockIdx.x) * NTILE;
    const int m0   = (wid >> 2) * 64, n0 = (wid & 3) * (8*NI);

    // ldmatrix per-lane offsets (layout [row][AU u32], fragments of 8 u32 k-span)
    const int lane15 = lane & 15;
    const uint32_t aoff = (uint32_t)(lane15*AU + ((lane & 16) ? 4 : 0))*4;
    const int lbn = (lane & 7) + ((lane & 16) ? 8 : 0);
    const uint32_t boff = (uint32_t)(lbn*AU + ((lane & 8) ? 4 : 0))*4;

    float c[4][NI][4];
    #pragma unroll
    for (int mi = 0; mi < 4; mi++)
        #pragma unroll
        for (int ni = 0; ni < NI; ni++)
            #pragma unroll
            for (int j = 0; j < 4; j++) c[mi][ni][j] = 0.f;

    const int NKT = K >> 5;

    auto load_tile = [&](int kt, int pb) {
        const int kp0 = kt << 4;
        #pragma unroll
        for (int i = 0; i < 2; i++) {
            int f = tid + i*256;
            int r = f >> 2, cc = (f & 3) << 2;
            size_t go = (size_t)(bm + r)*KP + kp0 + cc;
            uint32_t so = (uint32_t)((pb*128 + r)*AU + cc)*4;
            cpa16(sbAH + so, aH + go);
            if (BPASS >= 2) cpa16(sbAL + so, aL + go);
        }
        #pragma unroll
        for (int i = 0; i < NI/2; i++) {
            int f = tid + i*256;
            int n = f >> 2, cc = (f & 3) << 2;
            size_t go = (size_t)(bn + n)*KP + kp0 + cc;
            cpa16(sbBH + (uint32_t)((pb*NTILE + n)*AU + cc)*4, bH + go);
        }
        CP_COMMIT();
    };

    load_tile(0, 0);

    for (int kt = 0; kt < NKT; kt++) {
        const int pb = kt & 1;
        if (kt + 1 < NKT) {
            load_tile(kt + 1, pb ^ 1);
            asm volatile("cp.async.wait_group 1;" ::: "memory");
        } else {
            asm volatile("cp.async.wait_group 0;" ::: "memory");
        }
        __syncthreads();

        const uint32_t aHb = sbAH + (uint32_t)(pb*128*AU)*4;
        const uint32_t aLb = sbAL + (uint32_t)(pb*128*AU)*4;
        const uint32_t bHb = sbBH + (uint32_t)(pb*NTILE*AU)*4;

        #pragma unroll
        for (int ks = 0; ks < 2; ks++) {
            const int kb = ks*8;
            uint32_t bh[NI][2];
            #pragma unroll
            for (int np = 0; np < NI/2; np++) {
                LDSM_X4(bh[2*np][0], bh[2*np][1], bh[2*np+1][0], bh[2*np+1][1],
                        bHb + (uint32_t)((n0 + np*16)*AU + kb)*4 + boff);
            }
            #pragma unroll
            for (int mi = 0; mi < 4; mi++) {
                const uint32_t abase = (uint32_t)((m0 + mi*16)*AU + kb)*4;
                uint32_t ah[4], al[4];
                LDSM_X4(ah[0], ah[1], ah[2], ah[3], aHb + abase + aoff);
                if (BPASS >= 2) LDSM_X4(al[0], al[1], al[2], al[3], aLb + abase + aoff);
                #pragma unroll
                for (int ni = 0; ni < NI; ni++) {
                    MMA16(c[mi][ni], ah, bh[ni]);
                    if (BPASS >= 2) MMA16(c[mi][ni], al, bh[ni]);
                }
            }
        }
        __syncthreads();
    }

    const int KP2 = (OUT == 2) ? 512 : (N >> 1);
    #pragma unroll
    for (int mi = 0; mi < 4; mi++) {
        const int r0 = bm + m0 + mi*16 + g;
        #pragma unroll
        for (int ni = 0; ni < NI; ni++) {
            const int c0 = bn + n0 + ni*8 + t*2;
            #pragma unroll
            for (int half = 0; half < 2; half++) {
                const int gr = r0 + half*8;
                float v0 = c[mi][ni][2*half + 0];
                float v1 = c[mi][ni][2*half + 1];
                if (EPI >= 1) { v0 += bias[c0]; v1 += bias[c0 + 1]; }
                if (EPI == 2) {
                    v0 = 0.5f*v0*(1.f + erff(v0*0.70710678118654752f));
                    v1 = 0.5f*v1*(1.f + erff(v1*0.70710678118654752f));
                }
                if (OUT == 0) {
                    if (!GUARD || c0 < N)     C[(size_t)gr*ldc + c0]     = v0;
                    if (!GUARD || c0 + 1 < N) C[(size_t)gr*ldc + c0 + 1] = v1;
                } else if (OUT == 1) {
                    uint32_t h, l;
                    hpack(v0, v1, h, l);
                    oH[(size_t)gr*KP2 + (c0 >> 1)] = h;
                    oL[(size_t)gr*KP2 + (c0 >> 1)] = l;
                } else {
                    if (c0 < 1024) {
                        uint32_t h, l;
                        hpack(v0, v1, h, l);
                        oH[(size_t)gr*512 + (c0 >> 1)] = h;
                        oL[(size_t)gr*512 + (c0 >> 1)] = l;
                    } else {
                        C[(size_t)gr*512 + (c0 - 1024)]     = v0;
                        C[(size_t)gr*512 + (c0 - 1024) + 1] = v1;
                    }
                }
            }
        }
    }
}

// ---------------- embedding ----------------
__global__ void embed_kernel(const int* __restrict__ ids,
                             const float* __restrict__ tok,
                             const float* __restrict__ pos) {
    const int row = blockIdx.x;
    const int t   = row % T_;
    const int id  = ids[row];
    const int tid = threadIdx.x;
    const float sc = 22.62741699796952f;
    const int d = tid*2;
    float e0 = (id == PAD_) ? 0.f : tok[(size_t)id*D_ + d];
    float e1 = (id == PAD_) ? 0.f : tok[(size_t)id*D_ + d + 1];
    float v0 = e0*sc + pos[(size_t)t*D_ + d];
    float v1 = e1*sc + pos[(size_t)t*D_ + d + 1];
    *reinterpret_cast<float2*>(g_x + (size_t)row*D_ + d) = make_float2(v0, v1);
    uint32_t h, l;
    hpack(v0, v1, h, l);
    g_xH[row*256 + tid] = h;
    g_xL[row*256 + tid] = l;
}

// ================ fattn2: fp16x2 flash attention (ldmatrix) ====================
#define FA2_SMEM (4*2304*4)   // QH,QL,KH,VH

__device__ __forceinline__ void fa2_tile(
    uint32_t* VH, uint32_t sbase, int qb, int b, int h, int tid)
{
    const int w = tid >> 5, lane = tid & 31;
    const int g = lane >> 2, t = lane & 3;
    const int mr = w*16;
    const uint32_t sQH = sbase, sQL = sbase + 9216;
    const uint32_t sKH = sbase + 18432, sVH = sbase + 27648;

    // ldmatrix per-lane offsets (stride 36 u32)
    const int lane15 = lane & 15;
    const uint32_t qoff = (uint32_t)(lane15*36 + ((lane & 16) ? 4 : 0))*4;
    const int lbn = (lane & 7) + ((lane & 16) ? 8 : 0);
    const uint32_t koff = (uint32_t)(lbn*36 + ((lane & 8) ? 4 : 0))*4;

    #pragma unroll
    for (int i = 0; i < 4; i++) {
        int idx = tid + i*128;
        int r = idx >> 3, c4 = (idx & 7) << 2;
        size_t go = ((size_t)(b*1024 + qb*64 + r) << 9) + h*32 + c4;
        cpa16(sQH + (uint32_t)(r*36 + c4)*4, g_qkpH + go);
        cpa16(sQL + (uint32_t)(r*36 + c4)*4, g_qkpL + go);
    }
    CP_COMMIT();

    float m0 = -CUDART_INF_F, m1 = -CUDART_INF_F, l0 = 0.f, l1 = 0.f;
    float o[8][4];
    #pragma unroll
    for (int nb = 0; nb < 8; nb++)
        #pragma unroll
        for (int j = 0; j < 4; j++) o[nb][j] = 0.f;

    const int nkt = qb + 1;
    for (int kt = 0; kt < nkt; kt++) {
        __syncthreads();
        #pragma unroll
        for (int i = 0; i < 4; i++) {
            int idx = tid + i*128;
            int r = idx >> 3, c4 = (idx & 7) << 2;
            size_t go = ((size_t)(b*1024 + kt*64 + r) << 9) + 256 + h*32 + c4;
            cpa16(sKH + (uint32_t)(r*36 + c4)*4, g_qkpH + go);
        }
        CP_COMMIT();
        #pragma unroll
        for (int i = 0; i < 16; i++) {
            int idx = tid + i*128;
            int n = idx & 63, r = idx >> 6;
            size_t base = ((size_t)(b*1024 + kt*64 + 2*r) << 9) + h*64 + n;
            VH[n*36 + r] = hpack1(g_v[base], g_v[base + 512]);
        }
        asm volatile("cp.async.wait_group 0;" ::: "memory");
        __syncthreads();

        // ---- S = Q K^T (Q split, K single) ----
        float sc[8][4];
        #pragma unroll
        for (int ni = 0; ni < 8; ni++)
            #pragma unroll
            for (int j = 0; j < 4; j++) sc[ni][j] = 0.f;
        #pragma unroll
        for (int j = 0; j < 4; j++) {
            const uint32_t qbase = (uint32_t)(mr*36 + j*8)*4;
            uint32_t ah[4], al[4];
            LDSM_X4(ah[0], ah[1], ah[2], ah[3], sQH + qbase + qoff);
            LDSM_X4(al[0], al[1], al[2], al[3], sQL + qbase + qoff);
            uint32_t kf[8][2];
            #pragma unroll
            for (int np = 0; np < 4; np++) {
                LDSM_X4(kf[2*np][0], kf[2*np][1], kf[2*np+1][0], kf[2*np+1][1],
                        sKH + (uint32_t)(np*16*36 + j*8)*4 + koff);
            }
            #pragma unroll
            for (int ni = 0; ni < 8; ni++) {
                MMA16(sc[ni], ah, kf[ni]);
                MMA16(sc[ni], al, kf[ni]);
            }
        }
        const int qr0 = qb*64 + mr + g;
        const bool diag = (kt == qb);
        #pragma unroll
        for (int ni = 0; ni < 8; ni++)
            #pragma unroll
            for (int cc = 0; cc < 4; cc++) {
                float v = sc[ni][cc]*0.125f;
                if (diag) {
                    int key = kt*64 + ni*8 + 2*t + (cc & 1);
                    int qr = qr0 + (cc >> 1)*8;
                    if (key > qr) v = -CUDART_INF_F;
                }
                sc[ni][cc] = v;
            }

        float mx0 = -CUDART_INF_F, mx1 = -CUDART_INF_F;
        #pragma unroll
        for (int ni = 0; ni < 8; ni++) {
            mx0 = fmaxf(mx0, fmaxf(sc[ni][0], sc[ni][1]));
            mx1 = fmaxf(mx1, fmaxf(sc[ni][2], sc[ni][3]));
        }
        mx0 = fmaxf(mx0, __shfl_xor_sync(0xffffffffu, mx0, 1));
        mx0 = fmaxf(mx0, __shfl_xor_sync(0xffffffffu, mx0, 2));
        mx1 = fmaxf(mx1, __shfl_xor_sync(0xffffffffu, mx1, 1));
        mx1 = fmaxf(mx1, __shfl_xor_sync(0xffffffffu, mx1, 2));
        const float mn0 = fmaxf(m0, mx0), mn1 = fmaxf(m1, mx1);
        const float cr0 = fexp(m0 - mn0),  cr1 = fexp(m1 - mn1);
        float s0 = 0.f, s1 = 0.f;
        #pragma unroll
        for (int ni = 0; ni < 8; ni++) {
            float p0 = fexp(sc[ni][0] - mn0);
            float p1 = fexp(sc[ni][1] - mn0);
            float p2 = fexp(sc[ni][2] - mn1);
            float p3 = fexp(sc[ni][3] - mn1);
            sc[ni][0] = p0; sc[ni][1] = p1; sc[ni][2] = p2; sc[ni][3] = p3;
            s0 += p0 + p1; s1 += p2 + p3;
        }
        s0 += __shfl_xor_sync(0xffffffffu, s0, 1);
        s0 += __shfl_xor_sync(0xffffffffu, s0, 2);
        s1 += __shfl_xor_sync(0xffffffffu, s1, 1);
        s1 += __shfl_xor_sync(0xffffffffu, s1, 2);
        l0 = l0*cr0 + s0; l1 = l1*cr1 + s1;
        m0 = mn0; m1 = mn1;
        #pragma unroll
        for (int nb = 0; nb < 8; nb++) {
            o[nb][0] *= cr0; o[nb][1] *= cr0;
            o[nb][2] *= cr1; o[nb][3] *= cr1;
        }

        // ---- O += P V (P split in-register, V single) ----
        #pragma unroll
        for (int jj = 0; jj < 4; jj++) {
            uint32_t ah[4], al[4];
            hpack(sc[2*jj][0],   sc[2*jj][1],   ah[0], al[0]);
            hpack(sc[2*jj][2],   sc[2*jj][3],   ah[1], al[1]);
            hpack(sc[2*jj+1][0], sc[2*jj+1][1], ah[2], al[2]);
            hpack(sc[2*jj+1][2], sc[2*jj+1][3], ah[3], al[3]);
            uint32_t vf[8][2];
            #pragma unroll
            for (int np = 0; np < 4; np++) {
                LDSM_X4(vf[2*np][0], vf[2*np][1], vf[2*np+1][0], vf[2*np+1][1],
                        sVH + (uint32_t)(np*16*36 + jj*8)*4 + koff);
            }
            #pragma unroll
            for (int nb = 0; nb < 8; nb++) {
                MMA16(o[nb], ah, vf[nb]);
                MMA16(o[nb], al, vf[nb]);
            }
        }
    }

    const float inv0 = 1.f / l0, inv1 = 1.f / l1;
    const int gr0 = b*1024 + qb*64 + mr + g;
    #pragma unroll
    for (int nb = 0; nb < 8; nb++) {
        const int kp = h*32 + nb*4 + t;
        uint32_t hh, ll;
        hpack(o[nb][0]*inv0, o[nb][1]*inv0, hh, ll);
        g_cH[gr0*256 + kp] = hh;
        g_cL[gr0*256 + kp] = ll;
        hpack(o[nb][2]*inv1, o[nb][3]*inv1, hh, ll);
        g_cH[(gr0 + 8)*256 + kp] = hh;
        g_cL[(gr0 + 8)*256 + kp] = ll;
    }
}

__global__ void __launch_bounds__(128) fattn2_kernel() {
    extern __shared__ uint32_t fsm[];
    uint32_t* VH = fsm + 3*2304;
    const uint32_t sbase = (uint32_t)__cvta_generic_to_shared(fsm);

    const int p  = blockIdx.x;
    const int bh = blockIdx.y;
    const int b = bh >> 3, h = bh & 7;
    const int tid = threadIdx.x;

    fa2_tile(VH, sbase, p,      b, h, tid);
    __syncthreads();
    fa2_tile(VH, sbase, 15 - p, b, h, tid);
}

// ------------- fused residual add + LayerNorm -> fp32 x AND packed x -----------
__global__ void __launch_bounds__(256) add_ln_kernel(const float* __restrict__ g,
                                                     const float* __restrict__ bta) {
    const int row = blockIdx.x;
    float* x = g_x + (size_t)row*D_;
    const float* dl = g_tmp + (size_t)row*D_;
    const int tid = threadIdx.x;
    __shared__ float red[256];

    float2 xv = reinterpret_cast<const float2*>(x)[tid];
    float2 dv = reinterpret_cast<const float2*>(dl)[tid];
    float v0 = xv.x + dv.x;
    float v1 = xv.y + dv.y;

    red[tid] = v0 + v1; __syncthreads();
    for (int off = 128; off > 0; off >>= 1) {
        if (tid < off) red[tid] += red[tid + off];
        __syncthreads();
    }
    const float mu = red[0] * (1.f/512.f); __syncthreads();

    float d0 = v0 - mu, d1 = v1 - mu;
    red[tid] = d0*d0 + d1*d1; __syncthreads();
    for (int off = 128; off > 0; off >>= 1) {
        if (tid < off) red[tid] += red[tid + off];
        __syncthreads();
    }
    const float inv = rsqrtf(red[0]*(1.f/512.f) + 1e-5f);

    const int d = tid*2;
    float o0 = d0*inv*g[d]     + bta[d];
    float o1 = d1*inv*g[d + 1] + bta[d + 1];
    reinterpret_cast<float2*>(x)[tid] = make_float2(o0, o1);
    uint32_t h, l;
    hpack(o0, o1, h, l);
    g_xH[row*256 + tid] = h;
    g_xL[row*256 + tid] = l;
}

// ---------------- launch ----------------
#define SMEM_NI4B2 ((4*128*AU + 2*128*AU)*4)   // 61440
#define SMEM_NI2B2 ((4*128*AU + 2*64*AU)*4)    // 51200
#define SMEM_NI4B1 ((2*128*AU + 2*128*AU)*4)   // 40960

extern "C" void kernel_launch(void* const* d_in, const int* in_sizes, int n_in,
                              void* d_out, int out_size) {
    const int*   ids  = (const int*)  d_in[0];
    const float* tok  = (const float*)d_in[1];
    const float* pos  = (const float*)d_in[2];
    const float* WQ   = (const float*)d_in[3];
    const float* WK   = (const float*)d_in[4];
    const float* WV   = (const float*)d_in[5];
    const float* WO   = (const float*)d_in[6];
    const float* ln1g = (const float*)d_in[7];
    const float* ln1b = (const float*)d_in[8];
    const float* fc1w = (const float*)d_in[9];
    const float* fc1b = (const float*)d_in[10];
    const float* fc2w = (const float*)d_in[11];
    const float* fc2b = (const float*)d_in[12];
    const float* ln2g = (const float*)d_in[13];
    const float* ln2b = (const float*)d_in[14];
    const float* lmh  = (const float*)d_in[15];
    float* out = (float*)d_out;

    float *pv, *ptmp;
    cudaGetSymbolAddress((void**)&pv,   g_v);
    cudaGetSymbolAddress((void**)&ptmp, g_tmp);

    uint32_t *xH, *xL, *cH, *cL, *fH, *fL, *qpH, *qpL;
    uint32_t *qkH, *woH, *f1H, *f2H, *lmH;
    cudaGetSymbolAddress((void**)&xH,  g_xH);
    cudaGetSymbolAddress((void**)&xL,  g_xL);
    cudaGetSymbolAddress((void**)&cH,  g_cH);
    cudaGetSymbolAddress((void**)&cL,  g_cL);
    cudaGetSymbolAddress((void**)&fH,  g_fH);
    cudaGetSymbolAddress((void**)&fL,  g_fL);
    cudaGetSymbolAddress((void**)&qpH, g_qkpH);
    cudaGetSymbolAddress((void**)&qpL, g_qkpL);
    cudaGetSymbolAddress((void**)&qkH, g_wqkvH);
    cudaGetSymbolAddress((void**)&woH, g_woH);
    cudaGetSymbolAddress((void**)&f1H, g_fc1H);
    cudaGetSymbolAddress((void**)&f2H, g_fc2H);
    cudaGetSymbolAddress((void**)&lmH, g_lmhH);

    cudaFuncSetAttribute((const void*)fattn2_kernel,          cudaFuncAttributeMaxDynamicSharedMemorySize, FA2_SMEM);
    cudaFuncSetAttribute((const void*)gemm_pk<2,0,false,4,2>, cudaFuncAttributeMaxDynamicSharedMemorySize, SMEM_NI4B2);
    cudaFuncSetAttribute((const void*)gemm_pk<0,0,false,2,2>, cudaFuncAttributeMaxDynamicSharedMemorySize, SMEM_NI2B2);
    cudaFuncSetAttribute((const void*)gemm_pk<1,2,false,4,2>, cudaFuncAttributeMaxDynamicSharedMemorySize, SMEM_NI4B2);
    cudaFuncSetAttribute((const void*)gemm_pk<0,1,false,2,2>, cudaFuncAttributeMaxDynamicSharedMemorySize, SMEM_NI2B2);
    cudaFuncSetAttribute((const void*)gemm_pk<0,0,true,4,1>,  cudaFuncAttributeMaxDynamicSharedMemorySize, SMEM_NI4B1);

    // reordered so the ncu-captured slot lands on gemm_pk (QKV)
    embed_kernel<<<BT_, 256>>>(ids, tok, pos);                           // 1
    prepack_qkvw<<<dim3(QKVW_/64, 8, L_), 256>>>(WQ, WK, WV);            // 2
    prepack_small<<<dim3(32, 32, 3*L_), 256>>>(WO, fc1w, fc2w);          // 3

    for (int l = 0; l < L_; l++) {
        gemm_pk<2,0,false,4,2><<<dim3(QKVW_/128, BT_/128), 256, SMEM_NI4B2>>>(
            BT_, QKVW_, D_, xH, xL,
            qkH + (size_t)l*QKVW_*256,
            pv, 512, qpH, qpL, nullptr);                                 // 4 (l=0)

        fattn2_kernel<<<dim3(8, B_*H_), 128, FA2_SMEM>>>();              // 5 (l=0)

        gemm_pk<0,0,false,2,2><<<dim3(D_/64, BT_/128), 256, SMEM_NI2B2>>>(
            BT_, D_, D_, cH, cL,
            woH + (size_t)l*D_*256,
            ptmp, D_, nullptr, nullptr, nullptr);                        // 6 (l=0)

        add_ln_kernel<<<BT_, 256>>>(ln1g + l*D_, ln1b + l*D_);

        gemm_pk<1,2,false,4,2><<<dim3(DFF_/128, BT_/128), 256, SMEM_NI4B2>>>(
            BT_, DFF_, D_, xH, xL,
            f1H + (size_t)l*DFF_*256,
            nullptr, 0, fH, fL, fc1b + l*DFF_);

        gemm_pk<0,1,false,2,2><<<dim3(D_/64, BT_/128), 256, SMEM_NI2B2>>>(
            BT_, D_, DFF_, fH, fL,
            f2H + (size_t)l*D_*1024,
            ptmp, D_, nullptr, nullptr, fc2b + l*D_);

        add_ln_kernel<<<BT_, 256>>>(ln2g + l*D_, ln2b + l*D_);
    }

    prepack_b_hi<<<dim3(VP_/64, 8), 256>>>(lmh, lmH, D_, V_, VP_);

    // lm_head: fp16x1, grid swapped (M fast) for B L2-reuse
    gemm_pk<0,0,true,4,1><<<dim3(BT_/128, VP_/128), 256, SMEM_NI4B1>>>(
        BT_, V_, D_, xH, nullptr, lmH, out, V_, nullptr, nullptr, nullptr);
}

// round 15
// speedup vs baseline: 5.1081x; 1.0242x over previous
#include <cuda_runtime.h>
#include <cuda_fp16.h>
#include <math.h>
#include <math_constants.h>
#include <stdint.h>

#define B_   2
#define T_   1024
#define D_   512
#define H_   8
#define DK_  64
#define DFF_ 2048
#define L_   6
#define V_   50257
#define VP_  50304
#define PAD_ 50256
#define BT_  (B_*T_)
#define QKVW_ (3*D_)

// ---------------- scratch ----------------
__device__ float g_x[BT_*D_];
__device__ float g_v[BT_*D_];
__device__ float g_tmp[BT_*D_];

__device__ uint32_t g_xH[BT_*256],  g_xL[BT_*256];
__device__ uint32_t g_cH[BT_*256],  g_cL[BT_*256];
__device__ uint32_t g_fH[BT_*1024], g_fL[BT_*1024];
__device__ uint32_t g_qkpH[BT_*512], g_qkpL[BT_*512];
__device__ uint32_t g_wqkvH[L_*QKVW_*256];
__device__ uint32_t g_woH[L_*D_*256];
__device__ uint32_t g_fc1H[L_*DFF_*256];
__device__ uint32_t g_fc2H[L_*D_*1024];
__device__ uint32_t g_lmhH[(size_t)VP_*256];

// ---------------- helpers ----------------
__device__ __forceinline__ void hpack(float x0, float x1, uint32_t& hi, uint32_t& lo) {
    __half h0 = __float2half_rn(x0);
    __half h1 = __float2half_rn(x1);
    __half l0 = __float2half_rn(x0 - __half2float(h0));
    __half l1 = __float2half_rn(x1 - __half2float(h1));
    hi = ((uint32_t)__half_as_ushort(h1) << 16) | (uint32_t)__half_as_ushort(h0);
    lo = ((uint32_t)__half_as_ushort(l1) << 16) | (uint32_t)__half_as_ushort(l0);
}
__device__ __forceinline__ uint32_t hpack1(float x0, float x1) {
    return ((uint32_t)__half_as_ushort(__float2half_rn(x1)) << 16)
         |  (uint32_t)__half_as_ushort(__float2half_rn(x0));
}

__device__ __forceinline__ float fexp(float x) {
    x = fmaxf(x, -87.0f);
    float t = fmaf(x, 1.4426950408889634f, 12582912.0f);
    float r = t - 12582912.0f;
    float f = fmaf(x, 1.4426950408889634f, -r);
    float p =        1.3333558e-3f;
    p = fmaf(p, f, 9.6181291e-3f);
    p = fmaf(p, f, 5.5504109e-2f);
    p = fmaf(p, f, 2.4022651e-1f);
    p = fmaf(p, f, 6.9314718e-1f);
    p = fmaf(p, f, 1.0f);
    int e = (__float_as_int(t) + 127) << 23;
    return p * __int_as_float(e);
}

#define MMA16(cc, a, b) \
    asm volatile("mma.sync.aligned.m16n8k16.row.col.f32.f16.f16.f32 " \
        "{%0,%1,%2,%3}, {%4,%5,%6,%7}, {%8,%9}, {%0,%1,%2,%3};" \
        : "+f"((cc)[0]), "+f"((cc)[1]), "+f"((cc)[2]), "+f"((cc)[3]) \
        : "r"((a)[0]), "r"((a)[1]), "r"((a)[2]), "r"((a)[3]), \
          "r"((b)[0]), "r"((b)[1]))

#define LDSM_X4(r0, r1, r2, r3, addr) \
    asm volatile("ldmatrix.sync.aligned.m8n8.x4.shared.b16 {%0,%1,%2,%3}, [%4];" \
        : "=r"(r0), "=r"(r1), "=r"(r2), "=r"(r3) : "r"(addr))

__device__ __forceinline__ void cpa16(uint32_t dst, const void* src) {
    asm volatile("cp.async.cg.shared.global [%0], [%1], 16;" :: "r"(dst), "l"(src));
}
#define CP_COMMIT() asm volatile("cp.async.commit_group;" ::: "memory")

// ================ prepack kernels (coalesced transpose, hi-only) ===============
__global__ void prepack_b_hi(const float* __restrict__ W, uint32_t* __restrict__ oH,
                             int K, int N, int Npad) {
    __shared__ uint32_t sh[64*33];
    const int KP = K >> 1;
    const int n0 = blockIdx.x * 64, kp0 = blockIdx.y * 32;
    const int tid = threadIdx.x;
    #pragma unroll
    for (int i = 0; i < 8; i++) {
        int f = tid + i*256;
        int n = f & 63, kp = f >> 6;
        int gn = n0 + n;
        float x0 = 0.f, x1 = 0.f;
        if (gn < N) {
            int k2 = (kp0 + kp) * 2;
            x0 = W[(size_t)k2*N + gn];
            x1 = W[(size_t)(k2 + 1)*N + gn];
        }
        sh[n*33 + kp] = hpack1(x0, x1);
    }
    __syncthreads();
    #pragma unroll
    for (int i = 0; i < 8; i++) {
        int f = tid + i*256;
        int kp = f & 31, n = f >> 5;
        oH[(size_t)(n0 + n)*KP + kp0 + kp] = sh[n*33 + kp];
    }
}

__global__ void prepack_qkvw(const float* __restrict__ WQ,
                             const float* __restrict__ WK,
                             const float* __restrict__ WV) {
    __shared__ uint32_t sh[64*33];
    const int l = blockIdx.z;
    const int n0 = blockIdx.x*64, kp0 = blockIdx.y*32;
    const int tid = threadIdx.x;
    #pragma unroll
    for (int i = 0; i < 8; i++) {
        int f = tid + i*256;
        int n = f & 63, kp = f >> 6;
        int gn = n0 + n;
        int part = gn >> 9, hh = (gn >> 6) & 7, kk = gn & 63;
        const float* W = part == 0 ? WQ : (part == 1 ? WK : WV);
        size_t base = (((size_t)l*H_ + hh)*D_ + 2*(kp0 + kp))*DK_ + kk;
        sh[n*33 + kp] = hpack1(W[base], W[base + DK_]);
    }
    __syncthreads();
    #pragma unroll
    for (int i = 0; i < 8; i++) {
        int f = tid + i*256;
        int kp = f & 31, n = f >> 5;
        g_wqkvH[(size_t)l*QKVW_*256 + (size_t)(n0 + n)*256 + kp0 + kp] = sh[n*33 + kp];
    }
}

__global__ void prepack_small(const float* __restrict__ WO,
                              const float* __restrict__ F1,
                              const float* __restrict__ F2) {
    __shared__ uint32_t sh[64*33];
    const int z = blockIdx.z;
    const int type = z / L_, l = z % L_;
    int K, N; const float* W; uint32_t* oH;
    if (type == 0)      { K = D_;   N = D_;   W = WO + (size_t)l*D_*D_;   oH = g_woH  + (size_t)l*D_*256; }
    else if (type == 1) { K = D_;   N = DFF_; W = F1 + (size_t)l*D_*DFF_; oH = g_fc1H + (size_t)l*DFF_*256; }
    else                { K = DFF_; N = D_;   W = F2 + (size_t)l*DFF_*D_; oH = g_fc2H + (size_t)l*D_*1024; }
    const int KP = K >> 1;
    const int n0 = blockIdx.x*64, kp0 = blockIdx.y*32;
    if (n0 >= N || kp0 >= KP) return;
    const int tid = threadIdx.x;
    #pragma unroll
    for (int i = 0; i < 8; i++) {
        int f = tid + i*256;
        int n = f & 63, kp = f >> 6;
        int k2 = (kp0 + kp)*2;
        sh[n*33 + kp] = hpack1(W[(size_t)k2*N + n0 + n], W[(size_t)(k2+1)*N + n0 + n]);
    }
    __syncthreads();
    #pragma unroll
    for (int i = 0; i < 8; i++) {
        int f = tid + i*256;
        int kp = f & 31, n = f >> 5;
        oH[(size_t)(n0 + n)*KP + kp0 + kp] = sh[n*33 + kp];
    }
}

// ========= fp16-split mma.sync GEMM, 3-stage cp.async + ldmatrix ===============
// OUT: 0 fp32 C, 1 packed hi/lo, 2 qkv-mode. BPASS: 2 = A split; 1 = single.
#define AU 20
#define NST 3   // pipeline stages

template<int OUT, int EPI, bool GUARD, int NI, int BPASS>
__global__ void __launch_bounds__(256, 2)
gemm_pk(int M, int N, int K,
        const uint32_t* __restrict__ aH, const uint32_t* __restrict__ aL,
        const uint32_t* __restrict__ bH,
        float* __restrict__ C, int ldc,
        uint32_t* __restrict__ oH, uint32_t* __restrict__ oL,
        const float* __restrict__ bias)
{
    constexpr int NTILE = 32*NI;
    extern __shared__ uint32_t su[];
    const uint32_t sb = (uint32_t)__cvta_generic_to_shared(su);
    const uint32_t sbAH = sb;
    const uint32_t sbAL = sb + NST*128*AU*4;                       // valid if BPASS>=2
    const uint32_t sbBH = sb + (BPASS >= 2 ? 2 : 1)*NST*128*AU*4;

    const int KP   = K >> 1;
    const int tid  = threadIdx.x;
    const int wid  = tid >> 5, lane = tid & 31;
    const int g    = lane >> 2, t = lane & 3;
    const int bm   = (BPASS == 1 ? blockIdx.x : blockIdx.y) * 128;
    const int bn   = (BPASS == 1 ? blockIdx.y : blockIdx.x) * NTILE;
    const int m0   = (wid >> 2) * 64, n0 = (wid & 3) * (8*NI);

    const int lane15 = lane & 15;
    const uint32_t aoff = (uint32_t)(lane15*AU + ((lane & 16) ? 4 : 0))*4;
    const int lbn = (lane & 7) + ((lane & 16) ? 8 : 0);
    const uint32_t boff = (uint32_t)(lbn*AU + ((lane & 8) ? 4 : 0))*4;

    float c[4][NI][4];
    #pragma unroll
    for (int mi = 0; mi < 4; mi++)
        #pragma unroll
        for (int ni = 0; ni < NI; ni++)
            #pragma unroll
            for (int j = 0; j < 4; j++) c[mi][ni][j] = 0.f;

    const int NKT = K >> 5;

    auto load_tile = [&](int kt, int st) {
        const int kp0 = kt << 4;
        #pragma unroll
        for (int i = 0; i < 2; i++) {
            int f = tid + i*256;
            int r = f >> 2, cc = (f & 3) << 2;
            size_t go = (size_t)(bm + r)*KP + kp0 + cc;
            uint32_t so = (uint32_t)((st*128 + r)*AU + cc)*4;
            cpa16(sbAH + so, aH + go);
            if (BPASS >= 2) cpa16(sbAL + so, aL + go);
        }
        #pragma unroll
        for (int i = 0; i < NI/2; i++) {
            int f = tid + i*256;
            int n = f >> 2, cc = (f & 3) << 2;
            size_t go = (size_t)(bn + n)*KP + kp0 + cc;
            cpa16(sbBH + (uint32_t)((st*NTILE + n)*AU + cc)*4, bH + go);
        }
        CP_COMMIT();
    };

    // prologue: fill NST-1 stages
    load_tile(0, 0);
    load_tile(1, 1);

    for (int kt = 0; kt < NKT; kt++) {
        const int st = kt % NST;
        // ensure load kt complete (keep newest group pending if one exists)
        if (kt + 1 < NKT) {
            asm volatile("cp.async.wait_group 1;" ::: "memory");
        } else {
            asm volatile("cp.async.wait_group 0;" ::: "memory");
        }
        __syncthreads();   // data visible + stage (kt-1)%NST free across all warps

        if (kt + NST - 1 < NKT)
            load_tile(kt + NST - 1, (kt + NST - 1) % NST);

        const uint32_t aHb = sbAH + (uint32_t)(st*128*AU)*4;
        const uint32_t aLb = sbAL + (uint32_t)(st*128*AU)*4;
        const uint32_t bHb = sbBH + (uint32_t)(st*NTILE*AU)*4;

        #pragma unroll
        for (int ks = 0; ks < 2; ks++) {
            const int kb = ks*8;
            uint32_t bh[NI][2];
            #pragma unroll
            for (int np = 0; np < NI/2; np++) {
                LDSM_X4(bh[2*np][0], bh[2*np][1], bh[2*np+1][0], bh[2*np+1][1],
                        bHb + (uint32_t)((n0 + np*16)*AU + kb)*4 + boff);
            }
            #pragma unroll
            for (int mi = 0; mi < 4; mi++) {
                const uint32_t abase = (uint32_t)((m0 + mi*16)*AU + kb)*4;
                uint32_t ah[4], al[4];
                LDSM_X4(ah[0], ah[1], ah[2], ah[3], aHb + abase + aoff);
                if (BPASS >= 2) LDSM_X4(al[0], al[1], al[2], al[3], aLb + abase + aoff);
                #pragma unroll
                for (int ni = 0; ni < NI; ni++) {
                    MMA16(c[mi][ni], ah, bh[ni]);
                    if (BPASS >= 2) MMA16(c[mi][ni], al, bh[ni]);
                }
            }
        }
    }

    const int KP2 = (OUT == 2) ? 512 : (N >> 1);
    #pragma unroll
    for (int mi = 0; mi < 4; mi++) {
        const int r0 = bm + m0 + mi*16 + g;
        #pragma unroll
        for (int ni = 0; ni < NI; ni++) {
            const int c0 = bn + n0 + ni*8 + t*2;
            #pragma unroll
            for (int half = 0; half < 2; half++) {
                const int gr = r0 + half*8;
                float v0 = c[mi][ni][2*half + 0];
                float v1 = c[mi][ni][2*half + 1];
                if (EPI >= 1) { v0 += bias[c0]; v1 += bias[c0 + 1]; }
                if (EPI == 2) {
                    v0 = 0.5f*v0*(1.f + erff(v0*0.70710678118654752f));
                    v1 = 0.5f*v1*(1.f + erff(v1*0.70710678118654752f));
                }
                if (OUT == 0) {
                    if (!GUARD || c0 < N)     C[(size_t)gr*ldc + c0]     = v0;
                    if (!GUARD || c0 + 1 < N) C[(size_t)gr*ldc + c0 + 1] = v1;
                } else if (OUT == 1) {
                    uint32_t h, l;
                    hpack(v0, v1, h, l);
                    oH[(size_t)gr*KP2 + (c0 >> 1)] = h;
                    oL[(size_t)gr*KP2 + (c0 >> 1)] = l;
                } else {
                    if (c0 < 1024) {
                        uint32_t h, l;
                        hpack(v0, v1, h, l);
                        oH[(size_t)gr*512 + (c0 >> 1)] = h;
                        oL[(size_t)gr*512 + (c0 >> 1)] = l;
                    } else {
                        C[(size_t)gr*512 + (c0 - 1024)]     = v0;
                        C[(size_t)gr*512 + (c0 - 1024) + 1] = v1;
                    }
                }
            }
        }
    }
}

// ---------------- embedding ----------------
__global__ void embed_kernel(const int* __restrict__ ids,
                             const float* __restrict__ tok,
                             const float* __restrict__ pos) {
    const int row = blockIdx.x;
    const int t   = row % T_;
    const int id  = ids[row];
    const int tid = threadIdx.x;
    const float sc = 22.62741699796952f;
    const int d = tid*2;
    float e0 = (id == PAD_) ? 0.f : tok[(size_t)id*D_ + d];
    float e1 = (id == PAD_) ? 0.f : tok[(size_t)id*D_ + d + 1];
    float v0 = e0*sc + pos[(size_t)t*D_ + d];
    float v1 = e1*sc + pos[(size_t)t*D_ + d + 1];
    *reinterpret_cast<float2*>(g_x + (size_t)row*D_ + d) = make_float2(v0, v1);
    uint32_t h, l;
    hpack(v0, v1, h, l);
    g_xH[row*256 + tid] = h;
    g_xL[row*256 + tid] = l;
}

// ================ fattn2: fp16x2 flash attention (ldmatrix) ====================
#define FA2_SMEM (4*2304*4)

__device__ __forceinline__ void fa2_tile(
    uint32_t* VH, uint32_t sbase, int qb, int b, int h, int tid)
{
    const int w = tid >> 5, lane = tid & 31;
    const int g = lane >> 2, t = lane & 3;
    const int mr = w*16;
    const uint32_t sQH = sbase, sQL = sbase + 9216;
    const uint32_t sKH = sbase + 18432, sVH = sbase + 27648;

    const int lane15 = lane & 15;
    const uint32_t qoff = (uint32_t)(lane15*36 + ((lane & 16) ? 4 : 0))*4;
    const int lbn = (lane & 7) + ((lane & 16) ? 8 : 0);
    const uint32_t koff = (uint32_t)(lbn*36 + ((lane & 8) ? 4 : 0))*4;

    #pragma unroll
    for (int i = 0; i < 4; i++) {
        int idx = tid + i*128;
        int r = idx >> 3, c4 = (idx & 7) << 2;
        size_t go = ((size_t)(b*1024 + qb*64 + r) << 9) + h*32 + c4;
        cpa16(sQH + (uint32_t)(r*36 + c4)*4, g_qkpH + go);
        cpa16(sQL + (uint32_t)(r*36 + c4)*4, g_qkpL + go);
    }
    CP_COMMIT();

    float m0 = -CUDART_INF_F, m1 = -CUDART_INF_F, l0 = 0.f, l1 = 0.f;
    float o[8][4];
    #pragma unroll
    for (int nb = 0; nb < 8; nb++)
        #pragma unroll
        for (int j = 0; j < 4; j++) o[nb][j] = 0.f;

    const int nkt = qb + 1;
    for (int kt = 0; kt < nkt; kt++) {
        __syncthreads();
        #pragma unroll
        for (int i = 0; i < 4; i++) {
            int idx = tid + i*128;
            int r = idx >> 3, c4 = (idx & 7) << 2;
            size_t go = ((size_t)(b*1024 + kt*64 + r) << 9) + 256 + h*32 + c4;
            cpa16(sKH + (uint32_t)(r*36 + c4)*4, g_qkpH + go);
        }
        CP_COMMIT();
        #pragma unroll
        for (int i = 0; i < 16; i++) {
            int idx = tid + i*128;
            int n = idx & 63, r = idx >> 6;
            size_t base = ((size_t)(b*1024 + kt*64 + 2*r) << 9) + h*64 + n;
            VH[n*36 + r] = hpack1(g_v[base], g_v[base + 512]);
        }
        asm volatile("cp.async.wait_group 0;" ::: "memory");
        __syncthreads();

        float sc[8][4];
        #pragma unroll
        for (int ni = 0; ni < 8; ni++)
            #pragma unroll
            for (int j = 0; j < 4; j++) sc[ni][j] = 0.f;
        #pragma unroll
        for (int j = 0; j < 4; j++) {
            const uint32_t qbase = (uint32_t)(mr*36 + j*8)*4;
            uint32_t ah[4], al[4];
            LDSM_X4(ah[0], ah[1], ah[2], ah[3], sQH + qbase + qoff);
            LDSM_X4(al[0], al[1], al[2], al[3], sQL + qbase + qoff);
            uint32_t kf[8][2];
            #pragma unroll
            for (int np = 0; np < 4; np++) {
                LDSM_X4(kf[2*np][0], kf[2*np][1], kf[2*np+1][0], kf[2*np+1][1],
                        sKH + (uint32_t)(np*16*36 + j*8)*4 + koff);
            }
            #pragma unroll
            for (int ni = 0; ni < 8; ni++) {
                MMA16(sc[ni], ah, kf[ni]);
                MMA16(sc[ni], al, kf[ni]);
            }
        }
        const int qr0 = qb*64 + mr + g;
        const bool diag = (kt == qb);
        #pragma unroll
        for (int ni = 0; ni < 8; ni++)
            #pragma unroll
            for (int cc = 0; cc < 4; cc++) {
                float v = sc[ni][cc]*0.125f;
                if (diag) {
                    int key = kt*64 + ni*8 + 2*t + (cc & 1);
                    int qr = qr0 + (cc >> 1)*8;
                    if (key > qr) v = -CUDART_INF_F;
                }
                sc[ni][cc] = v;
            }

        float mx0 = -CUDART_INF_F, mx1 = -CUDART_INF_F;
        #pragma unroll
        for (int ni = 0; ni < 8; ni++) {
            mx0 = fmaxf(mx0, fmaxf(sc[ni][0], sc[ni][1]));
            mx1 = fmaxf(mx1, fmaxf(sc[ni][2], sc[ni][3]));
        }
        mx0 = fmaxf(mx0, __shfl_xor_sync(0xffffffffu, mx0, 1));
        mx0 = fmaxf(mx0, __shfl_xor_sync(0xffffffffu, mx0, 2));
        mx1 = fmaxf(mx1, __shfl_xor_sync(0xffffffffu, mx1, 1));
        mx1 = fmaxf(mx1, __shfl_xor_sync(0xffffffffu, mx1, 2));
        const float mn0 = fmaxf(m0, mx0), mn1 = fmaxf(m1, mx1);
        const float cr0 = fexp(m0 - mn0),  cr1 = fexp(m1 - mn1);
        float s0 = 0.f, s1 = 0.f;
        #pragma unroll
        for (int ni = 0; ni < 8; ni++) {
            float p0 = fexp(sc[ni][0] - mn0);
            float p1 = fexp(sc[ni][1] - mn0);
            float p2 = fexp(sc[ni][2] - mn1);
            float p3 = fexp(sc[ni][3] - mn1);
            sc[ni][0] = p0; sc[ni][1] = p1; sc[ni][2] = p2; sc[ni][3] = p3;
            s0 += p0 + p1; s1 += p2 + p3;
        }
        s0 += __shfl_xor_sync(0xffffffffu, s0, 1);
        s0 += __shfl_xor_sync(0xffffffffu, s0, 2);
        s1 += __shfl_xor_sync(0xffffffffu, s1, 1);
        s1 += __shfl_xor_sync(0xffffffffu, s1, 2);
        l0 = l0*cr0 + s0; l1 = l1*cr1 + s1;
        m0 = mn0; m1 = mn1;
        #pragma unroll
        for (int nb = 0; nb < 8; nb++) {
            o[nb][0] *= cr0; o[nb][1] *= cr0;
            o[nb][2] *= cr1; o[nb][3] *= cr1;
        }

        #pragma unroll
        for (int jj = 0; jj < 4; jj++) {
            uint32_t ah[4], al[4];
            hpack(sc[2*jj][0],   sc[2*jj][1],   ah[0], al[0]);
            hpack(sc[2*jj][2],   sc[2*jj][3],   ah[1], al[1]);
            hpack(sc[2*jj+1][0], sc[2*jj+1][1], ah[2], al[2]);
            hpack(sc[2*jj+1][2], sc[2*jj+1][3], ah[3], al[3]);
            uint32_t vf[8][2];
            #pragma unroll
            for (int np = 0; np < 4; np++) {
                LDSM_X4(vf[2*np][0], vf[2*np][1], vf[2*np+1][0], vf[2*np+1][1],
                        sVH + (uint32_t)(np*16*36 + jj*8)*4 + koff);
            }
            #pragma unroll
            for (int nb = 0; nb < 8; nb++) {
                MMA16(o[nb], ah, vf[nb]);
                MMA16(o[nb], al, vf[nb]);
            }
        }
    }

    const float inv0 = 1.f / l0, inv1 = 1.f / l1;
    const int gr0 = b*1024 + qb*64 + mr + g;
    #pragma unroll
    for (int nb = 0; nb < 8; nb++) {
        const int kp = h*32 + nb*4 + t;
        uint32_t hh, ll;
        hpack(o[nb][0]*inv0, o[nb][1]*inv0, hh, ll);
        g_cH[gr0*256 + kp] = hh;
        g_cL[gr0*256 + kp] = ll;
        hpack(o[nb][2]*inv1, o[nb][3]*inv1, hh, ll);
        g_cH[(gr0 + 8)*256 + kp] = hh;
        g_cL[(gr0 + 8)*256 + kp] = ll;
    }
}

__global__ void __launch_bounds__(128) fattn2_kernel() {
    extern __shared__ uint32_t fsm[];
    uint32_t* VH = fsm + 3*2304;
    const uint32_t sbase = (uint32_t)__cvta_generic_to_shared(fsm);

    const int p  = blockIdx.x;
    const int bh = blockIdx.y;
    const int b = bh >> 3, h = bh & 7;
    const int tid = threadIdx.x;

    fa2_tile(VH, sbase, p,      b, h, tid);
    __syncthreads();
    fa2_tile(VH, sbase, 15 - p, b, h, tid);
}

// ------------- fused residual add + LayerNorm -> fp32 x AND packed x -----------
__global__ void __launch_bounds__(256) add_ln_kernel(const float* __restrict__ g,
                                                     const float* __restrict__ bta) {
    const int row = blockIdx.x;
    float* x = g_x + (size_t)row*D_;
    const float* dl = g_tmp + (size_t)row*D_;
    const int tid = threadIdx.x;
    __shared__ float red[256];

    float2 xv = reinterpret_cast<const float2*>(x)[tid];
    float2 dv = reinterpret_cast<const float2*>(dl)[tid];
    float v0 = xv.x + dv.x;
    float v1 = xv.y + dv.y;

    red[tid] = v0 + v1; __syncthreads();
    for (int off = 128; off > 0; off >>= 1) {
        if (tid < off) red[tid] += red[tid + off];
        __syncthreads();
    }
    const float mu = red[0] * (1.f/512.f); __syncthreads();

    float d0 = v0 - mu, d1 = v1 - mu;
    red[tid] = d0*d0 + d1*d1; __syncthreads();
    for (int off = 128; off > 0; off >>= 1) {
        if (tid < off) red[tid] += red[tid + off];
        __syncthreads();
    }
    const float inv = rsqrtf(red[0]*(1.f/512.f) + 1e-5f);

    const int d = tid*2;
    float o0 = d0*inv*g[d]     + bta[d];
    float o1 = d1*inv*g[d + 1] + bta[d + 1];
    reinterpret_cast<float2*>(x)[tid] = make_float2(o0, o1);
    uint32_t h, l;
    hpack(o0, o1, h, l);
    g_xH[row*256 + tid] = h;
    g_xL[row*256 + tid] = l;
}

// ---------------- launch ----------------
#define SMEM_NI4B2 (NST*(2*128*AU + 128*AU)*4)   // 92160
#define SMEM_NI2B2 (NST*(2*128*AU + 64*AU)*4)    // 76800
#define SMEM_NI4B1 (NST*(128*AU + 128*AU)*4)     // 61440

extern "C" void kernel_launch(void* const* d_in, const int* in_sizes, int n_in,
                              void* d_out, int out_size) {
    const int*   ids  = (const int*)  d_in[0];
    const float* tok  = (const float*)d_in[1];
    const float* pos  = (const float*)d_in[2];
    const float* WQ   = (const float*)d_in[3];
    const float* WK   = (const float*)d_in[4];
    const float* WV   = (const float*)d_in[5];
    const float* WO   = (const float*)d_in[6];
    const float* ln1g = (const float*)d_in[7];
    const float* ln1b = (const float*)d_in[8];
    const float* fc1w = (const float*)d_in[9];
    const float* fc1b = (const float*)d_in[10];
    const float* fc2w = (const float*)d_in[11];
    const float* fc2b = (const float*)d_in[12];
    const float* ln2g = (const float*)d_in[13];
    const float* ln2b = (const float*)d_in[14];
    const float* lmh  = (const float*)d_in[15];
    float* out = (float*)d_out;

    float *pv, *ptmp;
    cudaGetSymbolAddress((void**)&pv,   g_v);
    cudaGetSymbolAddress((void**)&ptmp, g_tmp);

    uint32_t *xH, *xL, *cH, *cL, *fH, *fL, *qpH, *qpL;
    uint32_t *qkH, *woH, *f1H, *f2H, *lmH;
    cudaGetSymbolAddress((void**)&xH,  g_xH);
    cudaGetSymbolAddress((void**)&xL,  g_xL);
    cudaGetSymbolAddress((void**)&cH,  g_cH);
    cudaGetSymbolAddress((void**)&cL,  g_cL);
    cudaGetSymbolAddress((void**)&fH,  g_fH);
    cudaGetSymbolAddress((void**)&fL,  g_fL);
    cudaGetSymbolAddress((void**)&qpH, g_qkpH);
    cudaGetSymbolAddress((void**)&qpL, g_qkpL);
    cudaGetSymbolAddress((void**)&qkH, g_wqkvH);
    cudaGetSymbolAddress((void**)&woH, g_woH);
    cudaGetSymbolAddress((void**)&f1H, g_fc1H);
    cudaGetSymbolAddress((void**)&f2H, g_fc2H);
    cudaGetSymbolAddress((void**)&lmH, g_lmhH);

    cudaFuncSetAttribute((const void*)fattn2_kernel,          cudaFuncAttributeMaxDynamicSharedMemorySize, FA2_SMEM);
    cudaFuncSetAttribute((const void*)gemm_pk<2,0,false,4,2>, cudaFuncAttributeMaxDynamicSharedMemorySize, SMEM_NI4B2);
    cudaFuncSetAttribute((const void*)gemm_pk<0,0,false,2,2>, cudaFuncAttributeMaxDynamicSharedMemorySize, SMEM_NI2B2);
    cudaFuncSetAttribute((const void*)gemm_pk<1,2,false,4,2>, cudaFuncAttributeMaxDynamicSharedMemorySize, SMEM_NI4B2);
    cudaFuncSetAttribute((const void*)gemm_pk<0,1,false,2,2>, cudaFuncAttributeMaxDynamicSharedMemorySize, SMEM_NI2B2);
    cudaFuncSetAttribute((const void*)gemm_pk<0,0,true,4,1>,  cudaFuncAttributeMaxDynamicSharedMemorySize, SMEM_NI4B1);

    embed_kernel<<<BT_, 256>>>(ids, tok, pos);                           // 1
    prepack_qkvw<<<dim3(QKVW_/64, 8, L_), 256>>>(WQ, WK, WV);            // 2
    prepack_small<<<dim3(32, 32, 3*L_), 256>>>(WO, fc1w, fc2w);          // 3

    for (int l = 0; l < L_; l++) {
        gemm_pk<2,0,false,4,2><<<dim3(QKVW_/128, BT_/128), 256, SMEM_NI4B2>>>(
            BT_, QKVW_, D_, xH, xL,
            qkH + (size_t)l*QKVW_*256,
            pv, 512, qpH, qpL, nullptr);                                 // 4 (l=0)

        fattn2_kernel<<<dim3(8, B_*H_), 128, FA2_SMEM>>>();              // 5 (l=0)

        gemm_pk<0,0,false,2,2><<<dim3(D_/64, BT_/128), 256, SMEM_NI2B2>>>(
            BT_, D_, D_, cH, cL,
            woH + (size_t)l*D_*256,
            ptmp, D_, nullptr, nullptr, nullptr);                        // 6 (l=0)

        add_ln_kernel<<<BT_, 256>>>(ln1g + l*D_, ln1b + l*D_);

        gemm_pk<1,2,false,4,2><<<dim3(DFF_/128, BT_/128), 256, SMEM_NI4B2>>>(
            BT_, DFF_, D_, xH, xL,
            f1H + (size_t)l*DFF_*256,
            nullptr, 0, fH, fL, fc1b + l*DFF_);

        gemm_pk<0,1,false,2,2><<<dim3(D_/64, BT_/128), 256, SMEM_NI2B2>>>(
            BT_, D_, DFF_, fH, fL,
            f2H + (size_t)l*D_*1024,
            ptmp, D_, nullptr, nullptr, fc2b + l*D_);

        add_ln_kernel<<<BT_, 256>>>(ln2g + l*D_, ln2b + l*D_);
    }

    prepack_b_hi<<<dim3(VP_/64, 8), 256>>>(lmh, lmH, D_, V_, VP_);

    // lm_head: fp16x1, grid swapped (M fast) for B L2-reuse
    gemm_pk<0,0,true,4,1><<<dim3(BT_/128, VP_/128), 256, SMEM_NI4B1>>>(
        BT_, V_, D_, xH, nullptr, lmH, out, V_, nullptr, nullptr, nullptr);
}

// round 16
// speedup vs baseline: 6.3841x; 1.2498x over previous
#include <cuda_runtime.h>
#include <cuda_fp16.h>
#include <math.h>
#include <math_constants.h>
#include <stdint.h>

#define B_   2
#define T_   1024
#define D_   512
#define H_   8
#define DK_  64
#define DFF_ 2048
#define L_   6
#define V_   50257
#define VP_  50304
#define PAD_ 50256
#define BT_  (B_*T_)
#define QKVW_ (3*D_)

// ---------------- scratch ----------------
__device__ float g_x[BT_*D_];
__device__ float g_v[BT_*D_];
__device__ float g_tmp[BT_*D_];

// single-fp16 packed activations (u32 = half2 of adjacent k)
__device__ uint32_t g_xH[BT_*256];
__device__ uint32_t g_cH[BT_*256];
__device__ uint32_t g_fH[BT_*1024];
__device__ uint32_t g_qkpH[BT_*512];
// packed weights (hi only)
__device__ uint32_t g_wqkvH[L_*QKVW_*256];
__device__ uint32_t g_woH[L_*D_*256];
__device__ uint32_t g_fc1H[L_*DFF_*256];
__device__ uint32_t g_fc2H[L_*D_*1024];
__device__ uint32_t g_lmhH[(size_t)VP_*256];

// ---------------- helpers ----------------
__device__ __forceinline__ uint32_t hpack1(float x0, float x1) {
    return ((uint32_t)__half_as_ushort(__float2half_rn(x1)) << 16)
         |  (uint32_t)__half_as_ushort(__float2half_rn(x0));
}

__device__ __forceinline__ float fexp(float x) {
    x = fmaxf(x, -87.0f);
    float t = fmaf(x, 1.4426950408889634f, 12582912.0f);
    float r = t - 12582912.0f;
    float f = fmaf(x, 1.4426950408889634f, -r);
    float p =        1.3333558e-3f;
    p = fmaf(p, f, 9.6181291e-3f);
    p = fmaf(p, f, 5.5504109e-2f);
    p = fmaf(p, f, 2.4022651e-1f);
    p = fmaf(p, f, 6.9314718e-1f);
    p = fmaf(p, f, 1.0f);
    int e = (__float_as_int(t) + 127) << 23;
    return p * __int_as_float(e);
}

#define MMA16(cc, a, b) \
    asm volatile("mma.sync.aligned.m16n8k16.row.col.f32.f16.f16.f32 " \
        "{%0,%1,%2,%3}, {%4,%5,%6,%7}, {%8,%9}, {%0,%1,%2,%3};" \
        : "+f"((cc)[0]), "+f"((cc)[1]), "+f"((cc)[2]), "+f"((cc)[3]) \
        : "r"((a)[0]), "r"((a)[1]), "r"((a)[2]), "r"((a)[3]), \
          "r"((b)[0]), "r"((b)[1]))

#define LDSM_X4(r0, r1, r2, r3, addr) \
    asm volatile("ldmatrix.sync.aligned.m8n8.x4.shared.b16 {%0,%1,%2,%3}, [%4];" \
        : "=r"(r0), "=r"(r1), "=r"(r2), "=r"(r3) : "r"(addr))

__device__ __forceinline__ void cpa16(uint32_t dst, const void* src) {
    asm volatile("cp.async.cg.shared.global [%0], [%1], 16;" :: "r"(dst), "l"(src));
}
#define CP_COMMIT() asm volatile("cp.async.commit_group;" ::: "memory")

// ================ prepack kernels (coalesced transpose, hi-only) ===============
__global__ void prepack_b_hi(const float* __restrict__ W, uint32_t* __restrict__ oH,
                             int K, int N, int Npad) {
    __shared__ uint32_t sh[64*33];
    const int KP = K >> 1;
    const int n0 = blockIdx.x * 64, kp0 = blockIdx.y * 32;
    const int tid = threadIdx.x;
    #pragma unroll
    for (int i = 0; i < 8; i++) {
        int f = tid + i*256;
        int n = f & 63, kp = f >> 6;
        int gn = n0 + n;
        float x0 = 0.f, x1 = 0.f;
        if (gn < N) {
            int k2 = (kp0 + kp) * 2;
            x0 = W[(size_t)k2*N + gn];
            x1 = W[(size_t)(k2 + 1)*N + gn];
        }
        sh[n*33 + kp] = hpack1(x0, x1);
    }
    __syncthreads();
    #pragma unroll
    for (int i = 0; i < 8; i++) {
        int f = tid + i*256;
        int kp = f & 31, n = f >> 5;
        oH[(size_t)(n0 + n)*KP + kp0 + kp] = sh[n*33 + kp];
    }
}

__global__ void prepack_qkvw(const float* __restrict__ WQ,
                             const float* __restrict__ WK,
                             const float* __restrict__ WV) {
    __shared__ uint32_t sh[64*33];
    const int l = blockIdx.z;
    const int n0 = blockIdx.x*64, kp0 = blockIdx.y*32;
    const int tid = threadIdx.x;
    #pragma unroll
    for (int i = 0; i < 8; i++) {
        int f = tid + i*256;
        int n = f & 63, kp = f >> 6;
        int gn = n0 + n;
        int part = gn >> 9, hh = (gn >> 6) & 7, kk = gn & 63;
        const float* W = part == 0 ? WQ : (part == 1 ? WK : WV);
        size_t base = (((size_t)l*H_ + hh)*D_ + 2*(kp0 + kp))*DK_ + kk;
        sh[n*33 + kp] = hpack1(W[base], W[base + DK_]);
    }
    __syncthreads();
    #pragma unroll
    for (int i = 0; i < 8; i++) {
        int f = tid + i*256;
        int kp = f & 31, n = f >> 5;
        g_wqkvH[(size_t)l*QKVW_*256 + (size_t)(n0 + n)*256 + kp0 + kp] = sh[n*33 + kp];
    }
}

__global__ void prepack_small(const float* __restrict__ WO,
                              const float* __restrict__ F1,
                              const float* __restrict__ F2) {
    __shared__ uint32_t sh[64*33];
    const int z = blockIdx.z;
    const int type = z / L_, l = z % L_;
    int K, N; const float* W; uint32_t* oH;
    if (type == 0)      { K = D_;   N = D_;   W = WO + (size_t)l*D_*D_;   oH = g_woH  + (size_t)l*D_*256; }
    else if (type == 1) { K = D_;   N = DFF_; W = F1 + (size_t)l*D_*DFF_; oH = g_fc1H + (size_t)l*DFF_*256; }
    else                { K = DFF_; N = D_;   W = F2 + (size_t)l*DFF_*D_; oH = g_fc2H + (size_t)l*D_*1024; }
    const int KP = K >> 1;
    const int n0 = blockIdx.x*64, kp0 = blockIdx.y*32;
    if (n0 >= N || kp0 >= KP) return;
    const int tid = threadIdx.x;
    #pragma unroll
    for (int i = 0; i < 8; i++) {
        int f = tid + i*256;
        int n = f & 63, kp = f >> 6;
        int k2 = (kp0 + kp)*2;
        sh[n*33 + kp] = hpack1(W[(size_t)k2*N + n0 + n], W[(size_t)(k2+1)*N + n0 + n]);
    }
    __syncthreads();
    #pragma unroll
    for (int i = 0; i < 8; i++) {
        int f = tid + i*256;
        int kp = f & 31, n = f >> 5;
        oH[(size_t)(n0 + n)*KP + kp0 + kp] = sh[n*33 + kp];
    }
}

// ========= single-pass fp16 mma.sync GEMM, 3-stage cp.async + ldmatrix =========
// OUT: 0 fp32 C, 1 packed, 2 qkv-mode (c<1024 packed Q/K, else fp32 V)
// SWAP: grid dims swapped (bm from x) for L2 B-reuse on huge-N GEMMs.
#define AU 20
#define NST 3

template<int OUT, int EPI, bool GUARD, int NI, bool SWAP>
__global__ void __launch_bounds__(256, 2)
gemm_pk(int M, int N, int K,
        const uint32_t* __restrict__ aH,
        const uint32_t* __restrict__ bH,
        float* __restrict__ C, int ldc,
        uint32_t* __restrict__ oH,
        const float* __restrict__ bias)
{
    constexpr int NTILE = 32*NI;
    extern __shared__ uint32_t su[];
    const uint32_t sb = (uint32_t)__cvta_generic_to_shared(su);
    const uint32_t sbAH = sb;
    const uint32_t sbBH = sb + NST*128*AU*4;

    const int KP   = K >> 1;
    const int tid  = threadIdx.x;
    const int wid  = tid >> 5, lane = tid & 31;
    const int g    = lane >> 2, t = lane & 3;
    const int bm   = (SWAP ? blockIdx.x : blockIdx.y) * 128;
    const int bn   = (SWAP ? blockIdx.y : blockIdx.x) * NTILE;
    const int m0   = (wid >> 2) * 64, n0 = (wid & 3) * (8*NI);

    const int lane15 = lane & 15;
    const uint32_t aoff = (uint32_t)(lane15*AU + ((lane & 16) ? 4 : 0))*4;
    const int lbn = (lane & 7) + ((lane & 16) ? 8 : 0);
    const uint32_t boff = (uint32_t)(lbn*AU + ((lane & 8) ? 4 : 0))*4;

    float c[4][NI][4];
    #pragma unroll
    for (int mi = 0; mi < 4; mi++)
        #pragma unroll
        for (int ni = 0; ni < NI; ni++)
            #pragma unroll
            for (int j = 0; j < 4; j++) c[mi][ni][j] = 0.f;

    const int NKT = K >> 5;

    auto load_tile = [&](int kt, int st) {
        const int kp0 = kt << 4;
        #pragma unroll
        for (int i = 0; i < 2; i++) {
            int f = tid + i*256;
            int r = f >> 2, cc = (f & 3) << 2;
            size_t go = (size_t)(bm + r)*KP + kp0 + cc;
            cpa16(sbAH + (uint32_t)((st*128 + r)*AU + cc)*4, aH + go);
        }
        #pragma unroll
        for (int i = 0; i < NI/2; i++) {
            int f = tid + i*256;
            int n = f >> 2, cc = (f & 3) << 2;
            size_t go = (size_t)(bn + n)*KP + kp0 + cc;
            cpa16(sbBH + (uint32_t)((st*NTILE + n)*AU + cc)*4, bH + go);
        }
        CP_COMMIT();
    };

    load_tile(0, 0);
    load_tile(1, 1);

    for (int kt = 0; kt < NKT; kt++) {
        const int st = kt % NST;
        if (kt + 1 < NKT) {
            asm volatile("cp.async.wait_group 1;" ::: "memory");
        } else {
            asm volatile("cp.async.wait_group 0;" ::: "memory");
        }
        __syncthreads();

        if (kt + NST - 1 < NKT)
            load_tile(kt + NST - 1, (kt + NST - 1) % NST);

        const uint32_t aHb = sbAH + (uint32_t)(st*128*AU)*4;
        const uint32_t bHb = sbBH + (uint32_t)(st*NTILE*AU)*4;

        #pragma unroll
        for (int ks = 0; ks < 2; ks++) {
            const int kb = ks*8;
            uint32_t bh[NI][2];
            #pragma unroll
            for (int np = 0; np < NI/2; np++) {
                LDSM_X4(bh[2*np][0], bh[2*np][1], bh[2*np+1][0], bh[2*np+1][1],
                        bHb + (uint32_t)((n0 + np*16)*AU + kb)*4 + boff);
            }
            #pragma unroll
            for (int mi = 0; mi < 4; mi++) {
                uint32_t ah[4];
                LDSM_X4(ah[0], ah[1], ah[2], ah[3],
                        aHb + (uint32_t)((m0 + mi*16)*AU + kb)*4 + aoff);
                #pragma unroll
                for (int ni = 0; ni < NI; ni++)
                    MMA16(c[mi][ni], ah, bh[ni]);
            }
        }
    }

    const int KP2 = (OUT == 2) ? 512 : (N >> 1);
    #pragma unroll
    for (int mi = 0; mi < 4; mi++) {
        const int r0 = bm + m0 + mi*16 + g;
        #pragma unroll
        for (int ni = 0; ni < NI; ni++) {
            const int c0 = bn + n0 + ni*8 + t*2;
            #pragma unroll
            for (int half = 0; half < 2; half++) {
                const int gr = r0 + half*8;
                float v0 = c[mi][ni][2*half + 0];
                float v1 = c[mi][ni][2*half + 1];
                if (EPI >= 1) { v0 += bias[c0]; v1 += bias[c0 + 1]; }
                if (EPI == 2) {
                    v0 = 0.5f*v0*(1.f + erff(v0*0.70710678118654752f));
                    v1 = 0.5f*v1*(1.f + erff(v1*0.70710678118654752f));
                }
                if (OUT == 0) {
                    if (!GUARD || c0 < N)     C[(size_t)gr*ldc + c0]     = v0;
                    if (!GUARD || c0 + 1 < N) C[(size_t)gr*ldc + c0 + 1] = v1;
                } else if (OUT == 1) {
                    oH[(size_t)gr*KP2 + (c0 >> 1)] = hpack1(v0, v1);
                } else {
                    if (c0 < 1024) {
                        oH[(size_t)gr*512 + (c0 >> 1)] = hpack1(v0, v1);
                    } else {
                        C[(size_t)gr*512 + (c0 - 1024)]     = v0;
                        C[(size_t)gr*512 + (c0 - 1024) + 1] = v1;
                    }
                }
            }
        }
    }
}

// ---------------- embedding ----------------
__global__ void embed_kernel(const int* __restrict__ ids,
                             const float* __restrict__ tok,
                             const float* __restrict__ pos) {
    const int row = blockIdx.x;
    const int t   = row % T_;
    const int id  = ids[row];
    const int tid = threadIdx.x;
    const float sc = 22.62741699796952f;
    const int d = tid*2;
    float e0 = (id == PAD_) ? 0.f : tok[(size_t)id*D_ + d];
    float e1 = (id == PAD_) ? 0.f : tok[(size_t)id*D_ + d + 1];
    float v0 = e0*sc + pos[(size_t)t*D_ + d];
    float v1 = e1*sc + pos[(size_t)t*D_ + d + 1];
    *reinterpret_cast<float2*>(g_x + (size_t)row*D_ + d) = make_float2(v0, v1);
    g_xH[row*256 + tid] = hpack1(v0, v1);
}

// ================ fattn2: single-fp16 flash attention (ldmatrix) ===============
#define FA2_SMEM (3*2304*4)   // QH, KH, VH

__device__ __forceinline__ void fa2_tile(
    uint32_t* VH, uint32_t sbase, int qb, int b, int h, int tid)
{
    const int w = tid >> 5, lane = tid & 31;
    const int g = lane >> 2, t = lane & 3;
    const int mr = w*16;
    const uint32_t sQH = sbase;
    const uint32_t sKH = sbase + 9216, sVH = sbase + 18432;

    const int lane15 = lane & 15;
    const uint32_t qoff = (uint32_t)(lane15*36 + ((lane & 16) ? 4 : 0))*4;
    const int lbn = (lane & 7) + ((lane & 16) ? 8 : 0);
    const uint32_t koff = (uint32_t)(lbn*36 + ((lane & 8) ? 4 : 0))*4;

    #pragma unroll
    for (int i = 0; i < 4; i++) {
        int idx = tid + i*128;
        int r = idx >> 3, c4 = (idx & 7) << 2;
        size_t go = ((size_t)(b*1024 + qb*64 + r) << 9) + h*32 + c4;
        cpa16(sQH + (uint32_t)(r*36 + c4)*4, g_qkpH + go);
    }
    CP_COMMIT();

    float m0 = -CUDART_INF_F, m1 = -CUDART_INF_F, l0 = 0.f, l1 = 0.f;
    float o[8][4];
    #pragma unroll
    for (int nb = 0; nb < 8; nb++)
        #pragma unroll
        for (int j = 0; j < 4; j++) o[nb][j] = 0.f;

    const int nkt = qb + 1;
    for (int kt = 0; kt < nkt; kt++) {
        __syncthreads();
        #pragma unroll
        for (int i = 0; i < 4; i++) {
            int idx = tid + i*128;
            int r = idx >> 3, c4 = (idx & 7) << 2;
            size_t go = ((size_t)(b*1024 + kt*64 + r) << 9) + 256 + h*32 + c4;
            cpa16(sKH + (uint32_t)(r*36 + c4)*4, g_qkpH + go);
        }
        CP_COMMIT();
        #pragma unroll
        for (int i = 0; i < 16; i++) {
            int idx = tid + i*128;
            int n = idx & 63, r = idx >> 6;
            size_t base = ((size_t)(b*1024 + kt*64 + 2*r) << 9) + h*64 + n;
            VH[n*36 + r] = hpack1(g_v[base], g_v[base + 512]);
        }
        asm volatile("cp.async.wait_group 0;" ::: "memory");
        __syncthreads();

        // ---- S = Q K^T ----
        float sc[8][4];
        #pragma unroll
        for (int ni = 0; ni < 8; ni++)
            #pragma unroll
            for (int j = 0; j < 4; j++) sc[ni][j] = 0.f;
        #pragma unroll
        for (int j = 0; j < 4; j++) {
            uint32_t ah[4];
            LDSM_X4(ah[0], ah[1], ah[2], ah[3], sQH + (uint32_t)(mr*36 + j*8)*4 + qoff);
            uint32_t kf[8][2];
            #pragma unroll
            for (int np = 0; np < 4; np++) {
                LDSM_X4(kf[2*np][0], kf[2*np][1], kf[2*np+1][0], kf[2*np+1][1],
                        sKH + (uint32_t)(np*16*36 + j*8)*4 + koff);
            }
            #pragma unroll
            for (int ni = 0; ni < 8; ni++)
                MMA16(sc[ni], ah, kf[ni]);
        }
        const int qr0 = qb*64 + mr + g;
        const bool diag = (kt == qb);
        #pragma unroll
        for (int ni = 0; ni < 8; ni++)
            #pragma unroll
            for (int cc = 0; cc < 4; cc++) {
                float v = sc[ni][cc]*0.125f;
                if (diag) {
                    int key = kt*64 + ni*8 + 2*t + (cc & 1);
                    int qr = qr0 + (cc >> 1)*8;
                    if (key > qr) v = -CUDART_INF_F;
                }
                sc[ni][cc] = v;
            }

        float mx0 = -CUDART_INF_F, mx1 = -CUDART_INF_F;
        #pragma unroll
        for (int ni = 0; ni < 8; ni++) {
            mx0 = fmaxf(mx0, fmaxf(sc[ni][0], sc[ni][1]));
            mx1 = fmaxf(mx1, fmaxf(sc[ni][2], sc[ni][3]));
        }
        mx0 = fmaxf(mx0, __shfl_xor_sync(0xffffffffu, mx0, 1));
        mx0 = fmaxf(mx0, __shfl_xor_sync(0xffffffffu, mx0, 2));
        mx1 = fmaxf(mx1, __shfl_xor_sync(0xffffffffu, mx1, 1));
        mx1 = fmaxf(mx1, __shfl_xor_sync(0xffffffffu, mx1, 2));
        const float mn0 = fmaxf(m0, mx0), mn1 = fmaxf(m1, mx1);
        const float cr0 = fexp(m0 - mn0),  cr1 = fexp(m1 - mn1);
        float s0 = 0.f, s1 = 0.f;
        #pragma unroll
        for (int ni = 0; ni < 8; ni++) {
            float p0 = fexp(sc[ni][0] - mn0);
            float p1 = fexp(sc[ni][1] - mn0);
            float p2 = fexp(sc[ni][2] - mn1);
            float p3 = fexp(sc[ni][3] - mn1);
            sc[ni][0] = p0; sc[ni][1] = p1; sc[ni][2] = p2; sc[ni][3] = p3;
            s0 += p0 + p1; s1 += p2 + p3;
        }
        s0 += __shfl_xor_sync(0xffffffffu, s0, 1);
        s0 += __shfl_xor_sync(0xffffffffu, s0, 2);
        s1 += __shfl_xor_sync(0xffffffffu, s1, 1);
        s1 += __shfl_xor_sync(0xffffffffu, s1, 2);
        l0 = l0*cr0 + s0; l1 = l1*cr1 + s1;
        m0 = mn0; m1 = mn1;
        #pragma unroll
        for (int nb = 0; nb < 8; nb++) {
            o[nb][0] *= cr0; o[nb][1] *= cr0;
            o[nb][2] *= cr1; o[nb][3] *= cr1;
        }

        // ---- O += P V (P single fp16 in-register) ----
        #pragma unroll
        for (int jj = 0; jj < 4; jj++) {
            uint32_t ah[4];
            ah[0] = hpack1(sc[2*jj][0],   sc[2*jj][1]);
            ah[1] = hpack1(sc[2*jj][2],   sc[2*jj][3]);
            ah[2] = hpack1(sc[2*jj+1][0], sc[2*jj+1][1]);
            ah[3] = hpack1(sc[2*jj+1][2], sc[2*jj+1][3]);
            uint32_t vf[8][2];
            #pragma unroll
            for (int np = 0; np < 4; np++) {
                LDSM_X4(vf[2*np][0], vf[2*np][1], vf[2*np+1][0], vf[2*np+1][1],
                        sVH + (uint32_t)(np*16*36 + jj*8)*4 + koff);
            }
            #pragma unroll
            for (int nb = 0; nb < 8; nb++)
                MMA16(o[nb], ah, vf[nb]);
        }
    }

    const float inv0 = 1.f / l0, inv1 = 1.f / l1;
    const int gr0 = b*1024 + qb*64 + mr + g;
    #pragma unroll
    for (int nb = 0; nb < 8; nb++) {
        const int kp = h*32 + nb*4 + t;
        g_cH[gr0*256 + kp]       = hpack1(o[nb][0]*inv0, o[nb][1]*inv0);
        g_cH[(gr0 + 8)*256 + kp] = hpack1(o[nb][2]*inv1, o[nb][3]*inv1);
    }
}

__global__ void __launch_bounds__(128) fattn2_kernel() {
    extern __shared__ uint32_t fsm[];
    uint32_t* VH = fsm + 2*2304;
    const uint32_t sbase = (uint32_t)__cvta_generic_to_shared(fsm);

    const int p  = blockIdx.x;
    const int bh = blockIdx.y;
    const int b = bh >> 3, h = bh & 7;
    const int tid = threadIdx.x;

    fa2_tile(VH, sbase, p,      b, h, tid);
    __syncthreads();
    fa2_tile(VH, sbase, 15 - p, b, h, tid);
}

// ------------- fused residual add + LayerNorm -> fp32 x AND packed x -----------
__global__ void __launch_bounds__(256) add_ln_kernel(const float* __restrict__ g,
                                                     const float* __restrict__ bta) {
    const int row = blockIdx.x;
    float* x = g_x + (size_t)row*D_;
    const float* dl = g_tmp + (size_t)row*D_;
    const int tid = threadIdx.x;
    __shared__ float red[256];

    float2 xv = reinterpret_cast<const float2*>(x)[tid];
    float2 dv = reinterpret_cast<const float2*>(dl)[tid];
    float v0 = xv.x + dv.x;
    float v1 = xv.y + dv.y;

    red[tid] = v0 + v1; __syncthreads();
    for (int off = 128; off > 0; off >>= 1) {
        if (tid < off) red[tid] += red[tid + off];
        __syncthreads();
    }
    const float mu = red[0] * (1.f/512.f); __syncthreads();

    float d0 = v0 - mu, d1 = v1 - mu;
    red[tid] = d0*d0 + d1*d1; __syncthreads();
    for (int off = 128; off > 0; off >>= 1) {
        if (tid < off) red[tid] += red[tid + off];
        __syncthreads();
    }
    const float inv = rsqrtf(red[0]*(1.f/512.f) + 1e-5f);

    const int d = tid*2;
    float o0 = d0*inv*g[d]     + bta[d];
    float o1 = d1*inv*g[d + 1] + bta[d + 1];
    reinterpret_cast<float2*>(x)[tid] = make_float2(o0, o1);
    g_xH[row*256 + tid] = hpack1(o0, o1);
}

// ---------------- launch ----------------
#define SMEM_NI4 (NST*(128*AU + 128*AU)*4)   // 61440
#define SMEM_NI2 (NST*(128*AU + 64*AU)*4)    // 46080

extern "C" void kernel_launch(void* const* d_in, const int* in_sizes, int n_in,
                              void* d_out, int out_size) {
    const int*   ids  = (const int*)  d_in[0];
    const float* tok  = (const float*)d_in[1];
    const float* pos  = (const float*)d_in[2];
    const float* WQ   = (const float*)d_in[3];
    const float* WK   = (const float*)d_in[4];
    const float* WV   = (const float*)d_in[5];
    const float* WO   = (const float*)d_in[6];
    const float* ln1g = (const float*)d_in[7];
    const float* ln1b = (const float*)d_in[8];
    const float* fc1w = (const float*)d_in[9];
    const float* fc1b = (const float*)d_in[10];
    const float* fc2w = (const float*)d_in[11];
    const float* fc2b = (const float*)d_in[12];
    const float* ln2g = (const float*)d_in[13];
    const float* ln2b = (const float*)d_in[14];
    const float* lmh  = (const float*)d_in[15];
    float* out = (float*)d_out;

    float *pv, *ptmp;
    cudaGetSymbolAddress((void**)&pv,   g_v);
    cudaGetSymbolAddress((void**)&ptmp, g_tmp);

    uint32_t *xH, *cH, *fH, *qpH, *qkH, *woH, *f1H, *f2H, *lmH;
    cudaGetSymbolAddress((void**)&xH,  g_xH);
    cudaGetSymbolAddress((void**)&cH,  g_cH);
    cudaGetSymbolAddress((void**)&fH,  g_fH);
    cudaGetSymbolAddress((void**)&qpH, g_qkpH);
    cudaGetSymbolAddress((void**)&qkH, g_wqkvH);
    cudaGetSymbolAddress((void**)&woH, g_woH);
    cudaGetSymbolAddress((void**)&f1H, g_fc1H);
    cudaGetSymbolAddress((void**)&f2H, g_fc2H);
    cudaGetSymbolAddress((void**)&lmH, g_lmhH);

    cudaFuncSetAttribute((const void*)fattn2_kernel,             cudaFuncAttributeMaxDynamicSharedMemorySize, FA2_SMEM);
    cudaFuncSetAttribute((const void*)gemm_pk<2,0,false,4,false>, cudaFuncAttributeMaxDynamicSharedMemorySize, SMEM_NI4);
    cudaFuncSetAttribute((const void*)gemm_pk<0,0,false,2,false>, cudaFuncAttributeMaxDynamicSharedMemorySize, SMEM_NI2);
    cudaFuncSetAttribute((const void*)gemm_pk<1,2,false,4,false>, cudaFuncAttributeMaxDynamicSharedMemorySize, SMEM_NI4);
    cudaFuncSetAttribute((const void*)gemm_pk<0,1,false,2,false>, cudaFuncAttributeMaxDynamicSharedMemorySize, SMEM_NI2);
    cudaFuncSetAttribute((const void*)gemm_pk<0,0,true,4,true>,   cudaFuncAttributeMaxDynamicSharedMemorySize, SMEM_NI4);

    embed_kernel<<<BT_, 256>>>(ids, tok, pos);                           // 1
    prepack_qkvw<<<dim3(QKVW_/64, 8, L_), 256>>>(WQ, WK, WV);            // 2
    prepack_small<<<dim3(32, 32, 3*L_), 256>>>(WO, fc1w, fc2w);          // 3

    for (int l = 0; l < L_; l++) {
        gemm_pk<2,0,false,4,false><<<dim3(QKVW_/128, BT_/128), 256, SMEM_NI4>>>(
            BT_, QKVW_, D_, xH,
            qkH + (size_t)l*QKVW_*256,
            pv, 512, qpH, nullptr);                                      // 4 (l=0)

        fattn2_kernel<<<dim3(8, B_*H_), 128, FA2_SMEM>>>();              // 5 (l=0)

        gemm_pk<0,0,false,2,false><<<dim3(D_/64, BT_/128), 256, SMEM_NI2>>>(
            BT_, D_, D_, cH,
            woH + (size_t)l*D_*256,
            ptmp, D_, nullptr, nullptr);

        add_ln_kernel<<<BT_, 256>>>(ln1g + l*D_, ln1b + l*D_);

        gemm_pk<1,2,false,4,false><<<dim3(DFF_/128, BT_/128), 256, SMEM_NI4>>>(
            BT_, DFF_, D_, xH,
            f1H + (size_t)l*DFF_*256,
            nullptr, 0, fH, fc1b + l*DFF_);

        gemm_pk<0,1,false,2,false><<<dim3(D_/64, BT_/128), 256, SMEM_NI2>>>(
            BT_, D_, DFF_, fH,
            f2H + (size_t)l*D_*1024,
            ptmp, D_, nullptr, fc2b + l*D_);

        add_ln_kernel<<<BT_, 256>>>(ln2g + l*D_, ln2b + l*D_);
    }

    prepack_b_hi<<<dim3(VP_/64, 8), 256>>>(lmh, lmH, D_, V_, VP_);

    gemm_pk<0,0,true,4,true><<<dim3(BT_/128, VP_/128), 256, SMEM_NI4>>>(
        BT_, V_, D_, xH, lmH, out, V_, nullptr, nullptr);
}